// round 1
// baseline (speedup 1.0000x reference)
#include <cuda_runtime.h>
#include <math.h>

// Problem constants
#define BSZ   4
#define TLEN  2048
#define EDIM  1024
#define NHEAD 16
#define DHEAD 64
#define CHK   128
#define NCH   16            // TLEN / CHK
#define MROWS (BSZ*TLEN)    // 8192

// Scratch (device globals; allocation-free rule)
__device__ float g_q[(size_t)MROWS*EDIM];
__device__ float g_k[(size_t)MROWS*EDIM];
__device__ float g_v[(size_t)MROWS*EDIM];
__device__ float g_y[(size_t)MROWS*EDIM];
__device__ float g_kv[(size_t)BSZ*NHEAD*NCH*DHEAD*DHEAD];
__device__ float g_S [(size_t)BSZ*NHEAD*NCH*DHEAD*DHEAD];
__device__ float g_zk[(size_t)BSZ*NHEAD*NCH*DHEAD];
__device__ float g_Z [(size_t)BSZ*NHEAD*NCH*DHEAD];

// ---------------------------------------------------------------------------
// SGEMM (NT): C[m,n] = sum_k A[m,k]*B[n,k]. BM=BN=128, BK=16, 256 thr, 8x8/thr
// EPI: 0=plain, 1=phi (elu+1), 2=+bias
// ---------------------------------------------------------------------------
template <int EPI>
__global__ void __launch_bounds__(256, 2)
sgemm_nt(const float* __restrict__ A, const float* __restrict__ B,
         const float* __restrict__ bias, float* __restrict__ C,
         int Mm, int Nn, int Kk)
{
    constexpr int BK = 16;
    __shared__ float As[2][BK][128];
    __shared__ float Bs[2][BK][128];

    const int tid = threadIdx.x;
    const int tx = tid & 15, ty = tid >> 4;
    const size_t m0 = (size_t)blockIdx.y * 128;
    const size_t n0 = (size_t)blockIdx.x * 128;
    const float* Ap = A + m0 * Kk;
    const float* Bp = B + n0 * Kk;

    // load tile 0
    #pragma unroll
    for (int it = 0; it < 2; ++it) {
        int i = tid + it * 256;             // 0..511
        int row = i >> 2, kq = (i & 3) << 2;
        float4 av = *(const float4*)(Ap + (size_t)row * Kk + kq);
        float4 bv = *(const float4*)(Bp + (size_t)row * Kk + kq);
        As[0][kq + 0][row] = av.x; As[0][kq + 1][row] = av.y;
        As[0][kq + 2][row] = av.z; As[0][kq + 3][row] = av.w;
        Bs[0][kq + 0][row] = bv.x; Bs[0][kq + 1][row] = bv.y;
        Bs[0][kq + 2][row] = bv.z; Bs[0][kq + 3][row] = bv.w;
    }
    __syncthreads();

    float acc[8][8] = {};
    float4 ra[2], rb[2];
    const int nT = Kk / BK;

    for (int t = 0; t < nT; ++t) {
        const int cur = t & 1, nxt = cur ^ 1;
        if (t + 1 < nT) {
            const int k0 = (t + 1) * BK;
            #pragma unroll
            for (int it = 0; it < 2; ++it) {
                int i = tid + it * 256;
                int row = i >> 2, kq = (i & 3) << 2;
                ra[it] = *(const float4*)(Ap + (size_t)row * Kk + k0 + kq);
                rb[it] = *(const float4*)(Bp + (size_t)row * Kk + k0 + kq);
            }
        }
        #pragma unroll
        for (int kk = 0; kk < BK; ++kk) {
            float af[8], bf[8];
            *(float4*)&af[0] = *(const float4*)&As[cur][kk][ty * 4];
            *(float4*)&af[4] = *(const float4*)&As[cur][kk][64 + ty * 4];
            *(float4*)&bf[0] = *(const float4*)&Bs[cur][kk][tx * 4];
            *(float4*)&bf[4] = *(const float4*)&Bs[cur][kk][64 + tx * 4];
            #pragma unroll
            for (int i = 0; i < 8; ++i)
                #pragma unroll
                for (int j = 0; j < 8; ++j)
                    acc[i][j] = fmaf(af[i], bf[j], acc[i][j]);
        }
        if (t + 1 < nT) {
            #pragma unroll
            for (int it = 0; it < 2; ++it) {
                int i = tid + it * 256;
                int row = i >> 2, kq = (i & 3) << 2;
                As[nxt][kq + 0][row] = ra[it].x; As[nxt][kq + 1][row] = ra[it].y;
                As[nxt][kq + 2][row] = ra[it].z; As[nxt][kq + 3][row] = ra[it].w;
                Bs[nxt][kq + 0][row] = rb[it].x; Bs[nxt][kq + 1][row] = rb[it].y;
                Bs[nxt][kq + 2][row] = rb[it].z; Bs[nxt][kq + 3][row] = rb[it].w;
            }
            __syncthreads();
        }
    }

    // epilogue
    #pragma unroll
    for (int i = 0; i < 8; ++i) {
        int mi = (i < 4) ? (ty * 4 + i) : (64 + ty * 4 + (i - 4));
        size_t mrow = m0 + mi;
        #pragma unroll
        for (int jh = 0; jh < 2; ++jh) {
            int nb = (jh == 0) ? (tx * 4) : (64 + tx * 4);
            float o[4];
            #pragma unroll
            for (int jj = 0; jj < 4; ++jj) {
                float vv = acc[i][jh * 4 + jj];
                if (EPI == 1) vv = (vv > 0.f) ? (vv + 1.f) : __expf(vv);
                if (EPI == 2) vv += bias[n0 + nb + jj];
                o[jj] = vv;
            }
            *(float4*)(C + mrow * Nn + n0 + nb) = *(float4*)o;
        }
    }
}

// ---------------------------------------------------------------------------
// Per-chunk kv state: kv[d,e] = sum_c k[c,d]*v[c,e], zk[d] = sum_c k[c,d]
// One CTA per (b,h,n). 256 threads, 4x4 outputs/thread, 32-row strips.
// ---------------------------------------------------------------------------
__global__ void __launch_bounds__(256)
chunk_kv_kernel(const float* __restrict__ k, const float* __restrict__ v,
                float* __restrict__ kv, float* __restrict__ zk)
{
    const int n = blockIdx.x, h = blockIdx.y, b = blockIdx.z;
    __shared__ float sK[32][DHEAD + 4];
    __shared__ float sV[32][DHEAD + 4];
    const int tid = threadIdx.x;
    const int d0 = (tid >> 4) << 2, e0 = (tid & 15) << 2;
    const size_t rowbase = ((size_t)(b * TLEN + n * CHK)) * EDIM + h * DHEAD;

    float acc[4][4] = {};
    float z = 0.f;

    for (int s = 0; s < 4; ++s) {
        #pragma unroll
        for (int it = 0; it < 2; ++it) {
            int i = tid + it * 256;          // 0..511
            int row = i >> 4, cq = (i & 15) << 2;
            *(float4*)&sK[row][cq] =
                *(const float4*)(k + rowbase + (size_t)(s * 32 + row) * EDIM + cq);
            *(float4*)&sV[row][cq] =
                *(const float4*)(v + rowbase + (size_t)(s * 32 + row) * EDIM + cq);
        }
        __syncthreads();
        #pragma unroll 8
        for (int c = 0; c < 32; ++c) {
            float kf[4], vf[4];
            *(float4*)kf = *(const float4*)&sK[c][d0];
            *(float4*)vf = *(const float4*)&sV[c][e0];
            #pragma unroll
            for (int i = 0; i < 4; ++i)
                #pragma unroll
                for (int j = 0; j < 4; ++j)
                    acc[i][j] = fmaf(kf[i], vf[j], acc[i][j]);
        }
        if (tid < DHEAD) {
            #pragma unroll 8
            for (int c = 0; c < 32; ++c) z += sK[c][tid];
        }
        __syncthreads();
    }

    const size_t obase = ((size_t)((b * NHEAD + h) * NCH) + n) * DHEAD * DHEAD;
    #pragma unroll
    for (int i = 0; i < 4; ++i)
        *(float4*)(kv + obase + (size_t)(d0 + i) * DHEAD + e0) = *(float4*)&acc[i][0];
    if (tid < DHEAD)
        zk[((size_t)((b * NHEAD + h) * NCH) + n) * DHEAD + tid] = z;
}

// ---------------------------------------------------------------------------
// Exclusive prefix over the N=16 chunk axis (KV state and key-sum)
// ---------------------------------------------------------------------------
__global__ void prefix_scan_kernel(const float* __restrict__ src,
                                   float* __restrict__ dst, int per)
{
    int i = blockIdx.x * blockDim.x + threadIdx.x;
    int total = BSZ * NHEAD * per;
    if (i >= total) return;
    int bh = i / per, r = i - bh * per;
    size_t base = (size_t)bh * NCH * per + r;
    float acc = 0.f;
    #pragma unroll
    for (int nn = 0; nn < NCH; ++nn) {
        dst[base + (size_t)nn * per] = acc;
        acc += src[base + (size_t)nn * per];
    }
}

// ---------------------------------------------------------------------------
// Per-chunk attention. One CTA per (b,h,n), 256 threads.
// A = Q K^T (masked) materialized transposed [s][c] in smem for the
// conflict-free second pass; num = A V + Q S_prev; den = rowsum(A)+Q.Z+eps.
// ---------------------------------------------------------------------------
#define SQT_OFF   0
#define SKT_OFF   (64 * 132)
#define SV_OFF    (2 * 64 * 132)
#define SS_OFF    (SV_OFF + 128 * 68)
#define SA_OFF    (SS_OFF + 64 * 68)
#define SZ_OFF    (SA_OFF + 128 * 132)
#define SDEN_OFF  (SZ_OFF + 64)
#define ATTN_SMEM ((SDEN_OFF + 128) * 4)

__global__ void __launch_bounds__(256)
chunk_attn_kernel(const float* __restrict__ q, const float* __restrict__ k,
                  const float* __restrict__ v, const float* __restrict__ S,
                  const float* __restrict__ Z, float* __restrict__ y)
{
    extern __shared__ float sm[];
    float* sQt  = sm + SQT_OFF;    // [64][132]  d-major
    float* sKt  = sm + SKT_OFF;    // [64][132]  d-major
    float* sV   = sm + SV_OFF;     // [128][68]
    float* sS   = sm + SS_OFF;     // [64][68]
    float* sA   = sm + SA_OFF;     // [128][132] s-major (A transposed)
    float* sZ   = sm + SZ_OFF;     // [64]
    float* sDen = sm + SDEN_OFF;   // [128]

    const int n = blockIdx.x, h = blockIdx.y, b = blockIdx.z;
    const int tid = threadIdx.x;
    const int tx = tid & 15, ty = tid >> 4;
    const size_t rowbase = ((size_t)(b * TLEN + n * CHK)) * EDIM + h * DHEAD;

    // stage q (transposed), k (transposed), v
    #pragma unroll
    for (int it = 0; it < 8; ++it) {
        int i = tid + it * 256;              // 0..2047
        int row = i >> 4, cq = (i & 15) << 2;
        float4 qv = *(const float4*)(q + rowbase + (size_t)row * EDIM + cq);
        sQt[(cq + 0) * 132 + row] = qv.x; sQt[(cq + 1) * 132 + row] = qv.y;
        sQt[(cq + 2) * 132 + row] = qv.z; sQt[(cq + 3) * 132 + row] = qv.w;
        float4 kk4 = *(const float4*)(k + rowbase + (size_t)row * EDIM + cq);
        sKt[(cq + 0) * 132 + row] = kk4.x; sKt[(cq + 1) * 132 + row] = kk4.y;
        sKt[(cq + 2) * 132 + row] = kk4.z; sKt[(cq + 3) * 132 + row] = kk4.w;
        *(float4*)&sV[row * 68 + cq] =
            *(const float4*)(v + rowbase + (size_t)row * EDIM + cq);
    }
    const size_t sbase = ((size_t)((b * NHEAD + h) * NCH) + n) * DHEAD * DHEAD;
    #pragma unroll
    for (int it = 0; it < 4; ++it) {
        int i = tid + it * 256;              // 0..1023
        int row = i >> 4, cq = (i & 15) << 2;
        *(float4*)&sS[row * 68 + cq] = *(const float4*)(S + sbase + row * DHEAD + cq);
    }
    if (tid < DHEAD)
        sZ[tid] = Z[((size_t)((b * NHEAD + h) * NCH) + n) * DHEAD + tid];
    __syncthreads();

    // Phase A: A[c][s] = sum_d Qt[d][c] * Kt[d][s]; store masked, transposed
    {
        float acc[8][8] = {};
        #pragma unroll 8
        for (int d = 0; d < DHEAD; ++d) {
            float af[8], bf[8];
            *(float4*)&af[0] = *(const float4*)&sQt[d * 132 + ty * 4];
            *(float4*)&af[4] = *(const float4*)&sQt[d * 132 + 64 + ty * 4];
            *(float4*)&bf[0] = *(const float4*)&sKt[d * 132 + tx * 4];
            *(float4*)&bf[4] = *(const float4*)&sKt[d * 132 + 64 + tx * 4];
            #pragma unroll
            for (int i = 0; i < 8; ++i)
                #pragma unroll
                for (int j = 0; j < 8; ++j)
                    acc[i][j] = fmaf(af[i], bf[j], acc[i][j]);
        }
        #pragma unroll
        for (int j = 0; j < 8; ++j) {
            int s = (j < 4) ? (tx * 4 + j) : (64 + tx * 4 + (j - 4));
            float o0[4], o1[4];
            #pragma unroll
            for (int i = 0; i < 4; ++i) {
                int c0 = ty * 4 + i, c1 = 64 + ty * 4 + i;
                o0[i] = (s <= c0) ? acc[i][j] : 0.f;
                o1[i] = (s <= c1) ? acc[4 + i][j] : 0.f;
            }
            *(float4*)&sA[s * 132 + ty * 4]      = *(float4*)o0;
            *(float4*)&sA[s * 132 + 64 + ty * 4] = *(float4*)o1;
        }
    }
    __syncthreads();

    // Den: 1/(rowsum(A) + Q.Z + eps)
    if (tid < CHK) {
        int c = tid;
        float s1 = 0.f;
        #pragma unroll 8
        for (int s = 0; s < CHK; ++s) s1 += sA[s * 132 + c];
        float s2 = 0.f;
        #pragma unroll 8
        for (int d = 0; d < DHEAD; ++d) s2 += sQt[d * 132 + c] * sZ[d];
        sDen[c] = 1.0f / (s1 + s2 + 1e-6f);
    }
    __syncthreads();

    // Phase B: num = A V + Q S_prev; write y = num * invden
    {
        float acc2[8][4] = {};
        #pragma unroll 8
        for (int s = 0; s < CHK; ++s) {
            float af[8], bf[4];
            *(float4*)&af[0] = *(const float4*)&sA[s * 132 + ty * 4];
            *(float4*)&af[4] = *(const float4*)&sA[s * 132 + 64 + ty * 4];
            *(float4*)&bf[0] = *(const float4*)&sV[s * 68 + tx * 4];
            #pragma unroll
            for (int i = 0; i < 8; ++i)
                #pragma unroll
                for (int j = 0; j < 4; ++j)
                    acc2[i][j] = fmaf(af[i], bf[j], acc2[i][j]);
        }
        #pragma unroll 8
        for (int d = 0; d < DHEAD; ++d) {
            float af[8], bf[4];
            *(float4*)&af[0] = *(const float4*)&sQt[d * 132 + ty * 4];
            *(float4*)&af[4] = *(const float4*)&sQt[d * 132 + 64 + ty * 4];
            *(float4*)&bf[0] = *(const float4*)&sS[d * 68 + tx * 4];
            #pragma unroll
            for (int i = 0; i < 8; ++i)
                #pragma unroll
                for (int j = 0; j < 4; ++j)
                    acc2[i][j] = fmaf(af[i], bf[j], acc2[i][j]);
        }
        #pragma unroll
        for (int i = 0; i < 8; ++i) {
            int c = (i < 4) ? (ty * 4 + i) : (64 + ty * 4 + (i - 4));
            float inv = sDen[c];
            float o[4];
            #pragma unroll
            for (int j = 0; j < 4; ++j) o[j] = acc2[i][j] * inv;
            *(float4*)(y + rowbase + (size_t)c * EDIM + tx * 4) = *(float4*)o;
        }
    }
}

// ---------------------------------------------------------------------------
extern "C" void kernel_launch(void* const* d_in, const int* in_sizes, int n_in,
                              void* d_out, int out_size)
{
    const float* x  = (const float*)d_in[0];
    const float* Wq = (const float*)d_in[1];
    const float* Wk = (const float*)d_in[2];
    const float* Wv = (const float*)d_in[3];
    const float* Wp = (const float*)d_in[4];
    const float* bp = (const float*)d_in[5];
    float* out = (float*)d_out;

    float *q, *k, *v, *y, *kv, *S, *zk, *Z;
    cudaGetSymbolAddress((void**)&q,  g_q);
    cudaGetSymbolAddress((void**)&k,  g_k);
    cudaGetSymbolAddress((void**)&v,  g_v);
    cudaGetSymbolAddress((void**)&y,  g_y);
    cudaGetSymbolAddress((void**)&kv, g_kv);
    cudaGetSymbolAddress((void**)&S,  g_S);
    cudaGetSymbolAddress((void**)&zk, g_zk);
    cudaGetSymbolAddress((void**)&Z,  g_Z);

    cudaFuncSetAttribute(chunk_attn_kernel,
                         cudaFuncAttributeMaxDynamicSharedMemorySize, ATTN_SMEM);

    dim3 gg(EDIM / 128, MROWS / 128);
    sgemm_nt<1><<<gg, 256>>>(x, Wq, nullptr, q, MROWS, EDIM, EDIM);
    sgemm_nt<1><<<gg, 256>>>(x, Wk, nullptr, k, MROWS, EDIM, EDIM);
    sgemm_nt<0><<<gg, 256>>>(x, Wv, nullptr, v, MROWS, EDIM, EDIM);

    chunk_kv_kernel<<<dim3(NCH, NHEAD, BSZ), 256>>>(k, v, kv, zk);
    prefix_scan_kernel<<<(BSZ * NHEAD * DHEAD * DHEAD + 255) / 256, 256>>>(kv, S, DHEAD * DHEAD);
    prefix_scan_kernel<<<(BSZ * NHEAD * DHEAD + 255) / 256, 256>>>(zk, Z, DHEAD);

    chunk_attn_kernel<<<dim3(NCH, NHEAD, BSZ), 256, ATTN_SMEM>>>(q, k, v, S, Z, y);

    sgemm_nt<2><<<gg, 256>>>(y, Wp, bp, out, MROWS, EDIM, EDIM);
}

// round 3
// speedup vs baseline: 1.8716x; 1.8716x over previous
#include <cuda_runtime.h>
#include <cuda_bf16.h>
#include <math.h>
#include <stdint.h>

// Problem constants
#define BSZ   4
#define TLEN  2048
#define EDIM  1024
#define NHEAD 16
#define DHEAD 64
#define CHK   128
#define NCH   16            // TLEN / CHK
#define MROWS (BSZ*TLEN)    // 8192

// Scratch (device globals; allocation-free rule)
__device__ float g_q[(size_t)MROWS*EDIM];
__device__ float g_k[(size_t)MROWS*EDIM];
__device__ float g_v[(size_t)MROWS*EDIM];
__device__ float g_y[(size_t)MROWS*EDIM];
__device__ float g_kv[(size_t)BSZ*NHEAD*NCH*DHEAD*DHEAD];
__device__ float g_S [(size_t)BSZ*NHEAD*NCH*DHEAD*DHEAD];
__device__ float g_zk[(size_t)BSZ*NHEAD*NCH*DHEAD];
__device__ float g_Z [(size_t)BSZ*NHEAD*NCH*DHEAD];
// bf16 hi/lo split buffers
__device__ __nv_bfloat16 g_xhi[(size_t)MROWS*EDIM];
__device__ __nv_bfloat16 g_xlo[(size_t)MROWS*EDIM];
__device__ __nv_bfloat16 g_yhi[(size_t)MROWS*EDIM];
__device__ __nv_bfloat16 g_ylo[(size_t)MROWS*EDIM];
__device__ __nv_bfloat16 g_whi[(size_t)4*EDIM*EDIM];
__device__ __nv_bfloat16 g_wlo[(size_t)4*EDIM*EDIM];

// ---------------------------------------------------------------------------
// helpers
// ---------------------------------------------------------------------------
__device__ __forceinline__ uint32_t smem_u32(const void* p) {
    uint32_t a;
    asm("{ .reg .u64 t; cvta.to.shared.u64 t, %1; cvt.u32.u64 %0, t; }"
        : "=r"(a) : "l"(p));
    return a;
}
#define CP_ASYNC16(dst, src) \
    asm volatile("cp.async.cg.shared.global [%0], [%1], 16;" \
                 :: "r"(dst), "l"(src) : "memory")
#define CP_COMMIT() asm volatile("cp.async.commit_group;" ::: "memory")
#define CP_WAIT(N)  asm volatile("cp.async.wait_group %0;" :: "n"(N) : "memory")
#define LDSM_X4(r0, r1, r2, r3, a) \
    asm volatile("ldmatrix.sync.aligned.m8n8.x4.shared.b16 {%0,%1,%2,%3}, [%4];" \
                 : "=r"(r0), "=r"(r1), "=r"(r2), "=r"(r3) : "r"(a))
#define MMA16816(d, a, b0v, b1v) \
    asm volatile("mma.sync.aligned.m16n8k16.row.col.f32.bf16.bf16.f32 " \
                 "{%0,%1,%2,%3}, {%4,%5,%6,%7}, {%8,%9}, {%0,%1,%2,%3};" \
                 : "+f"((d)[0]), "+f"((d)[1]), "+f"((d)[2]), "+f"((d)[3]) \
                 : "r"((a)[0]), "r"((a)[1]), "r"((a)[2]), "r"((a)[3]), \
                   "r"(b0v), "r"(b1v))

// ---------------------------------------------------------------------------
// fp32 -> (hi, lo) bf16 split
// ---------------------------------------------------------------------------
__global__ void split_bf16_kernel(const float* __restrict__ in,
                                  __nv_bfloat16* __restrict__ hi,
                                  __nv_bfloat16* __restrict__ lo, int n4)
{
    int i = blockIdx.x * blockDim.x + threadIdx.x;
    if (i >= n4) return;
    float4 v = ((const float4*)in)[i];
    __nv_bfloat16 h0 = __float2bfloat16(v.x);
    __nv_bfloat16 h1 = __float2bfloat16(v.y);
    __nv_bfloat16 h2 = __float2bfloat16(v.z);
    __nv_bfloat16 h3 = __float2bfloat16(v.w);
    __nv_bfloat16 l0 = __float2bfloat16(v.x - __bfloat162float(h0));
    __nv_bfloat16 l1 = __float2bfloat16(v.y - __bfloat162float(h1));
    __nv_bfloat16 l2 = __float2bfloat16(v.z - __bfloat162float(h2));
    __nv_bfloat16 l3 = __float2bfloat16(v.w - __bfloat162float(h3));
    ((__nv_bfloat162*)hi)[2 * i + 0] = __halves2bfloat162(h0, h1);
    ((__nv_bfloat162*)hi)[2 * i + 1] = __halves2bfloat162(h2, h3);
    ((__nv_bfloat162*)lo)[2 * i + 0] = __halves2bfloat162(l0, l1);
    ((__nv_bfloat162*)lo)[2 * i + 1] = __halves2bfloat162(l2, l3);
}

// ---------------------------------------------------------------------------
// mma.sync split-bf16 GEMM (NT): C[m,n] = sum_k A[m,k]*B[n,k], ~fp32 accuracy.
// BM=BN=128, BK=32, 8 warps (2x4), warp tile 64x32, cp.async double-buffer.
// EPI: 0=plain, 1=phi (elu+1), 2=+bias
// ---------------------------------------------------------------------------
#define BK      32
#define LDT     40                      // BK + 8 pad (bf16 elems)
#define TILEB   (128 * LDT * 2)         // 10240 B per tile
#define STAGEB  (4 * TILEB)             // Ah, Al, Bh, Bl
#define GEMM_SMEM (2 * STAGEB)          // 81920 B
#define NT      (EDIM / BK)             // 32 chunks

template <int EPI>
__global__ void __launch_bounds__(256, 1)
tc_gemm(const __nv_bfloat16* __restrict__ Ahi, const __nv_bfloat16* __restrict__ Alo,
        const __nv_bfloat16* __restrict__ Bhi, const __nv_bfloat16* __restrict__ Blo,
        const float* __restrict__ bias, float* __restrict__ C)
{
    extern __shared__ char smc[];
    const uint32_t sb = smem_u32(smc);
    const int tid = threadIdx.x;
    const int wid = tid >> 5, lane = tid & 31;
    const int m0g = blockIdx.y * 128;
    const int n0g = blockIdx.x * 128;
    const int m_off = (wid & 1) * 64;       // 2 warps in M
    const int n_off = (wid >> 1) * 32;      // 4 warps in N

    // per-thread ldmatrix byte offsets within a tile (add ks*2 at use)
    uint32_t aoff[4], boff[2];
    #pragma unroll
    for (int mt = 0; mt < 4; ++mt)
        aoff[mt] = (uint32_t)(((m_off + 16 * mt + (lane & 15)) * LDT
                               + (lane >> 4) * 8) * 2);
    #pragma unroll
    for (int p = 0; p < 2; ++p)
        boff[p] = (uint32_t)(((n_off + 16 * p + ((lane >> 4) << 3) + (lane & 7)) * LDT
                              + ((lane >> 3) & 1) * 8) * 2);

    // cp.async staging: one chunk = 4 tiles of 128 rows x 32 bf16
    auto stage_tile = [&](const __nv_bfloat16* __restrict__ src, int row0,
                          int kc, uint32_t dstbase) {
        #pragma unroll
        for (int j = 0; j < 2; ++j) {
            int u = tid + j * 256;          // 0..511
            int row = u >> 2, seg = u & 3;  // seg: 16B segment within 64B row
            uint32_t d = dstbase + (uint32_t)((row * LDT + seg * 8) * 2);
            const __nv_bfloat16* g = src + (size_t)(row0 + row) * EDIM + kc + seg * 8;
            CP_ASYNC16(d, g);
        }
    };
    auto stage_chunk = [&](int t, int buf) {
        int kc = t * BK;
        uint32_t base = sb + buf * STAGEB;
        stage_tile(Ahi, m0g, kc, base);
        stage_tile(Alo, m0g, kc, base + TILEB);
        stage_tile(Bhi, n0g, kc, base + 2 * TILEB);
        stage_tile(Blo, n0g, kc, base + 3 * TILEB);
        CP_COMMIT();
    };

    float acc[4][4][4] = {};

    stage_chunk(0, 0);
    for (int t = 0; t < NT; ++t) {
        const int cur = t & 1;
        if (t + 1 < NT) {
            stage_chunk(t + 1, 1 - cur);
            CP_WAIT(1);
        } else {
            CP_WAIT(0);
        }
        __syncthreads();

        const uint32_t base = sb + cur * STAGEB;
        #pragma unroll
        for (int ks = 0; ks < BK; ks += 16) {
            const uint32_t kso = (uint32_t)(ks * 2);
            uint32_t ah[4][4], al[4][4], bh[2][4], bl[2][4];
            #pragma unroll
            for (int mt = 0; mt < 4; ++mt) {
                LDSM_X4(ah[mt][0], ah[mt][1], ah[mt][2], ah[mt][3],
                        base + aoff[mt] + kso);
                LDSM_X4(al[mt][0], al[mt][1], al[mt][2], al[mt][3],
                        base + TILEB + aoff[mt] + kso);
            }
            #pragma unroll
            for (int p = 0; p < 2; ++p) {
                LDSM_X4(bh[p][0], bh[p][1], bh[p][2], bh[p][3],
                        base + 2 * TILEB + boff[p] + kso);
                LDSM_X4(bl[p][0], bl[p][1], bl[p][2], bl[p][3],
                        base + 3 * TILEB + boff[p] + kso);
            }
            #pragma unroll
            for (int i = 0; i < 4; ++i)
                #pragma unroll
                for (int j = 0; j < 4; ++j) {
                    const int p = j >> 1, w = (j & 1) * 2;
                    MMA16816(acc[i][j], ah[i], bh[p][w], bh[p][w + 1]);
                    MMA16816(acc[i][j], ah[i], bl[p][w], bl[p][w + 1]);
                    MMA16816(acc[i][j], al[i], bh[p][w], bh[p][w + 1]);
                }
        }
        __syncthreads();
    }

    // epilogue: thread owns rows (r, r+8), cols (c, c+1) per mma tile
    #pragma unroll
    for (int i = 0; i < 4; ++i) {
        const int r = m0g + m_off + 16 * i + (lane >> 2);
        #pragma unroll
        for (int j = 0; j < 4; ++j) {
            const int c = n0g + n_off + 8 * j + ((lane & 3) << 1);
            float v0 = acc[i][j][0], v1 = acc[i][j][1];
            float v2 = acc[i][j][2], v3 = acc[i][j][3];
            if (EPI == 1) {
                v0 = (v0 > 0.f) ? (v0 + 1.f) : __expf(v0);
                v1 = (v1 > 0.f) ? (v1 + 1.f) : __expf(v1);
                v2 = (v2 > 0.f) ? (v2 + 1.f) : __expf(v2);
                v3 = (v3 > 0.f) ? (v3 + 1.f) : __expf(v3);
            }
            if (EPI == 2) {
                float b0 = bias[c], b1 = bias[c + 1];
                v0 += b0; v1 += b1; v2 += b0; v3 += b1;
            }
            *(float2*)(C + (size_t)r * EDIM + c)       = make_float2(v0, v1);
            *(float2*)(C + (size_t)(r + 8) * EDIM + c) = make_float2(v2, v3);
        }
    }
}

// ---------------------------------------------------------------------------
// Per-chunk kv state: kv[d,e] = sum_c k[c,d]*v[c,e], zk[d] = sum_c k[c,d]
// ---------------------------------------------------------------------------
__global__ void __launch_bounds__(256)
chunk_kv_kernel(const float* __restrict__ k, const float* __restrict__ v,
                float* __restrict__ kv, float* __restrict__ zk)
{
    const int n = blockIdx.x, h = blockIdx.y, b = blockIdx.z;
    __shared__ float sK[32][DHEAD + 4];
    __shared__ float sV[32][DHEAD + 4];
    const int tid = threadIdx.x;
    const int d0 = (tid >> 4) << 2, e0 = (tid & 15) << 2;
    const size_t rowbase = ((size_t)(b * TLEN + n * CHK)) * EDIM + h * DHEAD;

    float acc[4][4] = {};
    float z = 0.f;

    for (int s = 0; s < 4; ++s) {
        #pragma unroll
        for (int it = 0; it < 2; ++it) {
            int i = tid + it * 256;
            int row = i >> 4, cq = (i & 15) << 2;
            *(float4*)&sK[row][cq] =
                *(const float4*)(k + rowbase + (size_t)(s * 32 + row) * EDIM + cq);
            *(float4*)&sV[row][cq] =
                *(const float4*)(v + rowbase + (size_t)(s * 32 + row) * EDIM + cq);
        }
        __syncthreads();
        #pragma unroll 8
        for (int c = 0; c < 32; ++c) {
            float kf[4], vf[4];
            *(float4*)kf = *(const float4*)&sK[c][d0];
            *(float4*)vf = *(const float4*)&sV[c][e0];
            #pragma unroll
            for (int i = 0; i < 4; ++i)
                #pragma unroll
                for (int j = 0; j < 4; ++j)
                    acc[i][j] = fmaf(kf[i], vf[j], acc[i][j]);
        }
        if (tid < DHEAD) {
            #pragma unroll 8
            for (int c = 0; c < 32; ++c) z += sK[c][tid];
        }
        __syncthreads();
    }

    const size_t obase = ((size_t)((b * NHEAD + h) * NCH) + n) * DHEAD * DHEAD;
    #pragma unroll
    for (int i = 0; i < 4; ++i)
        *(float4*)(kv + obase + (size_t)(d0 + i) * DHEAD + e0) = *(float4*)&acc[i][0];
    if (tid < DHEAD)
        zk[((size_t)((b * NHEAD + h) * NCH) + n) * DHEAD + tid] = z;
}

// ---------------------------------------------------------------------------
// Exclusive prefix over the N=16 chunk axis
// ---------------------------------------------------------------------------
__global__ void prefix_scan_kernel(const float* __restrict__ src,
                                   float* __restrict__ dst, int per)
{
    int i = blockIdx.x * blockDim.x + threadIdx.x;
    int total = BSZ * NHEAD * per;
    if (i >= total) return;
    int bh = i / per, r = i - bh * per;
    size_t base = (size_t)bh * NCH * per + r;
    float acc = 0.f;
    #pragma unroll
    for (int nn = 0; nn < NCH; ++nn) {
        dst[base + (size_t)nn * per] = acc;
        acc += src[base + (size_t)nn * per];
    }
}

// ---------------------------------------------------------------------------
// Per-chunk attention (fp32, unchanged from R1 — known correct)
// ---------------------------------------------------------------------------
#define SQT_OFF   0
#define SKT_OFF   (64 * 132)
#define SV_OFF    (2 * 64 * 132)
#define SS_OFF    (SV_OFF + 128 * 68)
#define SA_OFF    (SS_OFF + 64 * 68)
#define SZ_OFF    (SA_OFF + 128 * 132)
#define SDEN_OFF  (SZ_OFF + 64)
#define ATTN_SMEM ((SDEN_OFF + 128) * 4)

__global__ void __launch_bounds__(256)
chunk_attn_kernel(const float* __restrict__ q, const float* __restrict__ k,
                  const float* __restrict__ v, const float* __restrict__ S,
                  const float* __restrict__ Z, float* __restrict__ y)
{
    extern __shared__ float sm[];
    float* sQt  = sm + SQT_OFF;
    float* sKt  = sm + SKT_OFF;
    float* sV   = sm + SV_OFF;
    float* sS   = sm + SS_OFF;
    float* sA   = sm + SA_OFF;
    float* sZ   = sm + SZ_OFF;
    float* sDen = sm + SDEN_OFF;

    const int n = blockIdx.x, h = blockIdx.y, b = blockIdx.z;
    const int tid = threadIdx.x;
    const int tx = tid & 15, ty = tid >> 4;
    const size_t rowbase = ((size_t)(b * TLEN + n * CHK)) * EDIM + h * DHEAD;

    #pragma unroll
    for (int it = 0; it < 8; ++it) {
        int i = tid + it * 256;
        int row = i >> 4, cq = (i & 15) << 2;
        float4 qv = *(const float4*)(q + rowbase + (size_t)row * EDIM + cq);
        sQt[(cq + 0) * 132 + row] = qv.x; sQt[(cq + 1) * 132 + row] = qv.y;
        sQt[(cq + 2) * 132 + row] = qv.z; sQt[(cq + 3) * 132 + row] = qv.w;
        float4 kk4 = *(const float4*)(k + rowbase + (size_t)row * EDIM + cq);
        sKt[(cq + 0) * 132 + row] = kk4.x; sKt[(cq + 1) * 132 + row] = kk4.y;
        sKt[(cq + 2) * 132 + row] = kk4.z; sKt[(cq + 3) * 132 + row] = kk4.w;
        *(float4*)&sV[row * 68 + cq] =
            *(const float4*)(v + rowbase + (size_t)row * EDIM + cq);
    }
    const size_t sbase = ((size_t)((b * NHEAD + h) * NCH) + n) * DHEAD * DHEAD;
    #pragma unroll
    for (int it = 0; it < 4; ++it) {
        int i = tid + it * 256;
        int row = i >> 4, cq = (i & 15) << 2;
        *(float4*)&sS[row * 68 + cq] = *(const float4*)(S + sbase + row * DHEAD + cq);
    }
    if (tid < DHEAD)
        sZ[tid] = Z[((size_t)((b * NHEAD + h) * NCH) + n) * DHEAD + tid];
    __syncthreads();

    {
        float acc[8][8] = {};
        #pragma unroll 8
        for (int d = 0; d < DHEAD; ++d) {
            float af[8], bf[8];
            *(float4*)&af[0] = *(const float4*)&sQt[d * 132 + ty * 4];
            *(float4*)&af[4] = *(const float4*)&sQt[d * 132 + 64 + ty * 4];
            *(float4*)&bf[0] = *(const float4*)&sKt[d * 132 + tx * 4];
            *(float4*)&bf[4] = *(const float4*)&sKt[d * 132 + 64 + tx * 4];
            #pragma unroll
            for (int i = 0; i < 8; ++i)
                #pragma unroll
                for (int j = 0; j < 8; ++j)
                    acc[i][j] = fmaf(af[i], bf[j], acc[i][j]);
        }
        #pragma unroll
        for (int j = 0; j < 8; ++j) {
            int s = (j < 4) ? (tx * 4 + j) : (64 + tx * 4 + (j - 4));
            float o0[4], o1[4];
            #pragma unroll
            for (int i = 0; i < 4; ++i) {
                int c0 = ty * 4 + i, c1 = 64 + ty * 4 + i;
                o0[i] = (s <= c0) ? acc[i][j] : 0.f;
                o1[i] = (s <= c1) ? acc[4 + i][j] : 0.f;
            }
            *(float4*)&sA[s * 132 + ty * 4]      = *(float4*)o0;
            *(float4*)&sA[s * 132 + 64 + ty * 4] = *(float4*)o1;
        }
    }
    __syncthreads();

    if (tid < CHK) {
        int c = tid;
        float s1 = 0.f;
        #pragma unroll 8
        for (int s = 0; s < CHK; ++s) s1 += sA[s * 132 + c];
        float s2 = 0.f;
        #pragma unroll 8
        for (int d = 0; d < DHEAD; ++d) s2 += sQt[d * 132 + c] * sZ[d];
        sDen[c] = 1.0f / (s1 + s2 + 1e-6f);
    }
    __syncthreads();

    {
        float acc2[8][4] = {};
        #pragma unroll 8
        for (int s = 0; s < CHK; ++s) {
            float af[8], bf[4];
            *(float4*)&af[0] = *(const float4*)&sA[s * 132 + ty * 4];
            *(float4*)&af[4] = *(const float4*)&sA[s * 132 + 64 + ty * 4];
            *(float4*)&bf[0] = *(const float4*)&sV[s * 68 + tx * 4];
            #pragma unroll
            for (int i = 0; i < 8; ++i)
                #pragma unroll
                for (int j = 0; j < 4; ++j)
                    acc2[i][j] = fmaf(af[i], bf[j], acc2[i][j]);
        }
        #pragma unroll 8
        for (int d = 0; d < DHEAD; ++d) {
            float af[8], bf[4];
            *(float4*)&af[0] = *(const float4*)&sQt[d * 132 + ty * 4];
            *(float4*)&af[4] = *(const float4*)&sQt[d * 132 + 64 + ty * 4];
            *(float4*)&bf[0] = *(const float4*)&sS[d * 68 + tx * 4];
            #pragma unroll
            for (int i = 0; i < 8; ++i)
                #pragma unroll
                for (int j = 0; j < 4; ++j)
                    acc2[i][j] = fmaf(af[i], bf[j], acc2[i][j]);
        }
        #pragma unroll
        for (int i = 0; i < 8; ++i) {
            int c = (i < 4) ? (ty * 4 + i) : (64 + ty * 4 + (i - 4));
            float inv = sDen[c];
            float o[4];
            #pragma unroll
            for (int j = 0; j < 4; ++j) o[j] = acc2[i][j] * inv;
            *(float4*)(y + rowbase + (size_t)c * EDIM + tx * 4) = *(float4*)o;
        }
    }
}

// ---------------------------------------------------------------------------
extern "C" void kernel_launch(void* const* d_in, const int* in_sizes, int n_in,
                              void* d_out, int out_size)
{
    const float* x  = (const float*)d_in[0];
    const float* Wq = (const float*)d_in[1];
    const float* Wk = (const float*)d_in[2];
    const float* Wv = (const float*)d_in[3];
    const float* Wp = (const float*)d_in[4];
    const float* bp = (const float*)d_in[5];
    float* out = (float*)d_out;

    float *q, *k, *v, *y, *kv, *S, *zk, *Z;
    __nv_bfloat16 *xhi, *xlo, *yhi, *ylo, *whi, *wlo;
    cudaGetSymbolAddress((void**)&q,  g_q);
    cudaGetSymbolAddress((void**)&k,  g_k);
    cudaGetSymbolAddress((void**)&v,  g_v);
    cudaGetSymbolAddress((void**)&y,  g_y);
    cudaGetSymbolAddress((void**)&kv, g_kv);
    cudaGetSymbolAddress((void**)&S,  g_S);
    cudaGetSymbolAddress((void**)&zk, g_zk);
    cudaGetSymbolAddress((void**)&Z,  g_Z);
    cudaGetSymbolAddress((void**)&xhi, g_xhi);
    cudaGetSymbolAddress((void**)&xlo, g_xlo);
    cudaGetSymbolAddress((void**)&yhi, g_yhi);
    cudaGetSymbolAddress((void**)&ylo, g_ylo);
    cudaGetSymbolAddress((void**)&whi, g_whi);
    cudaGetSymbolAddress((void**)&wlo, g_wlo);

    cudaFuncSetAttribute(chunk_attn_kernel,
                         cudaFuncAttributeMaxDynamicSharedMemorySize, ATTN_SMEM);
    cudaFuncSetAttribute(tc_gemm<0>, cudaFuncAttributeMaxDynamicSharedMemorySize, GEMM_SMEM);
    cudaFuncSetAttribute(tc_gemm<1>, cudaFuncAttributeMaxDynamicSharedMemorySize, GEMM_SMEM);
    cudaFuncSetAttribute(tc_gemm<2>, cudaFuncAttributeMaxDynamicSharedMemorySize, GEMM_SMEM);

    const size_t WSZ = (size_t)EDIM * EDIM;   // 1M elems per weight

    // hi/lo splits
    split_bf16_kernel<<<(MROWS * EDIM / 4 + 255) / 256, 256>>>(x, xhi, xlo, MROWS * EDIM / 4);
    split_bf16_kernel<<<(WSZ / 4 + 255) / 256, 256>>>(Wq, whi + 0 * WSZ, wlo + 0 * WSZ, WSZ / 4);
    split_bf16_kernel<<<(WSZ / 4 + 255) / 256, 256>>>(Wk, whi + 1 * WSZ, wlo + 1 * WSZ, WSZ / 4);
    split_bf16_kernel<<<(WSZ / 4 + 255) / 256, 256>>>(Wv, whi + 2 * WSZ, wlo + 2 * WSZ, WSZ / 4);
    split_bf16_kernel<<<(WSZ / 4 + 255) / 256, 256>>>(Wp, whi + 3 * WSZ, wlo + 3 * WSZ, WSZ / 4);

    dim3 gg(EDIM / 128, MROWS / 128);   // (8, 64)
    tc_gemm<1><<<gg, 256, GEMM_SMEM>>>(xhi, xlo, whi + 0 * WSZ, wlo + 0 * WSZ, nullptr, q);
    tc_gemm<1><<<gg, 256, GEMM_SMEM>>>(xhi, xlo, whi + 1 * WSZ, wlo + 1 * WSZ, nullptr, k);
    tc_gemm<0><<<gg, 256, GEMM_SMEM>>>(xhi, xlo, whi + 2 * WSZ, wlo + 2 * WSZ, nullptr, v);

    chunk_kv_kernel<<<dim3(NCH, NHEAD, BSZ), 256>>>(k, v, kv, zk);
    prefix_scan_kernel<<<(BSZ * NHEAD * DHEAD * DHEAD + 255) / 256, 256>>>(kv, S, DHEAD * DHEAD);
    prefix_scan_kernel<<<(BSZ * NHEAD * DHEAD + 255) / 256, 256>>>(zk, Z, DHEAD);

    chunk_attn_kernel<<<dim3(NCH, NHEAD, BSZ), 256, ATTN_SMEM>>>(q, k, v, S, Z, y);

    split_bf16_kernel<<<(MROWS * EDIM / 4 + 255) / 256, 256>>>(y, yhi, ylo, MROWS * EDIM / 4);
    tc_gemm<2><<<gg, 256, GEMM_SMEM>>>(yhi, ylo, whi + 3 * WSZ, wlo + 3 * WSZ, bp, out);
}

// round 4
// speedup vs baseline: 2.3782x; 1.2707x over previous
#include <cuda_runtime.h>
#include <cuda_fp16.h>
#include <math.h>
#include <stdint.h>

// Problem constants
#define BSZ   4
#define TLEN  2048
#define EDIM  1024
#define NHEAD 16
#define DHEAD 64
#define CHK   128
#define NCH   16            // TLEN / CHK
#define MROWS (BSZ*TLEN)    // 8192

// Scratch (device globals; allocation-free rule)
__device__ float g_q[(size_t)MROWS*EDIM];
__device__ float g_k[(size_t)MROWS*EDIM];
__device__ float g_v[(size_t)MROWS*EDIM];
__device__ float g_y[(size_t)MROWS*EDIM];
__device__ float g_kv[(size_t)BSZ*NHEAD*NCH*DHEAD*DHEAD];
__device__ float g_S [(size_t)BSZ*NHEAD*NCH*DHEAD*DHEAD];
__device__ float g_zk[(size_t)BSZ*NHEAD*NCH*DHEAD];
__device__ float g_Z [(size_t)BSZ*NHEAD*NCH*DHEAD];
// fp16 buffers: activations cast to fp16; weights split hi/lo fp16
__device__ __half g_xh[(size_t)MROWS*EDIM];
__device__ __half g_yh[(size_t)MROWS*EDIM];
__device__ __half g_whi[(size_t)4*EDIM*EDIM];
__device__ __half g_wlo[(size_t)4*EDIM*EDIM];

// ---------------------------------------------------------------------------
// helpers
// ---------------------------------------------------------------------------
__device__ __forceinline__ uint32_t smem_u32(const void* p) {
    uint32_t a;
    asm("{ .reg .u64 t; cvta.to.shared.u64 t, %1; cvt.u32.u64 %0, t; }"
        : "=r"(a) : "l"(p));
    return a;
}
#define CP_ASYNC16(dst, src) \
    asm volatile("cp.async.cg.shared.global [%0], [%1], 16;" \
                 :: "r"(dst), "l"(src) : "memory")
#define CP_COMMIT() asm volatile("cp.async.commit_group;" ::: "memory")
#define CP_WAIT(N)  asm volatile("cp.async.wait_group %0;" :: "n"(N) : "memory")
#define LDSM_X4(r0, r1, r2, r3, a) \
    asm volatile("ldmatrix.sync.aligned.m8n8.x4.shared.b16 {%0,%1,%2,%3}, [%4];" \
                 : "=r"(r0), "=r"(r1), "=r"(r2), "=r"(r3) : "r"(a))
#define MMA16816H(d, a, b0v, b1v) \
    asm volatile("mma.sync.aligned.m16n8k16.row.col.f32.f16.f16.f32 " \
                 "{%0,%1,%2,%3}, {%4,%5,%6,%7}, {%8,%9}, {%0,%1,%2,%3};" \
                 : "+f"((d)[0]), "+f"((d)[1]), "+f"((d)[2]), "+f"((d)[3]) \
                 : "r"((a)[0]), "r"((a)[1]), "r"((a)[2]), "r"((a)[3]), \
                   "r"(b0v), "r"(b1v))

// ---------------------------------------------------------------------------
// fp32 -> fp16 cast (activations)
// ---------------------------------------------------------------------------
__global__ void cast_f16_kernel(const float* __restrict__ in,
                                __half* __restrict__ hh, int n4)
{
    int i = blockIdx.x * blockDim.x + threadIdx.x;
    if (i >= n4) return;
    float4 v = ((const float4*)in)[i];
    ((__half2*)hh)[2 * i + 0] = __floats2half2_rn(v.x, v.y);
    ((__half2*)hh)[2 * i + 1] = __floats2half2_rn(v.z, v.w);
}

// ---------------------------------------------------------------------------
// fp32 -> (hi, lo) fp16 split (weights)
// ---------------------------------------------------------------------------
__global__ void split_f16_kernel(const float* __restrict__ in,
                                 __half* __restrict__ hi,
                                 __half* __restrict__ lo, int n4)
{
    int i = blockIdx.x * blockDim.x + threadIdx.x;
    if (i >= n4) return;
    float4 v = ((const float4*)in)[i];
    __half h0 = __float2half_rn(v.x);
    __half h1 = __float2half_rn(v.y);
    __half h2 = __float2half_rn(v.z);
    __half h3 = __float2half_rn(v.w);
    __half l0 = __float2half_rn(v.x - __half2float(h0));
    __half l1 = __float2half_rn(v.y - __half2float(h1));
    __half l2 = __float2half_rn(v.z - __half2float(h2));
    __half l3 = __float2half_rn(v.w - __half2float(h3));
    ((__half2*)hi)[2 * i + 0] = __halves2half2(h0, h1);
    ((__half2*)hi)[2 * i + 1] = __halves2half2(h2, h3);
    ((__half2*)lo)[2 * i + 0] = __halves2half2(l0, l1);
    ((__half2*)lo)[2 * i + 1] = __halves2half2(l2, l3);
}

// ---------------------------------------------------------------------------
// mma.sync fp16 2-pass GEMM (NT): C[m,n] = sum_k A[m,k]*B[n,k].
// C = A_h*B_hi + A_h*B_lo; residual A_lo*B ~ 2.8e-4 relative.
// BM=BN=128, BK=32, 8 warps (2x4), warp tile 64x32, cp.async double-buffer.
// EPI: 0=plain, 1=phi (elu+1), 2=+bias
// ---------------------------------------------------------------------------
#define BK      32
#define LDT     40                      // BK + 8 pad (fp16 elems)
#define TILEB   (128 * LDT * 2)         // 10240 B per tile
#define STAGEB  (3 * TILEB)             // Ah, Bh, Bl
#define GEMM_SMEM (2 * STAGEB)          // 61440 B
#define NT      (EDIM / BK)             // 32 chunks

template <int EPI>
__global__ void __launch_bounds__(256, 1)
tc_gemm(const __half* __restrict__ Ah,
        const __half* __restrict__ Bhi, const __half* __restrict__ Blo,
        const float* __restrict__ bias, float* __restrict__ C)
{
    extern __shared__ char smc[];
    const uint32_t sb = smem_u32(smc);
    const int tid = threadIdx.x;
    const int wid = tid >> 5, lane = tid & 31;
    const int m0g = blockIdx.y * 128;
    const int n0g = blockIdx.x * 128;
    const int m_off = (wid & 1) * 64;       // 2 warps in M
    const int n_off = (wid >> 1) * 32;      // 4 warps in N

    // per-thread ldmatrix byte offsets within a tile (add ks*2 at use)
    uint32_t aoff[4], boff[2];
    #pragma unroll
    for (int mt = 0; mt < 4; ++mt)
        aoff[mt] = (uint32_t)(((m_off + 16 * mt + (lane & 15)) * LDT
                               + (lane >> 4) * 8) * 2);
    #pragma unroll
    for (int p = 0; p < 2; ++p)
        boff[p] = (uint32_t)(((n_off + 16 * p + ((lane >> 4) << 3) + (lane & 7)) * LDT
                              + ((lane >> 3) & 1) * 8) * 2);

    // cp.async staging: one chunk = 3 tiles of 128 rows x 32 fp16
    auto stage_tile = [&](const __half* __restrict__ src, int row0,
                          int kc, uint32_t dstbase) {
        #pragma unroll
        for (int j = 0; j < 2; ++j) {
            int u = tid + j * 256;          // 0..511
            int row = u >> 2, seg = u & 3;  // 16B segment within 64B row
            uint32_t d = dstbase + (uint32_t)((row * LDT + seg * 8) * 2);
            const __half* g = src + (size_t)(row0 + row) * EDIM + kc + seg * 8;
            CP_ASYNC16(d, g);
        }
    };
    auto stage_chunk = [&](int t, int buf) {
        int kc = t * BK;
        uint32_t base = sb + buf * STAGEB;
        stage_tile(Ah, m0g, kc, base);
        stage_tile(Bhi, n0g, kc, base + TILEB);
        stage_tile(Blo, n0g, kc, base + 2 * TILEB);
        CP_COMMIT();
    };

    float acc[4][4][4] = {};

    stage_chunk(0, 0);
    for (int t = 0; t < NT; ++t) {
        const int cur = t & 1;
        if (t + 1 < NT) {
            stage_chunk(t + 1, 1 - cur);
            CP_WAIT(1);
        } else {
            CP_WAIT(0);
        }
        __syncthreads();

        const uint32_t base = sb + cur * STAGEB;
        #pragma unroll
        for (int ks = 0; ks < BK; ks += 16) {
            const uint32_t kso = (uint32_t)(ks * 2);
            uint32_t ah[4][4], bh[2][4], bl[2][4];
            #pragma unroll
            for (int mt = 0; mt < 4; ++mt)
                LDSM_X4(ah[mt][0], ah[mt][1], ah[mt][2], ah[mt][3],
                        base + aoff[mt] + kso);
            #pragma unroll
            for (int p = 0; p < 2; ++p) {
                LDSM_X4(bh[p][0], bh[p][1], bh[p][2], bh[p][3],
                        base + TILEB + boff[p] + kso);
                LDSM_X4(bl[p][0], bl[p][1], bl[p][2], bl[p][3],
                        base + 2 * TILEB + boff[p] + kso);
            }
            #pragma unroll
            for (int i = 0; i < 4; ++i)
                #pragma unroll
                for (int j = 0; j < 4; ++j) {
                    const int p = j >> 1, w = (j & 1) * 2;
                    MMA16816H(acc[i][j], ah[i], bh[p][w], bh[p][w + 1]);
                    MMA16816H(acc[i][j], ah[i], bl[p][w], bl[p][w + 1]);
                }
        }
        __syncthreads();
    }

    // epilogue: thread owns rows (r, r+8), cols (c, c+1) per mma tile
    #pragma unroll
    for (int i = 0; i < 4; ++i) {
        const int r = m0g + m_off + 16 * i + (lane >> 2);
        #pragma unroll
        for (int j = 0; j < 4; ++j) {
            const int c = n0g + n_off + 8 * j + ((lane & 3) << 1);
            float v0 = acc[i][j][0], v1 = acc[i][j][1];
            float v2 = acc[i][j][2], v3 = acc[i][j][3];
            if (EPI == 1) {
                v0 = (v0 > 0.f) ? (v0 + 1.f) : __expf(v0);
                v1 = (v1 > 0.f) ? (v1 + 1.f) : __expf(v1);
                v2 = (v2 > 0.f) ? (v2 + 1.f) : __expf(v2);
                v3 = (v3 > 0.f) ? (v3 + 1.f) : __expf(v3);
            }
            if (EPI == 2) {
                float b0 = bias[c], b1 = bias[c + 1];
                v0 += b0; v1 += b1; v2 += b0; v3 += b1;
            }
            *(float2*)(C + (size_t)r * EDIM + c)       = make_float2(v0, v1);
            *(float2*)(C + (size_t)(r + 8) * EDIM + c) = make_float2(v2, v3);
        }
    }
}

// ---------------------------------------------------------------------------
// Per-chunk kv state: kv[d,e] = sum_c k[c,d]*v[c,e], zk[d] = sum_c k[c,d]
// ---------------------------------------------------------------------------
__global__ void __launch_bounds__(256)
chunk_kv_kernel(const float* __restrict__ k, const float* __restrict__ v,
                float* __restrict__ kv, float* __restrict__ zk)
{
    const int n = blockIdx.x, h = blockIdx.y, b = blockIdx.z;
    __shared__ float sK[32][DHEAD + 4];
    __shared__ float sV[32][DHEAD + 4];
    const int tid = threadIdx.x;
    const int d0 = (tid >> 4) << 2, e0 = (tid & 15) << 2;
    const size_t rowbase = ((size_t)(b * TLEN + n * CHK)) * EDIM + h * DHEAD;

    float acc[4][4] = {};
    float z = 0.f;

    for (int s = 0; s < 4; ++s) {
        #pragma unroll
        for (int it = 0; it < 2; ++it) {
            int i = tid + it * 256;
            int row = i >> 4, cq = (i & 15) << 2;
            *(float4*)&sK[row][cq] =
                *(const float4*)(k + rowbase + (size_t)(s * 32 + row) * EDIM + cq);
            *(float4*)&sV[row][cq] =
                *(const float4*)(v + rowbase + (size_t)(s * 32 + row) * EDIM + cq);
        }
        __syncthreads();
        #pragma unroll 8
        for (int c = 0; c < 32; ++c) {
            float kf[4], vf[4];
            *(float4*)kf = *(const float4*)&sK[c][d0];
            *(float4*)vf = *(const float4*)&sV[c][e0];
            #pragma unroll
            for (int i = 0; i < 4; ++i)
                #pragma unroll
                for (int j = 0; j < 4; ++j)
                    acc[i][j] = fmaf(kf[i], vf[j], acc[i][j]);
        }
        if (tid < DHEAD) {
            #pragma unroll 8
            for (int c = 0; c < 32; ++c) z += sK[c][tid];
        }
        __syncthreads();
    }

    const size_t obase = ((size_t)((b * NHEAD + h) * NCH) + n) * DHEAD * DHEAD;
    #pragma unroll
    for (int i = 0; i < 4; ++i)
        *(float4*)(kv + obase + (size_t)(d0 + i) * DHEAD + e0) = *(float4*)&acc[i][0];
    if (tid < DHEAD)
        zk[((size_t)((b * NHEAD + h) * NCH) + n) * DHEAD + tid] = z;
}

// ---------------------------------------------------------------------------
// Exclusive prefix over the N=16 chunk axis
// ---------------------------------------------------------------------------
__global__ void prefix_scan_kernel(const float* __restrict__ src,
                                   float* __restrict__ dst, int per)
{
    int i = blockIdx.x * blockDim.x + threadIdx.x;
    int total = BSZ * NHEAD * per;
    if (i >= total) return;
    int bh = i / per, r = i - bh * per;
    size_t base = (size_t)bh * NCH * per + r;
    float acc = 0.f;
    #pragma unroll
    for (int nn = 0; nn < NCH; ++nn) {
        dst[base + (size_t)nn * per] = acc;
        acc += src[base + (size_t)nn * per];
    }
}

// ---------------------------------------------------------------------------
// Per-chunk attention (fp32, known correct)
// ---------------------------------------------------------------------------
#define SQT_OFF   0
#define SKT_OFF   (64 * 132)
#define SV_OFF    (2 * 64 * 132)
#define SS_OFF    (SV_OFF + 128 * 68)
#define SA_OFF    (SS_OFF + 64 * 68)
#define SZ_OFF    (SA_OFF + 128 * 132)
#define SDEN_OFF  (SZ_OFF + 64)
#define ATTN_SMEM ((SDEN_OFF + 128) * 4)

__global__ void __launch_bounds__(256)
chunk_attn_kernel(const float* __restrict__ q, const float* __restrict__ k,
                  const float* __restrict__ v, const float* __restrict__ S,
                  const float* __restrict__ Z, float* __restrict__ y)
{
    extern __shared__ float sm[];
    float* sQt  = sm + SQT_OFF;
    float* sKt  = sm + SKT_OFF;
    float* sV   = sm + SV_OFF;
    float* sS   = sm + SS_OFF;
    float* sA   = sm + SA_OFF;
    float* sZ   = sm + SZ_OFF;
    float* sDen = sm + SDEN_OFF;

    const int n = blockIdx.x, h = blockIdx.y, b = blockIdx.z;
    const int tid = threadIdx.x;
    const int tx = tid & 15, ty = tid >> 4;
    const size_t rowbase = ((size_t)(b * TLEN + n * CHK)) * EDIM + h * DHEAD;

    #pragma unroll
    for (int it = 0; it < 8; ++it) {
        int i = tid + it * 256;
        int row = i >> 4, cq = (i & 15) << 2;
        float4 qv = *(const float4*)(q + rowbase + (size_t)row * EDIM + cq);
        sQt[(cq + 0) * 132 + row] = qv.x; sQt[(cq + 1) * 132 + row] = qv.y;
        sQt[(cq + 2) * 132 + row] = qv.z; sQt[(cq + 3) * 132 + row] = qv.w;
        float4 kk4 = *(const float4*)(k + rowbase + (size_t)row * EDIM + cq);
        sKt[(cq + 0) * 132 + row] = kk4.x; sKt[(cq + 1) * 132 + row] = kk4.y;
        sKt[(cq + 2) * 132 + row] = kk4.z; sKt[(cq + 3) * 132 + row] = kk4.w;
        *(float4*)&sV[row * 68 + cq] =
            *(const float4*)(v + rowbase + (size_t)row * EDIM + cq);
    }
    const size_t sbase = ((size_t)((b * NHEAD + h) * NCH) + n) * DHEAD * DHEAD;
    #pragma unroll
    for (int it = 0; it < 4; ++it) {
        int i = tid + it * 256;
        int row = i >> 4, cq = (i & 15) << 2;
        *(float4*)&sS[row * 68 + cq] = *(const float4*)(S + sbase + row * DHEAD + cq);
    }
    if (tid < DHEAD)
        sZ[tid] = Z[((size_t)((b * NHEAD + h) * NCH) + n) * DHEAD + tid];
    __syncthreads();

    {
        float acc[8][8] = {};
        #pragma unroll 8
        for (int d = 0; d < DHEAD; ++d) {
            float af[8], bf[8];
            *(float4*)&af[0] = *(const float4*)&sQt[d * 132 + ty * 4];
            *(float4*)&af[4] = *(const float4*)&sQt[d * 132 + 64 + ty * 4];
            *(float4*)&bf[0] = *(const float4*)&sKt[d * 132 + tx * 4];
            *(float4*)&bf[4] = *(const float4*)&sKt[d * 132 + 64 + tx * 4];
            #pragma unroll
            for (int i = 0; i < 8; ++i)
                #pragma unroll
                for (int j = 0; j < 8; ++j)
                    acc[i][j] = fmaf(af[i], bf[j], acc[i][j]);
        }
        #pragma unroll
        for (int j = 0; j < 8; ++j) {
            int s = (j < 4) ? (tx * 4 + j) : (64 + tx * 4 + (j - 4));
            float o0[4], o1[4];
            #pragma unroll
            for (int i = 0; i < 4; ++i) {
                int c0 = ty * 4 + i, c1 = 64 + ty * 4 + i;
                o0[i] = (s <= c0) ? acc[i][j] : 0.f;
                o1[i] = (s <= c1) ? acc[4 + i][j] : 0.f;
            }
            *(float4*)&sA[s * 132 + ty * 4]      = *(float4*)o0;
            *(float4*)&sA[s * 132 + 64 + ty * 4] = *(float4*)o1;
        }
    }
    __syncthreads();

    if (tid < CHK) {
        int c = tid;
        float s1 = 0.f;
        #pragma unroll 8
        for (int s = 0; s < CHK; ++s) s1 += sA[s * 132 + c];
        float s2 = 0.f;
        #pragma unroll 8
        for (int d = 0; d < DHEAD; ++d) s2 += sQt[d * 132 + c] * sZ[d];
        sDen[c] = 1.0f / (s1 + s2 + 1e-6f);
    }
    __syncthreads();

    {
        float acc2[8][4] = {};
        #pragma unroll 8
        for (int s = 0; s < CHK; ++s) {
            float af[8], bf[4];
            *(float4*)&af[0] = *(const float4*)&sA[s * 132 + ty * 4];
            *(float4*)&af[4] = *(const float4*)&sA[s * 132 + 64 + ty * 4];
            *(float4*)&bf[0] = *(const float4*)&sV[s * 68 + tx * 4];
            #pragma unroll
            for (int i = 0; i < 8; ++i)
                #pragma unroll
                for (int j = 0; j < 4; ++j)
                    acc2[i][j] = fmaf(af[i], bf[j], acc2[i][j]);
        }
        #pragma unroll 8
        for (int d = 0; d < DHEAD; ++d) {
            float af[8], bf[4];
            *(float4*)&af[0] = *(const float4*)&sQt[d * 132 + ty * 4];
            *(float4*)&af[4] = *(const float4*)&sQt[d * 132 + 64 + ty * 4];
            *(float4*)&bf[0] = *(const float4*)&sS[d * 68 + tx * 4];
            #pragma unroll
            for (int i = 0; i < 8; ++i)
                #pragma unroll
                for (int j = 0; j < 4; ++j)
                    acc2[i][j] = fmaf(af[i], bf[j], acc2[i][j]);
        }
        #pragma unroll
        for (int i = 0; i < 8; ++i) {
            int c = (i < 4) ? (ty * 4 + i) : (64 + ty * 4 + (i - 4));
            float inv = sDen[c];
            float o[4];
            #pragma unroll
            for (int j = 0; j < 4; ++j) o[j] = acc2[i][j] * inv;
            *(float4*)(y + rowbase + (size_t)c * EDIM + tx * 4) = *(float4*)o;
        }
    }
}

// ---------------------------------------------------------------------------
extern "C" void kernel_launch(void* const* d_in, const int* in_sizes, int n_in,
                              void* d_out, int out_size)
{
    const float* x  = (const float*)d_in[0];
    const float* Wq = (const float*)d_in[1];
    const float* Wk = (const float*)d_in[2];
    const float* Wv = (const float*)d_in[3];
    const float* Wp = (const float*)d_in[4];
    const float* bp = (const float*)d_in[5];
    float* out = (float*)d_out;

    float *q, *k, *v, *y, *kv, *S, *zk, *Z;
    __half *xh, *yh, *whi, *wlo;
    cudaGetSymbolAddress((void**)&q,  g_q);
    cudaGetSymbolAddress((void**)&k,  g_k);
    cudaGetSymbolAddress((void**)&v,  g_v);
    cudaGetSymbolAddress((void**)&y,  g_y);
    cudaGetSymbolAddress((void**)&kv, g_kv);
    cudaGetSymbolAddress((void**)&S,  g_S);
    cudaGetSymbolAddress((void**)&zk, g_zk);
    cudaGetSymbolAddress((void**)&Z,  g_Z);
    cudaGetSymbolAddress((void**)&xh, g_xh);
    cudaGetSymbolAddress((void**)&yh, g_yh);
    cudaGetSymbolAddress((void**)&whi, g_whi);
    cudaGetSymbolAddress((void**)&wlo, g_wlo);

    cudaFuncSetAttribute(chunk_attn_kernel,
                         cudaFuncAttributeMaxDynamicSharedMemorySize, ATTN_SMEM);
    cudaFuncSetAttribute(tc_gemm<0>, cudaFuncAttributeMaxDynamicSharedMemorySize, GEMM_SMEM);
    cudaFuncSetAttribute(tc_gemm<1>, cudaFuncAttributeMaxDynamicSharedMemorySize, GEMM_SMEM);
    cudaFuncSetAttribute(tc_gemm<2>, cudaFuncAttributeMaxDynamicSharedMemorySize, GEMM_SMEM);

    const size_t WSZ = (size_t)EDIM * EDIM;   // 1M elems per weight

    cast_f16_kernel<<<(MROWS * EDIM / 4 + 255) / 256, 256>>>(x, xh, MROWS * EDIM / 4);
    split_f16_kernel<<<(WSZ / 4 + 255) / 256, 256>>>(Wq, whi + 0 * WSZ, wlo + 0 * WSZ, WSZ / 4);
    split_f16_kernel<<<(WSZ / 4 + 255) / 256, 256>>>(Wk, whi + 1 * WSZ, wlo + 1 * WSZ, WSZ / 4);
    split_f16_kernel<<<(WSZ / 4 + 255) / 256, 256>>>(Wv, whi + 2 * WSZ, wlo + 2 * WSZ, WSZ / 4);
    split_f16_kernel<<<(WSZ / 4 + 255) / 256, 256>>>(Wp, whi + 3 * WSZ, wlo + 3 * WSZ, WSZ / 4);

    dim3 gg(EDIM / 128, MROWS / 128);   // (8, 64)
    tc_gemm<1><<<gg, 256, GEMM_SMEM>>>(xh, whi + 0 * WSZ, wlo + 0 * WSZ, nullptr, q);
    tc_gemm<1><<<gg, 256, GEMM_SMEM>>>(xh, whi + 1 * WSZ, wlo + 1 * WSZ, nullptr, k);
    tc_gemm<0><<<gg, 256, GEMM_SMEM>>>(xh, whi + 2 * WSZ, wlo + 2 * WSZ, nullptr, v);

    chunk_kv_kernel<<<dim3(NCH, NHEAD, BSZ), 256>>>(k, v, kv, zk);
    prefix_scan_kernel<<<(BSZ * NHEAD * DHEAD * DHEAD + 255) / 256, 256>>>(kv, S, DHEAD * DHEAD);
    prefix_scan_kernel<<<(BSZ * NHEAD * DHEAD + 255) / 256, 256>>>(zk, Z, DHEAD);

    chunk_attn_kernel<<<dim3(NCH, NHEAD, BSZ), 256, ATTN_SMEM>>>(q, k, v, S, Z, y);

    cast_f16_kernel<<<(MROWS * EDIM / 4 + 255) / 256, 256>>>(y, yh, MROWS * EDIM / 4);
    tc_gemm<2><<<gg, 256, GEMM_SMEM>>>(yh, whi + 3 * WSZ, wlo + 3 * WSZ, bp, out);
}

// round 7
// speedup vs baseline: 3.3069x; 1.3905x over previous
#include <cuda_runtime.h>
#include <cuda_fp16.h>
#include <math.h>
#include <stdint.h>

// Problem constants
#define BSZ   4
#define TLEN  2048
#define EDIM  1024
#define NHEAD 16
#define DHEAD 64
#define CHK   128
#define NCH   16            // TLEN / CHK
#define MROWS (BSZ*TLEN)    // 8192

// Scratch (device globals; allocation-free rule)
__device__ float g_q[(size_t)MROWS*EDIM];
__device__ float g_k[(size_t)MROWS*EDIM];
__device__ float g_v[(size_t)MROWS*EDIM];
__device__ float g_kv[(size_t)BSZ*NHEAD*NCH*DHEAD*DHEAD];
__device__ float g_S [(size_t)BSZ*NHEAD*NCH*DHEAD*DHEAD];
__device__ float g_zk[(size_t)BSZ*NHEAD*NCH*DHEAD];
__device__ float g_Z [(size_t)BSZ*NHEAD*NCH*DHEAD];
// fp16 buffers
__device__ __half g_xh[(size_t)MROWS*EDIM];
__device__ __half g_qh[(size_t)MROWS*EDIM];
__device__ __half g_kh[(size_t)MROWS*EDIM];
__device__ __half g_vh[(size_t)MROWS*EDIM];
__device__ __half g_yh[(size_t)MROWS*EDIM];
__device__ __half g_wh[(size_t)3*EDIM*EDIM];      // Wq,Wk,Wv single fp16
__device__ __half g_whi[(size_t)EDIM*EDIM];       // Wp hi
__device__ __half g_wlo[(size_t)EDIM*EDIM];       // Wp lo

// ---------------------------------------------------------------------------
// helpers
// ---------------------------------------------------------------------------
__device__ __forceinline__ uint32_t smem_u32(const void* p) {
    uint32_t a;
    asm("{ .reg .u64 t; cvta.to.shared.u64 t, %1; cvt.u32.u64 %0, t; }"
        : "=r"(a) : "l"(p));
    return a;
}
#define CP_ASYNC16(dst, src) \
    asm volatile("cp.async.cg.shared.global [%0], [%1], 16;" \
                 :: "r"(dst), "l"(src) : "memory")
#define CP_COMMIT() asm volatile("cp.async.commit_group;" ::: "memory")
#define CP_WAIT(N)  asm volatile("cp.async.wait_group %0;" :: "n"(N) : "memory")
#define LDSM_X4(r0, r1, r2, r3, a) \
    asm volatile("ldmatrix.sync.aligned.m8n8.x4.shared.b16 {%0,%1,%2,%3}, [%4];" \
                 : "=r"(r0), "=r"(r1), "=r"(r2), "=r"(r3) : "r"(a))
#define MMA16816H(d, a, b0v, b1v) \
    asm volatile("mma.sync.aligned.m16n8k16.row.col.f32.f16.f16.f32 " \
                 "{%0,%1,%2,%3}, {%4,%5,%6,%7}, {%8,%9}, {%0,%1,%2,%3};" \
                 : "+f"((d)[0]), "+f"((d)[1]), "+f"((d)[2]), "+f"((d)[3]) \
                 : "r"((a)[0]), "r"((a)[1]), "r"((a)[2]), "r"((a)[3]), \
                   "r"(b0v), "r"(b1v))

// ---------------------------------------------------------------------------
// fp32 -> fp16 cast
// ---------------------------------------------------------------------------
__global__ void cast_f16_kernel(const float* __restrict__ in,
                                __half* __restrict__ hh, int n4)
{
    int i = blockIdx.x * blockDim.x + threadIdx.x;
    if (i >= n4) return;
    float4 v = ((const float4*)in)[i];
    ((__half2*)hh)[2 * i + 0] = __floats2half2_rn(v.x, v.y);
    ((__half2*)hh)[2 * i + 1] = __floats2half2_rn(v.z, v.w);
}

// ---------------------------------------------------------------------------
// fp32 -> (hi, lo) fp16 split
// ---------------------------------------------------------------------------
__global__ void split_f16_kernel(const float* __restrict__ in,
                                 __half* __restrict__ hi,
                                 __half* __restrict__ lo, int n4)
{
    int i = blockIdx.x * blockDim.x + threadIdx.x;
    if (i >= n4) return;
    float4 v = ((const float4*)in)[i];
    __half h0 = __float2half_rn(v.x);
    __half h1 = __float2half_rn(v.y);
    __half h2 = __float2half_rn(v.z);
    __half h3 = __float2half_rn(v.w);
    __half l0 = __float2half_rn(v.x - __half2float(h0));
    __half l1 = __float2half_rn(v.y - __half2float(h1));
    __half l2 = __float2half_rn(v.z - __half2float(h2));
    __half l3 = __float2half_rn(v.w - __half2float(h3));
    ((__half2*)hi)[2 * i + 0] = __halves2half2(h0, h1);
    ((__half2*)hi)[2 * i + 1] = __halves2half2(h2, h3);
    ((__half2*)lo)[2 * i + 0] = __halves2half2(l0, l1);
    ((__half2*)lo)[2 * i + 1] = __halves2half2(l2, l3);
}

// ---------------------------------------------------------------------------
// mma.sync fp16 GEMM (NT): C[m,n] = sum_k A[m,k]*B[n,k].
// NPASS=1: C = A*Bhi. NPASS=2: C = A*Bhi + A*Blo (weight split).
// BM=BN=128, BK=32, 8 warps (2x4), warp tile 64x32, cp.async double-buffer.
// EPI: 0=plain, 1=phi (elu+1), 2=+bias. W16: also write fp16 copy.
// ---------------------------------------------------------------------------
#define BK      32
#define LDT     40                      // BK + 8 pad (fp16 elems)
#define TILEB   (128 * LDT * 2)         // 10240 B per tile
#define NT      (EDIM / BK)             // 32 chunks

template <int EPI, int NPASS, bool W16>
__global__ void __launch_bounds__(256, 1)
tc_gemm(const __half* __restrict__ Ah,
        const __half* __restrict__ Bhi, const __half* __restrict__ Blo,
        const float* __restrict__ bias, float* __restrict__ C,
        __half* __restrict__ C16)
{
    constexpr int NTILES = NPASS + 1;
    constexpr int STAGE = NTILES * TILEB;
    extern __shared__ char smc[];
    const uint32_t sb = smem_u32(smc);
    const int tid = threadIdx.x;
    const int wid = tid >> 5, lane = tid & 31;
    const int m0g = blockIdx.y * 128;
    const int n0g = blockIdx.x * 128;
    const int m_off = (wid & 1) * 64;
    const int n_off = (wid >> 1) * 32;

    uint32_t aoff[4], boff[2];
    #pragma unroll
    for (int mt = 0; mt < 4; ++mt)
        aoff[mt] = (uint32_t)(((m_off + 16 * mt + (lane & 15)) * LDT
                               + (lane >> 4) * 8) * 2);
    #pragma unroll
    for (int p = 0; p < 2; ++p)
        boff[p] = (uint32_t)(((n_off + 16 * p + ((lane >> 4) << 3) + (lane & 7)) * LDT
                              + ((lane >> 3) & 1) * 8) * 2);

    auto stage_tile = [&](const __half* __restrict__ src, int row0,
                          int kc, uint32_t dstbase) {
        #pragma unroll
        for (int j = 0; j < 2; ++j) {
            int u = tid + j * 256;
            int row = u >> 2, seg = u & 3;
            uint32_t d = dstbase + (uint32_t)((row * LDT + seg * 8) * 2);
            const __half* g = src + (size_t)(row0 + row) * EDIM + kc + seg * 8;
            CP_ASYNC16(d, g);
        }
    };
    auto stage_chunk = [&](int t, int buf) {
        int kc = t * BK;
        uint32_t base = sb + buf * STAGE;
        stage_tile(Ah, m0g, kc, base);
        stage_tile(Bhi, n0g, kc, base + TILEB);
        if (NPASS == 2) stage_tile(Blo, n0g, kc, base + 2 * TILEB);
        CP_COMMIT();
    };

    float acc[4][4][4] = {};

    stage_chunk(0, 0);
    for (int t = 0; t < NT; ++t) {
        const int cur = t & 1;
        if (t + 1 < NT) {
            stage_chunk(t + 1, 1 - cur);
            CP_WAIT(1);
        } else {
            CP_WAIT(0);
        }
        __syncthreads();

        const uint32_t base = sb + cur * STAGE;
        #pragma unroll
        for (int ks = 0; ks < BK; ks += 16) {
            const uint32_t kso = (uint32_t)(ks * 2);
            uint32_t ah[4][4], bh[2][4], bl[2][4];
            #pragma unroll
            for (int mt = 0; mt < 4; ++mt)
                LDSM_X4(ah[mt][0], ah[mt][1], ah[mt][2], ah[mt][3],
                        base + aoff[mt] + kso);
            #pragma unroll
            for (int p = 0; p < 2; ++p) {
                LDSM_X4(bh[p][0], bh[p][1], bh[p][2], bh[p][3],
                        base + TILEB + boff[p] + kso);
                if (NPASS == 2)
                    LDSM_X4(bl[p][0], bl[p][1], bl[p][2], bl[p][3],
                            base + 2 * TILEB + boff[p] + kso);
            }
            #pragma unroll
            for (int i = 0; i < 4; ++i)
                #pragma unroll
                for (int j = 0; j < 4; ++j) {
                    const int p = j >> 1, w = (j & 1) * 2;
                    MMA16816H(acc[i][j], ah[i], bh[p][w], bh[p][w + 1]);
                    if (NPASS == 2)
                        MMA16816H(acc[i][j], ah[i], bl[p][w], bl[p][w + 1]);
                }
        }
        __syncthreads();
    }

    #pragma unroll
    for (int i = 0; i < 4; ++i) {
        const int r = m0g + m_off + 16 * i + (lane >> 2);
        #pragma unroll
        for (int j = 0; j < 4; ++j) {
            const int c = n0g + n_off + 8 * j + ((lane & 3) << 1);
            float v0 = acc[i][j][0], v1 = acc[i][j][1];
            float v2 = acc[i][j][2], v3 = acc[i][j][3];
            if (EPI == 1) {
                v0 = (v0 > 0.f) ? (v0 + 1.f) : __expf(v0);
                v1 = (v1 > 0.f) ? (v1 + 1.f) : __expf(v1);
                v2 = (v2 > 0.f) ? (v2 + 1.f) : __expf(v2);
                v3 = (v3 > 0.f) ? (v3 + 1.f) : __expf(v3);
            }
            if (EPI == 2) {
                float b0 = bias[c], b1 = bias[c + 1];
                v0 += b0; v1 += b1; v2 += b0; v3 += b1;
            }
            *(float2*)(C + (size_t)r * EDIM + c)       = make_float2(v0, v1);
            *(float2*)(C + (size_t)(r + 8) * EDIM + c) = make_float2(v2, v3);
            if (W16) {
                *(__half2*)(C16 + (size_t)r * EDIM + c) = __floats2half2_rn(v0, v1);
                *(__half2*)(C16 + (size_t)(r + 8) * EDIM + c) = __floats2half2_rn(v2, v3);
            }
        }
    }
}

// ---------------------------------------------------------------------------
// Per-chunk kv state: kv[d,e] = sum_c k[c,d]*v[c,e], zk[d] = sum_c k[c,d]
// ---------------------------------------------------------------------------
__global__ void __launch_bounds__(256)
chunk_kv_kernel(const float* __restrict__ k, const float* __restrict__ v,
                float* __restrict__ kv, float* __restrict__ zk)
{
    const int n = blockIdx.x, h = blockIdx.y, b = blockIdx.z;
    __shared__ float sK[32][DHEAD + 4];
    __shared__ float sV[32][DHEAD + 4];
    const int tid = threadIdx.x;
    const int d0 = (tid >> 4) << 2, e0 = (tid & 15) << 2;
    const size_t rowbase = ((size_t)(b * TLEN + n * CHK)) * EDIM + h * DHEAD;

    float acc[4][4] = {};
    float z = 0.f;

    for (int s = 0; s < 4; ++s) {
        #pragma unroll
        for (int it = 0; it < 2; ++it) {
            int i = tid + it * 256;
            int row = i >> 4, cq = (i & 15) << 2;
            *(float4*)&sK[row][cq] =
                *(const float4*)(k + rowbase + (size_t)(s * 32 + row) * EDIM + cq);
            *(float4*)&sV[row][cq] =
                *(const float4*)(v + rowbase + (size_t)(s * 32 + row) * EDIM + cq);
        }
        __syncthreads();
        #pragma unroll 8
        for (int c = 0; c < 32; ++c) {
            float kf[4], vf[4];
            *(float4*)kf = *(const float4*)&sK[c][d0];
            *(float4*)vf = *(const float4*)&sV[c][e0];
            #pragma unroll
            for (int i = 0; i < 4; ++i)
                #pragma unroll
                for (int j = 0; j < 4; ++j)
                    acc[i][j] = fmaf(kf[i], vf[j], acc[i][j]);
        }
        if (tid < DHEAD) {
            #pragma unroll 8
            for (int c = 0; c < 32; ++c) z += sK[c][tid];
        }
        __syncthreads();
    }

    const size_t obase = ((size_t)((b * NHEAD + h) * NCH) + n) * DHEAD * DHEAD;
    #pragma unroll
    for (int i = 0; i < 4; ++i)
        *(float4*)(kv + obase + (size_t)(d0 + i) * DHEAD + e0) = *(float4*)&acc[i][0];
    if (tid < DHEAD)
        zk[((size_t)((b * NHEAD + h) * NCH) + n) * DHEAD + tid] = z;
}

// ---------------------------------------------------------------------------
// Exclusive prefix over the N=16 chunk axis
// ---------------------------------------------------------------------------
__global__ void prefix_scan_kernel(const float* __restrict__ src,
                                   float* __restrict__ dst, int per)
{
    int i = blockIdx.x * blockDim.x + threadIdx.x;
    int total = BSZ * NHEAD * per;
    if (i >= total) return;
    int bh = i / per, r = i - bh * per;
    size_t base = (size_t)bh * NCH * per + r;
    float acc = 0.f;
    #pragma unroll
    for (int nn = 0; nn < NCH; ++nn) {
        dst[base + (size_t)nn * per] = acc;
        acc += src[base + (size_t)nn * per];
    }
}

// ---------------------------------------------------------------------------
// Tensor-core per-chunk attention. One CTA per (b,h,n), 256 threads, 8 warps.
// A = QK^T (fp16 mma, fp32 acc), masked + stored fp16; den via quad-shuffle
// rowsums + smem atomics + phiq.Z; num = A.V + Q.S via NT mma against
// transposed-staged V^T / S^T. Writes y directly as fp16.
// ---------------------------------------------------------------------------
#define SQ_O    0                       // [128][72] fp16
#define SK_O    18432                   // [128][72] fp16
#define SVT_O   36864                   // [64][136] fp16 (V^T, e rows)
#define SST_O   54272                   // [64][72]  fp16 (S^T, e rows)
#define SA_O    63488                   // [128][136] fp16 masked A
#define SZ_O    98304                   // [64] fp32
#define SDEN_O  98560                   // [128] fp32
#define ATTN_SMEM 99072

__global__ void __launch_bounds__(256)
chunk_attn_mma(const __half* __restrict__ q16, const __half* __restrict__ k16,
               const __half* __restrict__ v16, const float* __restrict__ S,
               const float* __restrict__ Z, __half* __restrict__ y16)
{
    extern __shared__ char smc[];
    const uint32_t sb = smem_u32(smc);
    float* sZ   = (float*)(smc + SZ_O);
    float* sDen = (float*)(smc + SDEN_O);

    const int n = blockIdx.x, h = blockIdx.y, b = blockIdx.z;
    const int tid = threadIdx.x;
    const int wid = tid >> 5, lane = tid & 31;
    const int m_off = (wid & 1) * 64;
    const int n_off = (wid >> 1) * 32;      // pass A (N=128)
    const int n_off2 = (wid >> 1) * 16;     // pass B (N=64)
    const size_t rowbase = ((size_t)(b * TLEN + n * CHK)) * EDIM + h * DHEAD;
    const size_t sbase = ((size_t)((b * NHEAD + h) * NCH) + n) * DHEAD * DHEAD;
    const size_t zbase = ((size_t)((b * NHEAD + h) * NCH) + n) * DHEAD;

    // stage Q, K (row-major, stride 72): 128 rows x 64 halves = 1024 x 16B each
    #pragma unroll
    for (int it = 0; it < 4; ++it) {
        int u = tid + it * 256;             // 0..1023
        int row = u >> 3, seg = u & 7;      // 8 x 16B segments per row
        uint32_t so = (uint32_t)((row * 72 + seg * 8) * 2);
        *(uint4*)(smc + SQ_O + so) =
            *(const uint4*)(q16 + rowbase + (size_t)row * EDIM + seg * 8);
        *(uint4*)(smc + SK_O + so) =
            *(const uint4*)(k16 + rowbase + (size_t)row * EDIM + seg * 8);
    }
    // stage V^T [e][s] and S^T [e][d]
    {
        const int e = tid & 63;
        __half* vt = (__half*)(smc + SVT_O);
        for (int s = tid >> 6; s < CHK; s += 4)
            vt[e * 136 + s] = v16[rowbase + (size_t)s * EDIM + e];
        __half* st = (__half*)(smc + SST_O);
        for (int d = tid >> 6; d < DHEAD; d += 4)
            st[e * 72 + d] = __float2half_rn(S[sbase + (size_t)d * DHEAD + e]);
    }
    if (tid < DHEAD) sZ[tid] = Z[zbase + tid];
    __syncthreads();

    // den init: eps + phiq . Z
    if (tid < CHK) {
        float s2 = 1e-6f;
        const __half2* qr = (const __half2*)(smc + SQ_O + tid * 144);
        #pragma unroll
        for (int d2 = 0; d2 < 32; ++d2) {
            float2 qq = __half22float2(qr[d2]);
            s2 += qq.x * sZ[2 * d2] + qq.y * sZ[2 * d2 + 1];
        }
        sDen[tid] = s2;
    }
    __syncthreads();

    // fragment offsets
    uint32_t aoffQ[4], aoffA[4], boffK[2];
    #pragma unroll
    for (int mt = 0; mt < 4; ++mt) {
        int rr = m_off + 16 * mt + (lane & 15);
        aoffQ[mt] = (uint32_t)((rr * 72 + (lane >> 4) * 8) * 2);
        aoffA[mt] = (uint32_t)((rr * 136 + (lane >> 4) * 8) * 2);
    }
    #pragma unroll
    for (int p = 0; p < 2; ++p)
        boffK[p] = (uint32_t)(((n_off + 16 * p + ((lane >> 4) << 3) + (lane & 7)) * 72
                               + ((lane >> 3) & 1) * 8) * 2);
    const uint32_t boffV = (uint32_t)(((n_off2 + ((lane >> 4) << 3) + (lane & 7)) * 136
                                      + ((lane >> 3) & 1) * 8) * 2);
    const uint32_t boffS = (uint32_t)(((n_off2 + ((lane >> 4) << 3) + (lane & 7)) * 72
                                      + ((lane >> 3) & 1) * 8) * 2);

    // ---- Pass A: A = Q K^T (128x128, k=64) ----
    {
        float acc[4][4][4] = {};
        #pragma unroll
        for (int ks = 0; ks < DHEAD; ks += 16) {
            const uint32_t kso = (uint32_t)(ks * 2);
            uint32_t a[4][4], bk[2][4];
            #pragma unroll
            for (int mt = 0; mt < 4; ++mt)
                LDSM_X4(a[mt][0], a[mt][1], a[mt][2], a[mt][3],
                        sb + SQ_O + aoffQ[mt] + kso);
            #pragma unroll
            for (int p = 0; p < 2; ++p)
                LDSM_X4(bk[p][0], bk[p][1], bk[p][2], bk[p][3],
                        sb + SK_O + boffK[p] + kso);
            #pragma unroll
            for (int i = 0; i < 4; ++i)
                #pragma unroll
                for (int j = 0; j < 4; ++j) {
                    const int p = j >> 1, w = (j & 1) * 2;
                    MMA16816H(acc[i][j], a[i], bk[p][w], bk[p][w + 1]);
                }
        }
        // mask, store fp16 A, rowsum -> den
        #pragma unroll
        for (int i = 0; i < 4; ++i) {
            const int r1 = m_off + 16 * i + (lane >> 2);
            const int r2 = r1 + 8;
            float rs1 = 0.f, rs2 = 0.f;
            #pragma unroll
            for (int j = 0; j < 4; ++j) {
                const int c = n_off + 8 * j + ((lane & 3) << 1);
                float v0 = (c <= r1) ? acc[i][j][0] : 0.f;
                float v1 = (c + 1 <= r1) ? acc[i][j][1] : 0.f;
                float v2 = (c <= r2) ? acc[i][j][2] : 0.f;
                float v3 = (c + 1 <= r2) ? acc[i][j][3] : 0.f;
                rs1 += v0 + v1; rs2 += v2 + v3;
                *(__half2*)(smc + SA_O + (r1 * 136 + c) * 2) = __floats2half2_rn(v0, v1);
                *(__half2*)(smc + SA_O + (r2 * 136 + c) * 2) = __floats2half2_rn(v2, v3);
            }
            rs1 += __shfl_xor_sync(0xFFFFFFFFu, rs1, 1);
            rs1 += __shfl_xor_sync(0xFFFFFFFFu, rs1, 2);
            rs2 += __shfl_xor_sync(0xFFFFFFFFu, rs2, 1);
            rs2 += __shfl_xor_sync(0xFFFFFFFFu, rs2, 2);
            if ((lane & 3) == 0) {
                atomicAdd(&sDen[r1], rs1);
                atomicAdd(&sDen[r2], rs2);
            }
        }
    }
    __syncthreads();

    // ---- Pass B: num = A.V + Q.S  (128x64) ----
    {
        float acc2[4][2][4] = {};
        #pragma unroll
        for (int ks = 0; ks < CHK; ks += 16) {        // A.V, k=128
            const uint32_t kso = (uint32_t)(ks * 2);
            uint32_t a[4][4], bv[4];
            #pragma unroll
            for (int mt = 0; mt < 4; ++mt)
                LDSM_X4(a[mt][0], a[mt][1], a[mt][2], a[mt][3],
                        sb + SA_O + aoffA[mt] + kso);
            LDSM_X4(bv[0], bv[1], bv[2], bv[3], sb + SVT_O + boffV + kso);
            #pragma unroll
            for (int i = 0; i < 4; ++i)
                #pragma unroll
                for (int j2 = 0; j2 < 2; ++j2)
                    MMA16816H(acc2[i][j2], a[i], bv[2 * j2], bv[2 * j2 + 1]);
        }
        #pragma unroll
        for (int ks = 0; ks < DHEAD; ks += 16) {      // Q.S, k=64
            const uint32_t kso = (uint32_t)(ks * 2);
            uint32_t a[4][4], bs[4];
            #pragma unroll
            for (int mt = 0; mt < 4; ++mt)
                LDSM_X4(a[mt][0], a[mt][1], a[mt][2], a[mt][3],
                        sb + SQ_O + aoffQ[mt] + kso);
            LDSM_X4(bs[0], bs[1], bs[2], bs[3], sb + SST_O + boffS + kso);
            #pragma unroll
            for (int i = 0; i < 4; ++i)
                #pragma unroll
                for (int j2 = 0; j2 < 2; ++j2)
                    MMA16816H(acc2[i][j2], a[i], bs[2 * j2], bs[2 * j2 + 1]);
        }
        // write y = num / den (fp16)
        #pragma unroll
        for (int i = 0; i < 4; ++i) {
            const int r1 = m_off + 16 * i + (lane >> 2);
            const int r2 = r1 + 8;
            const float inv1 = 1.0f / sDen[r1];
            const float inv2 = 1.0f / sDen[r2];
            #pragma unroll
            for (int j2 = 0; j2 < 2; ++j2) {
                const int c = n_off2 + 8 * j2 + ((lane & 3) << 1);
                *(__half2*)(y16 + rowbase + (size_t)r1 * EDIM + c) =
                    __floats2half2_rn(acc2[i][j2][0] * inv1, acc2[i][j2][1] * inv1);
                *(__half2*)(y16 + rowbase + (size_t)r2 * EDIM + c) =
                    __floats2half2_rn(acc2[i][j2][2] * inv2, acc2[i][j2][3] * inv2);
            }
        }
    }
}

// ---------------------------------------------------------------------------
extern "C" void kernel_launch(void* const* d_in, const int* in_sizes, int n_in,
                              void* d_out, int out_size)
{
    const float* x  = (const float*)d_in[0];
    const float* Wq = (const float*)d_in[1];
    const float* Wk = (const float*)d_in[2];
    const float* Wv = (const float*)d_in[3];
    const float* Wp = (const float*)d_in[4];
    const float* bp = (const float*)d_in[5];
    float* out = (float*)d_out;

    float *q, *k, *v, *kv, *S, *zk, *Z;
    __half *xh, *qh, *kh, *vh, *yh, *wh, *whi, *wlo;
    cudaGetSymbolAddress((void**)&q,  g_q);
    cudaGetSymbolAddress((void**)&k,  g_k);
    cudaGetSymbolAddress((void**)&v,  g_v);
    cudaGetSymbolAddress((void**)&kv, g_kv);
    cudaGetSymbolAddress((void**)&S,  g_S);
    cudaGetSymbolAddress((void**)&zk, g_zk);
    cudaGetSymbolAddress((void**)&Z,  g_Z);
    cudaGetSymbolAddress((void**)&xh, g_xh);
    cudaGetSymbolAddress((void**)&qh, g_qh);
    cudaGetSymbolAddress((void**)&kh, g_kh);
    cudaGetSymbolAddress((void**)&vh, g_vh);
    cudaGetSymbolAddress((void**)&yh, g_yh);
    cudaGetSymbolAddress((void**)&wh, g_wh);
    cudaGetSymbolAddress((void**)&whi, g_whi);
    cudaGetSymbolAddress((void**)&wlo, g_wlo);

    const int SM1 = 2 * 2 * TILEB;   // NPASS=1: 40960
    const int SM2 = 2 * 3 * TILEB;   // NPASS=2: 61440
    cudaFuncSetAttribute(tc_gemm<1,1,true>,  cudaFuncAttributeMaxDynamicSharedMemorySize, SM1);
    cudaFuncSetAttribute(tc_gemm<0,1,true>,  cudaFuncAttributeMaxDynamicSharedMemorySize, SM1);
    cudaFuncSetAttribute(tc_gemm<2,2,false>, cudaFuncAttributeMaxDynamicSharedMemorySize, SM2);
    cudaFuncSetAttribute(chunk_attn_mma,
                         cudaFuncAttributeMaxDynamicSharedMemorySize, ATTN_SMEM);

    const size_t WSZ = (size_t)EDIM * EDIM;

    cast_f16_kernel<<<(MROWS * EDIM / 4 + 255) / 256, 256>>>(x, xh, MROWS * EDIM / 4);
    cast_f16_kernel<<<(WSZ / 4 + 255) / 256, 256>>>(Wq, wh + 0 * WSZ, WSZ / 4);
    cast_f16_kernel<<<(WSZ / 4 + 255) / 256, 256>>>(Wk, wh + 1 * WSZ, WSZ / 4);
    cast_f16_kernel<<<(WSZ / 4 + 255) / 256, 256>>>(Wv, wh + 2 * WSZ, WSZ / 4);
    split_f16_kernel<<<(WSZ / 4 + 255) / 256, 256>>>(Wp, whi, wlo, WSZ / 4);

    dim3 gg(EDIM / 128, MROWS / 128);   // (8, 64)
    tc_gemm<1,1,true><<<gg, 256, SM1>>>(xh, wh + 0 * WSZ, nullptr, nullptr, q, qh);
    tc_gemm<1,1,true><<<gg, 256, SM1>>>(xh, wh + 1 * WSZ, nullptr, nullptr, k, kh);
    tc_gemm<0,1,true><<<gg, 256, SM1>>>(xh, wh + 2 * WSZ, nullptr, nullptr, v, vh);

    chunk_kv_kernel<<<dim3(NCH, NHEAD, BSZ), 256>>>(k, v, kv, zk);
    prefix_scan_kernel<<<(BSZ * NHEAD * DHEAD * DHEAD + 255) / 256, 256>>>(kv, S, DHEAD * DHEAD);
    prefix_scan_kernel<<<(BSZ * NHEAD * DHEAD + 255) / 256, 256>>>(zk, Z, DHEAD);

    chunk_attn_mma<<<dim3(NCH, NHEAD, BSZ), 256, ATTN_SMEM>>>(qh, kh, vh, S, Z, yh);

    tc_gemm<2,2,false><<<gg, 256, SM2>>>(yh, whi, wlo, bp, out, nullptr);
}

// round 8
// speedup vs baseline: 4.0850x; 1.2353x over previous
#include <cuda_runtime.h>
#include <cuda_fp16.h>
#include <math.h>
#include <stdint.h>

// Problem constants
#define BSZ   4
#define TLEN  2048
#define EDIM  1024
#define NHEAD 16
#define DHEAD 64
#define CHK   128
#define NCH   16            // TLEN / CHK
#define MROWS (BSZ*TLEN)    // 8192

// Scratch (device globals; allocation-free rule)
__device__ float g_q[(size_t)MROWS*EDIM];
__device__ float g_k[(size_t)MROWS*EDIM];
__device__ float g_v[(size_t)MROWS*EDIM];
__device__ float g_kv[(size_t)BSZ*NHEAD*NCH*DHEAD*DHEAD];
__device__ float g_S [(size_t)BSZ*NHEAD*NCH*DHEAD*DHEAD];
__device__ float g_zk[(size_t)BSZ*NHEAD*NCH*DHEAD];
__device__ float g_Z [(size_t)BSZ*NHEAD*NCH*DHEAD];
// fp16 buffers
__device__ __half g_xh[(size_t)MROWS*EDIM];
__device__ __half g_qh[(size_t)MROWS*EDIM];
__device__ __half g_kh[(size_t)MROWS*EDIM];
__device__ __half g_vh[(size_t)MROWS*EDIM];
__device__ __half g_yh[(size_t)MROWS*EDIM];
__device__ __half g_wh[(size_t)4*EDIM*EDIM];      // Wq,Wk,Wv,Wp fp16

// ---------------------------------------------------------------------------
// helpers
// ---------------------------------------------------------------------------
__device__ __forceinline__ uint32_t smem_u32(const void* p) {
    uint32_t a;
    asm("{ .reg .u64 t; cvta.to.shared.u64 t, %1; cvt.u32.u64 %0, t; }"
        : "=r"(a) : "l"(p));
    return a;
}
#define CP_ASYNC16(dst, src) \
    asm volatile("cp.async.cg.shared.global [%0], [%1], 16;" \
                 :: "r"(dst), "l"(src) : "memory")
#define CP_COMMIT() asm volatile("cp.async.commit_group;" ::: "memory")
#define CP_WAIT(N)  asm volatile("cp.async.wait_group %0;" :: "n"(N) : "memory")
#define LDSM_X4(r0, r1, r2, r3, a) \
    asm volatile("ldmatrix.sync.aligned.m8n8.x4.shared.b16 {%0,%1,%2,%3}, [%4];" \
                 : "=r"(r0), "=r"(r1), "=r"(r2), "=r"(r3) : "r"(a))
#define MMA16816H(d, a, b0v, b1v) \
    asm volatile("mma.sync.aligned.m16n8k16.row.col.f32.f16.f16.f32 " \
                 "{%0,%1,%2,%3}, {%4,%5,%6,%7}, {%8,%9}, {%0,%1,%2,%3};" \
                 : "+f"((d)[0]), "+f"((d)[1]), "+f"((d)[2]), "+f"((d)[3]) \
                 : "r"((a)[0]), "r"((a)[1]), "r"((a)[2]), "r"((a)[3]), \
                   "r"(b0v), "r"(b1v))

// ---------------------------------------------------------------------------
// fp32 -> fp16 cast (x activations)
// ---------------------------------------------------------------------------
__global__ void cast_f16_kernel(const float* __restrict__ in,
                                __half* __restrict__ hh, int n4)
{
    int i = blockIdx.x * blockDim.x + threadIdx.x;
    if (i >= n4) return;
    float4 v = ((const float4*)in)[i];
    ((__half2*)hh)[2 * i + 0] = __floats2half2_rn(v.x, v.y);
    ((__half2*)hh)[2 * i + 1] = __floats2half2_rn(v.z, v.w);
}

// batched: cast all 4 weight matrices (blockIdx.y selects)
__global__ void cast_w_kernel(const float* __restrict__ W0,
                              const float* __restrict__ W1,
                              const float* __restrict__ W2,
                              const float* __restrict__ W3,
                              __half* __restrict__ dst, int n4)
{
    int i = blockIdx.x * blockDim.x + threadIdx.x;
    if (i >= n4) return;
    const float* src = (blockIdx.y == 0) ? W0 : (blockIdx.y == 1) ? W1
                     : (blockIdx.y == 2) ? W2 : W3;
    __half* out = dst + (size_t)blockIdx.y * EDIM * EDIM;
    float4 v = ((const float4*)src)[i];
    ((__half2*)out)[2 * i + 0] = __floats2half2_rn(v.x, v.y);
    ((__half2*)out)[2 * i + 1] = __floats2half2_rn(v.z, v.w);
}

// ---------------------------------------------------------------------------
// mma.sync fp16 GEMM (NT): C[m,n] = sum_k A[m,k]*B[n,k].
// BM=BN=128, BK=32, 8 warps (2x4), warp tile 64x32, cp.async double-buffer.
// QKV=true: batched over blockIdx.z (0=q,1=k phi epilogue; 2=v plain),
//           writes fp32 + fp16. QKV=false: single GEMM, +bias, fp32 only.
// ---------------------------------------------------------------------------
#define BK      32
#define LDT     40                      // BK + 8 pad (fp16 elems)
#define TILEB   (128 * LDT * 2)         // 10240 B per tile
#define NT      (EDIM / BK)             // 32 chunks
#define GEMM_SMEM (2 * 2 * TILEB)       // 40960 B

template <bool QKV>
__global__ void __launch_bounds__(256, 1)
tc_gemm(const __half* __restrict__ Ah, const __half* __restrict__ Wbase,
        const float* __restrict__ bias,
        float* __restrict__ C0, float* __restrict__ C1, float* __restrict__ C2,
        __half* __restrict__ H0, __half* __restrict__ H1, __half* __restrict__ H2)
{
    extern __shared__ char smc[];
    const uint32_t sb = smem_u32(smc);
    const int tid = threadIdx.x;
    const int wid = tid >> 5, lane = tid & 31;
    const int m0g = blockIdx.y * 128;
    const int n0g = blockIdx.x * 128;
    const int m_off = (wid & 1) * 64;
    const int n_off = (wid >> 1) * 32;
    const int z = QKV ? blockIdx.z : 0;
    const __half* Bh = Wbase + (size_t)z * EDIM * EDIM;
    float* C = QKV ? ((z == 0) ? C0 : (z == 1) ? C1 : C2) : C0;
    __half* C16 = QKV ? ((z == 0) ? H0 : (z == 1) ? H1 : H2) : nullptr;
    const bool phi = QKV && (z < 2);

    uint32_t aoff[4], boff[2];
    #pragma unroll
    for (int mt = 0; mt < 4; ++mt)
        aoff[mt] = (uint32_t)(((m_off + 16 * mt + (lane & 15)) * LDT
                               + (lane >> 4) * 8) * 2);
    #pragma unroll
    for (int p = 0; p < 2; ++p)
        boff[p] = (uint32_t)(((n_off + 16 * p + ((lane >> 4) << 3) + (lane & 7)) * LDT
                              + ((lane >> 3) & 1) * 8) * 2);

    auto stage_tile = [&](const __half* __restrict__ src, int row0,
                          int kc, uint32_t dstbase) {
        #pragma unroll
        for (int j = 0; j < 2; ++j) {
            int u = tid + j * 256;
            int row = u >> 2, seg = u & 3;
            uint32_t d = dstbase + (uint32_t)((row * LDT + seg * 8) * 2);
            const __half* g = src + (size_t)(row0 + row) * EDIM + kc + seg * 8;
            CP_ASYNC16(d, g);
        }
    };
    auto stage_chunk = [&](int t, int buf) {
        int kc = t * BK;
        uint32_t base = sb + buf * 2 * TILEB;
        stage_tile(Ah, m0g, kc, base);
        stage_tile(Bh, n0g, kc, base + TILEB);
        CP_COMMIT();
    };

    float acc[4][4][4] = {};

    stage_chunk(0, 0);
    for (int t = 0; t < NT; ++t) {
        const int cur = t & 1;
        if (t + 1 < NT) {
            stage_chunk(t + 1, 1 - cur);
            CP_WAIT(1);
        } else {
            CP_WAIT(0);
        }
        __syncthreads();

        const uint32_t base = sb + cur * 2 * TILEB;
        #pragma unroll
        for (int ks = 0; ks < BK; ks += 16) {
            const uint32_t kso = (uint32_t)(ks * 2);
            uint32_t ah[4][4], bh[2][4];
            #pragma unroll
            for (int mt = 0; mt < 4; ++mt)
                LDSM_X4(ah[mt][0], ah[mt][1], ah[mt][2], ah[mt][3],
                        base + aoff[mt] + kso);
            #pragma unroll
            for (int p = 0; p < 2; ++p)
                LDSM_X4(bh[p][0], bh[p][1], bh[p][2], bh[p][3],
                        base + TILEB + boff[p] + kso);
            #pragma unroll
            for (int i = 0; i < 4; ++i)
                #pragma unroll
                for (int j = 0; j < 4; ++j) {
                    const int p = j >> 1, w = (j & 1) * 2;
                    MMA16816H(acc[i][j], ah[i], bh[p][w], bh[p][w + 1]);
                }
        }
        __syncthreads();
    }

    #pragma unroll
    for (int i = 0; i < 4; ++i) {
        const int r = m0g + m_off + 16 * i + (lane >> 2);
        #pragma unroll
        for (int j = 0; j < 4; ++j) {
            const int c = n0g + n_off + 8 * j + ((lane & 3) << 1);
            float v0 = acc[i][j][0], v1 = acc[i][j][1];
            float v2 = acc[i][j][2], v3 = acc[i][j][3];
            if (QKV) {
                if (phi) {
                    v0 = (v0 > 0.f) ? (v0 + 1.f) : __expf(v0);
                    v1 = (v1 > 0.f) ? (v1 + 1.f) : __expf(v1);
                    v2 = (v2 > 0.f) ? (v2 + 1.f) : __expf(v2);
                    v3 = (v3 > 0.f) ? (v3 + 1.f) : __expf(v3);
                }
            } else {
                float b0 = bias[c], b1 = bias[c + 1];
                v0 += b0; v1 += b1; v2 += b0; v3 += b1;
            }
            *(float2*)(C + (size_t)r * EDIM + c)       = make_float2(v0, v1);
            *(float2*)(C + (size_t)(r + 8) * EDIM + c) = make_float2(v2, v3);
            if (QKV) {
                *(__half2*)(C16 + (size_t)r * EDIM + c) = __floats2half2_rn(v0, v1);
                *(__half2*)(C16 + (size_t)(r + 8) * EDIM + c) = __floats2half2_rn(v2, v3);
            }
        }
    }
}

// ---------------------------------------------------------------------------
// Per-chunk kv state via fp16 mma: kv[d,e] = sum_c k[c,d]*v[c,e] (64x64, k=128)
// zk[d] = sum_c k[c,d]. One CTA per (b,h,n), 256 threads (8 warps 2x4).
// K^T and V^T transposed-staged at stride 136 (conflict-free ldmatrix).
// ---------------------------------------------------------------------------
__global__ void __launch_bounds__(256)
chunk_kv_mma(const __half* __restrict__ k16, const __half* __restrict__ v16,
             float* __restrict__ kv, float* __restrict__ zk)
{
    __shared__ __half sKt[64 * 136];
    __shared__ __half sVt[64 * 136];
    const uint32_t sbK = smem_u32(sKt);
    const uint32_t sbV = smem_u32(sVt);

    const int n = blockIdx.x, h = blockIdx.y, b = blockIdx.z;
    const int tid = threadIdx.x;
    const int wid = tid >> 5, lane = tid & 31;
    const int m_off = (wid & 1) * 32;       // d
    const int n_off = (wid >> 1) * 16;      // e
    const size_t rowbase = ((size_t)(b * TLEN + n * CHK)) * EDIM + h * DHEAD;

    // transposed staging: sKt[d][c] = k[c,d], sVt[e][c] = v[c,e]
    {
        const int d = tid & 63;
        for (int c = tid >> 6; c < CHK; c += 4) {
            sKt[d * 136 + c] = k16[rowbase + (size_t)c * EDIM + d];
            sVt[d * 136 + c] = v16[rowbase + (size_t)c * EDIM + d];
        }
    }
    __syncthreads();

    // zk
    if (tid < DHEAD) {
        float z = 0.f;
        #pragma unroll 8
        for (int c = 0; c < CHK; ++c) z += __half2float(sKt[tid * 136 + c]);
        zk[((size_t)((b * NHEAD + h) * NCH) + n) * DHEAD + tid] = z;
    }

    uint32_t aoff[2];
    #pragma unroll
    for (int mt = 0; mt < 2; ++mt)
        aoff[mt] = (uint32_t)(((m_off + 16 * mt + (lane & 15)) * 136
                               + (lane >> 4) * 8) * 2);
    const uint32_t boff = (uint32_t)(((n_off + ((lane >> 4) << 3) + (lane & 7)) * 136
                                     + ((lane >> 3) & 1) * 8) * 2);

    float acc[2][2][4] = {};
    #pragma unroll
    for (int ks = 0; ks < CHK; ks += 16) {
        const uint32_t kso = (uint32_t)(ks * 2);
        uint32_t a[2][4], bv[4];
        #pragma unroll
        for (int mt = 0; mt < 2; ++mt)
            LDSM_X4(a[mt][0], a[mt][1], a[mt][2], a[mt][3], sbK + aoff[mt] + kso);
        LDSM_X4(bv[0], bv[1], bv[2], bv[3], sbV + boff + kso);
        #pragma unroll
        for (int i = 0; i < 2; ++i)
            #pragma unroll
            for (int j2 = 0; j2 < 2; ++j2)
                MMA16816H(acc[i][j2], a[i], bv[2 * j2], bv[2 * j2 + 1]);
    }

    const size_t obase = ((size_t)((b * NHEAD + h) * NCH) + n) * DHEAD * DHEAD;
    #pragma unroll
    for (int i = 0; i < 2; ++i) {
        const int r1 = m_off + 16 * i + (lane >> 2);
        const int r2 = r1 + 8;
        #pragma unroll
        for (int j2 = 0; j2 < 2; ++j2) {
            const int c = n_off + 8 * j2 + ((lane & 3) << 1);
            *(float2*)(kv + obase + (size_t)r1 * DHEAD + c) =
                make_float2(acc[i][j2][0], acc[i][j2][1]);
            *(float2*)(kv + obase + (size_t)r2 * DHEAD + c) =
                make_float2(acc[i][j2][2], acc[i][j2][3]);
        }
    }
}

// ---------------------------------------------------------------------------
// Exclusive prefix over the N=16 chunk axis
// ---------------------------------------------------------------------------
__global__ void prefix_scan_kernel(const float* __restrict__ src,
                                   float* __restrict__ dst, int per)
{
    int i = blockIdx.x * blockDim.x + threadIdx.x;
    int total = BSZ * NHEAD * per;
    if (i >= total) return;
    int bh = i / per, r = i - bh * per;
    size_t base = (size_t)bh * NCH * per + r;
    float acc = 0.f;
    #pragma unroll
    for (int nn = 0; nn < NCH; ++nn) {
        dst[base + (size_t)nn * per] = acc;
        acc += src[base + (size_t)nn * per];
    }
}

// ---------------------------------------------------------------------------
// Tensor-core per-chunk attention (known-good from R6)
// ---------------------------------------------------------------------------
#define SQ_O    0                       // [128][72] fp16
#define SK_O    18432                   // [128][72] fp16
#define SVT_O   36864                   // [64][136] fp16 (V^T, e rows)
#define SST_O   54272                   // [64][72]  fp16 (S^T, e rows)
#define SA_O    63488                   // [128][136] fp16 masked A
#define SZ_O    98304                   // [64] fp32
#define SDEN_O  98560                   // [128] fp32
#define ATTN_SMEM 99072

__global__ void __launch_bounds__(256)
chunk_attn_mma(const __half* __restrict__ q16, const __half* __restrict__ k16,
               const __half* __restrict__ v16, const float* __restrict__ S,
               const float* __restrict__ Z, __half* __restrict__ y16)
{
    extern __shared__ char smc[];
    const uint32_t sb = smem_u32(smc);
    float* sZ   = (float*)(smc + SZ_O);
    float* sDen = (float*)(smc + SDEN_O);

    const int n = blockIdx.x, h = blockIdx.y, b = blockIdx.z;
    const int tid = threadIdx.x;
    const int wid = tid >> 5, lane = tid & 31;
    const int m_off = (wid & 1) * 64;
    const int n_off = (wid >> 1) * 32;      // pass A (N=128)
    const int n_off2 = (wid >> 1) * 16;     // pass B (N=64)
    const size_t rowbase = ((size_t)(b * TLEN + n * CHK)) * EDIM + h * DHEAD;
    const size_t sbase = ((size_t)((b * NHEAD + h) * NCH) + n) * DHEAD * DHEAD;
    const size_t zbase = ((size_t)((b * NHEAD + h) * NCH) + n) * DHEAD;

    #pragma unroll
    for (int it = 0; it < 4; ++it) {
        int u = tid + it * 256;             // 0..1023
        int row = u >> 3, seg = u & 7;
        uint32_t so = (uint32_t)((row * 72 + seg * 8) * 2);
        *(uint4*)(smc + SQ_O + so) =
            *(const uint4*)(q16 + rowbase + (size_t)row * EDIM + seg * 8);
        *(uint4*)(smc + SK_O + so) =
            *(const uint4*)(k16 + rowbase + (size_t)row * EDIM + seg * 8);
    }
    {
        const int e = tid & 63;
        __half* vt = (__half*)(smc + SVT_O);
        for (int s = tid >> 6; s < CHK; s += 4)
            vt[e * 136 + s] = v16[rowbase + (size_t)s * EDIM + e];
        __half* st = (__half*)(smc + SST_O);
        for (int d = tid >> 6; d < DHEAD; d += 4)
            st[e * 72 + d] = __float2half_rn(S[sbase + (size_t)d * DHEAD + e]);
    }
    if (tid < DHEAD) sZ[tid] = Z[zbase + tid];
    __syncthreads();

    if (tid < CHK) {
        float s2 = 1e-6f;
        const __half2* qr = (const __half2*)(smc + SQ_O + tid * 144);
        #pragma unroll
        for (int d2 = 0; d2 < 32; ++d2) {
            float2 qq = __half22float2(qr[d2]);
            s2 += qq.x * sZ[2 * d2] + qq.y * sZ[2 * d2 + 1];
        }
        sDen[tid] = s2;
    }
    __syncthreads();

    uint32_t aoffQ[4], aoffA[4], boffK[2];
    #pragma unroll
    for (int mt = 0; mt < 4; ++mt) {
        int rr = m_off + 16 * mt + (lane & 15);
        aoffQ[mt] = (uint32_t)((rr * 72 + (lane >> 4) * 8) * 2);
        aoffA[mt] = (uint32_t)((rr * 136 + (lane >> 4) * 8) * 2);
    }
    #pragma unroll
    for (int p = 0; p < 2; ++p)
        boffK[p] = (uint32_t)(((n_off + 16 * p + ((lane >> 4) << 3) + (lane & 7)) * 72
                               + ((lane >> 3) & 1) * 8) * 2);
    const uint32_t boffV = (uint32_t)(((n_off2 + ((lane >> 4) << 3) + (lane & 7)) * 136
                                      + ((lane >> 3) & 1) * 8) * 2);
    const uint32_t boffS = (uint32_t)(((n_off2 + ((lane >> 4) << 3) + (lane & 7)) * 72
                                      + ((lane >> 3) & 1) * 8) * 2);

    // ---- Pass A: A = Q K^T ----
    {
        float acc[4][4][4] = {};
        #pragma unroll
        for (int ks = 0; ks < DHEAD; ks += 16) {
            const uint32_t kso = (uint32_t)(ks * 2);
            uint32_t a[4][4], bk[2][4];
            #pragma unroll
            for (int mt = 0; mt < 4; ++mt)
                LDSM_X4(a[mt][0], a[mt][1], a[mt][2], a[mt][3],
                        sb + SQ_O + aoffQ[mt] + kso);
            #pragma unroll
            for (int p = 0; p < 2; ++p)
                LDSM_X4(bk[p][0], bk[p][1], bk[p][2], bk[p][3],
                        sb + SK_O + boffK[p] + kso);
            #pragma unroll
            for (int i = 0; i < 4; ++i)
                #pragma unroll
                for (int j = 0; j < 4; ++j) {
                    const int p = j >> 1, w = (j & 1) * 2;
                    MMA16816H(acc[i][j], a[i], bk[p][w], bk[p][w + 1]);
                }
        }
        #pragma unroll
        for (int i = 0; i < 4; ++i) {
            const int r1 = m_off + 16 * i + (lane >> 2);
            const int r2 = r1 + 8;
            float rs1 = 0.f, rs2 = 0.f;
            #pragma unroll
            for (int j = 0; j < 4; ++j) {
                const int c = n_off + 8 * j + ((lane & 3) << 1);
                float v0 = (c <= r1) ? acc[i][j][0] : 0.f;
                float v1 = (c + 1 <= r1) ? acc[i][j][1] : 0.f;
                float v2 = (c <= r2) ? acc[i][j][2] : 0.f;
                float v3 = (c + 1 <= r2) ? acc[i][j][3] : 0.f;
                rs1 += v0 + v1; rs2 += v2 + v3;
                *(__half2*)(smc + SA_O + (r1 * 136 + c) * 2) = __floats2half2_rn(v0, v1);
                *(__half2*)(smc + SA_O + (r2 * 136 + c) * 2) = __floats2half2_rn(v2, v3);
            }
            rs1 += __shfl_xor_sync(0xFFFFFFFFu, rs1, 1);
            rs1 += __shfl_xor_sync(0xFFFFFFFFu, rs1, 2);
            rs2 += __shfl_xor_sync(0xFFFFFFFFu, rs2, 1);
            rs2 += __shfl_xor_sync(0xFFFFFFFFu, rs2, 2);
            if ((lane & 3) == 0) {
                atomicAdd(&sDen[r1], rs1);
                atomicAdd(&sDen[r2], rs2);
            }
        }
    }
    __syncthreads();

    // ---- Pass B: num = A.V + Q.S ----
    {
        float acc2[4][2][4] = {};
        #pragma unroll
        for (int ks = 0; ks < CHK; ks += 16) {
            const uint32_t kso = (uint32_t)(ks * 2);
            uint32_t a[4][4], bv[4];
            #pragma unroll
            for (int mt = 0; mt < 4; ++mt)
                LDSM_X4(a[mt][0], a[mt][1], a[mt][2], a[mt][3],
                        sb + SA_O + aoffA[mt] + kso);
            LDSM_X4(bv[0], bv[1], bv[2], bv[3], sb + SVT_O + boffV + kso);
            #pragma unroll
            for (int i = 0; i < 4; ++i)
                #pragma unroll
                for (int j2 = 0; j2 < 2; ++j2)
                    MMA16816H(acc2[i][j2], a[i], bv[2 * j2], bv[2 * j2 + 1]);
        }
        #pragma unroll
        for (int ks = 0; ks < DHEAD; ks += 16) {
            const uint32_t kso = (uint32_t)(ks * 2);
            uint32_t a[4][4], bs[4];
            #pragma unroll
            for (int mt = 0; mt < 4; ++mt)
                LDSM_X4(a[mt][0], a[mt][1], a[mt][2], a[mt][3],
                        sb + SQ_O + aoffQ[mt] + kso);
            LDSM_X4(bs[0], bs[1], bs[2], bs[3], sb + SST_O + boffS + kso);
            #pragma unroll
            for (int i = 0; i < 4; ++i)
                #pragma unroll
                for (int j2 = 0; j2 < 2; ++j2)
                    MMA16816H(acc2[i][j2], a[i], bs[2 * j2], bs[2 * j2 + 1]);
        }
        #pragma unroll
        for (int i = 0; i < 4; ++i) {
            const int r1 = m_off + 16 * i + (lane >> 2);
            const int r2 = r1 + 8;
            const float inv1 = 1.0f / sDen[r1];
            const float inv2 = 1.0f / sDen[r2];
            #pragma unroll
            for (int j2 = 0; j2 < 2; ++j2) {
                const int c = n_off2 + 8 * j2 + ((lane & 3) << 1);
                *(__half2*)(y16 + rowbase + (size_t)r1 * EDIM + c) =
                    __floats2half2_rn(acc2[i][j2][0] * inv1, acc2[i][j2][1] * inv1);
                *(__half2*)(y16 + rowbase + (size_t)r2 * EDIM + c) =
                    __floats2half2_rn(acc2[i][j2][2] * inv2, acc2[i][j2][3] * inv2);
            }
        }
    }
}

// ---------------------------------------------------------------------------
extern "C" void kernel_launch(void* const* d_in, const int* in_sizes, int n_in,
                              void* d_out, int out_size)
{
    const float* x  = (const float*)d_in[0];
    const float* Wq = (const float*)d_in[1];
    const float* Wk = (const float*)d_in[2];
    const float* Wv = (const float*)d_in[3];
    const float* Wp = (const float*)d_in[4];
    const float* bp = (const float*)d_in[5];
    float* out = (float*)d_out;

    float *q, *k, *v, *kv, *S, *zk, *Z;
    __half *xh, *qh, *kh, *vh, *yh, *wh;
    cudaGetSymbolAddress((void**)&q,  g_q);
    cudaGetSymbolAddress((void**)&k,  g_k);
    cudaGetSymbolAddress((void**)&v,  g_v);
    cudaGetSymbolAddress((void**)&kv, g_kv);
    cudaGetSymbolAddress((void**)&S,  g_S);
    cudaGetSymbolAddress((void**)&zk, g_zk);
    cudaGetSymbolAddress((void**)&Z,  g_Z);
    cudaGetSymbolAddress((void**)&xh, g_xh);
    cudaGetSymbolAddress((void**)&qh, g_qh);
    cudaGetSymbolAddress((void**)&kh, g_kh);
    cudaGetSymbolAddress((void**)&vh, g_vh);
    cudaGetSymbolAddress((void**)&yh, g_yh);
    cudaGetSymbolAddress((void**)&wh, g_wh);

    cudaFuncSetAttribute(tc_gemm<true>,  cudaFuncAttributeMaxDynamicSharedMemorySize, GEMM_SMEM);
    cudaFuncSetAttribute(tc_gemm<false>, cudaFuncAttributeMaxDynamicSharedMemorySize, GEMM_SMEM);
    cudaFuncSetAttribute(chunk_attn_mma,
                         cudaFuncAttributeMaxDynamicSharedMemorySize, ATTN_SMEM);

    const size_t WSZ = (size_t)EDIM * EDIM;
    const int W4 = (int)(WSZ / 4);

    cast_f16_kernel<<<(MROWS * EDIM / 4 + 255) / 256, 256>>>(x, xh, MROWS * EDIM / 4);
    cast_w_kernel<<<dim3((W4 + 255) / 256, 4), 256>>>(Wq, Wk, Wv, Wp, wh, W4);

    dim3 gq(EDIM / 128, MROWS / 128, 3);   // batched q/k/v
    tc_gemm<true><<<gq, 256, GEMM_SMEM>>>(xh, wh, nullptr, q, k, v, qh, kh, vh);

    chunk_kv_mma<<<dim3(NCH, NHEAD, BSZ), 256>>>(kh, vh, kv, zk);
    prefix_scan_kernel<<<(BSZ * NHEAD * DHEAD * DHEAD + 255) / 256, 256>>>(kv, S, DHEAD * DHEAD);
    prefix_scan_kernel<<<(BSZ * NHEAD * DHEAD + 255) / 256, 256>>>(zk, Z, DHEAD);

    chunk_attn_mma<<<dim3(NCH, NHEAD, BSZ), 256, ATTN_SMEM>>>(qh, kh, vh, S, Z, yh);

    dim3 gp(EDIM / 128, MROWS / 128);      // final projection (1-pass fp16)
    tc_gemm<false><<<gp, 256, GEMM_SMEM>>>(yh, wh + 3 * WSZ, bp, out,
                                           nullptr, nullptr, nullptr, nullptr, nullptr);
}

// round 9
// speedup vs baseline: 4.5238x; 1.1074x over previous
#include <cuda_runtime.h>
#include <cuda_fp16.h>
#include <math.h>
#include <stdint.h>

// Problem constants
#define BSZ   4
#define TLEN  2048
#define EDIM  1024
#define NHEAD 16
#define DHEAD 64
#define CHK   128
#define NCH   16            // TLEN / CHK
#define MROWS (BSZ*TLEN)    // 8192

// Scratch (device globals; allocation-free rule)
__device__ float g_kv[(size_t)BSZ*NHEAD*NCH*DHEAD*DHEAD];
__device__ float g_S [(size_t)BSZ*NHEAD*NCH*DHEAD*DHEAD];
__device__ float g_zk[(size_t)BSZ*NHEAD*NCH*DHEAD];
__device__ float g_Z [(size_t)BSZ*NHEAD*NCH*DHEAD];
// fp16 buffers
__device__ __half g_xh[(size_t)MROWS*EDIM];
__device__ __half g_qh[(size_t)MROWS*EDIM];
__device__ __half g_kh[(size_t)MROWS*EDIM];
__device__ __half g_vh[(size_t)MROWS*EDIM];
__device__ __half g_yh[(size_t)MROWS*EDIM];
__device__ __half g_wh[(size_t)4*EDIM*EDIM];      // Wq,Wk,Wv,Wp fp16

// ---------------------------------------------------------------------------
// helpers
// ---------------------------------------------------------------------------
__device__ __forceinline__ uint32_t smem_u32(const void* p) {
    uint32_t a;
    asm("{ .reg .u64 t; cvta.to.shared.u64 t, %1; cvt.u32.u64 %0, t; }"
        : "=r"(a) : "l"(p));
    return a;
}
#define CP_ASYNC16(dst, src) \
    asm volatile("cp.async.cg.shared.global [%0], [%1], 16;" \
                 :: "r"(dst), "l"(src) : "memory")
#define CP_COMMIT() asm volatile("cp.async.commit_group;" ::: "memory")
#define CP_WAIT(N)  asm volatile("cp.async.wait_group %0;" :: "n"(N) : "memory")
#define LDSM_X4(r0, r1, r2, r3, a) \
    asm volatile("ldmatrix.sync.aligned.m8n8.x4.shared.b16 {%0,%1,%2,%3}, [%4];" \
                 : "=r"(r0), "=r"(r1), "=r"(r2), "=r"(r3) : "r"(a))
#define LDSM_X4_T(r0, r1, r2, r3, a) \
    asm volatile("ldmatrix.sync.aligned.m8n8.x4.trans.shared.b16 {%0,%1,%2,%3}, [%4];" \
                 : "=r"(r0), "=r"(r1), "=r"(r2), "=r"(r3) : "r"(a))
#define MMA16816H(d, a, b0v, b1v) \
    asm volatile("mma.sync.aligned.m16n8k16.row.col.f32.f16.f16.f32 " \
                 "{%0,%1,%2,%3}, {%4,%5,%6,%7}, {%8,%9}, {%0,%1,%2,%3};" \
                 : "+f"((d)[0]), "+f"((d)[1]), "+f"((d)[2]), "+f"((d)[3]) \
                 : "r"((a)[0]), "r"((a)[1]), "r"((a)[2]), "r"((a)[3]), \
                   "r"(b0v), "r"(b1v))

// ---------------------------------------------------------------------------
// fp32 -> fp16 cast (x activations)
// ---------------------------------------------------------------------------
__global__ void cast_f16_kernel(const float* __restrict__ in,
                                __half* __restrict__ hh, int n4)
{
    int i = blockIdx.x * blockDim.x + threadIdx.x;
    if (i >= n4) return;
    float4 v = ((const float4*)in)[i];
    ((__half2*)hh)[2 * i + 0] = __floats2half2_rn(v.x, v.y);
    ((__half2*)hh)[2 * i + 1] = __floats2half2_rn(v.z, v.w);
}

// batched: cast all 4 weight matrices (blockIdx.y selects)
__global__ void cast_w_kernel(const float* __restrict__ W0,
                              const float* __restrict__ W1,
                              const float* __restrict__ W2,
                              const float* __restrict__ W3,
                              __half* __restrict__ dst, int n4)
{
    int i = blockIdx.x * blockDim.x + threadIdx.x;
    if (i >= n4) return;
    const float* src = (blockIdx.y == 0) ? W0 : (blockIdx.y == 1) ? W1
                     : (blockIdx.y == 2) ? W2 : W3;
    __half* out = dst + (size_t)blockIdx.y * EDIM * EDIM;
    float4 v = ((const float4*)src)[i];
    ((__half2*)out)[2 * i + 0] = __floats2half2_rn(v.x, v.y);
    ((__half2*)out)[2 * i + 1] = __floats2half2_rn(v.z, v.w);
}

// ---------------------------------------------------------------------------
// mma.sync fp16 GEMM (NT): C[m,n] = sum_k A[m,k]*B[n,k].
// BM=BN=128, BK=32, 8 warps (2x4), warp tile 64x32, cp.async double-buffer.
// QKV=true: batched blockIdx.z (0=q,1=k phi; 2=v), writes fp16 ONLY.
// QKV=false: single GEMM, +bias, fp32 out.
// ---------------------------------------------------------------------------
#define BK      32
#define LDT     40                      // BK + 8 pad (fp16 elems)
#define TILEB   (128 * LDT * 2)         // 10240 B per tile
#define NT      (EDIM / BK)             // 32 chunks
#define GEMM_SMEM (2 * 2 * TILEB)       // 40960 B

template <bool QKV>
__global__ void __launch_bounds__(256, 1)
tc_gemm(const __half* __restrict__ Ah, const __half* __restrict__ Wbase,
        const float* __restrict__ bias, float* __restrict__ C,
        __half* __restrict__ H0, __half* __restrict__ H1, __half* __restrict__ H2)
{
    extern __shared__ char smc[];
    const uint32_t sb = smem_u32(smc);
    const int tid = threadIdx.x;
    const int wid = tid >> 5, lane = tid & 31;
    const int m0g = blockIdx.y * 128;
    const int n0g = blockIdx.x * 128;
    const int m_off = (wid & 1) * 64;
    const int n_off = (wid >> 1) * 32;
    const int z = QKV ? blockIdx.z : 0;
    const __half* Bh = Wbase + (size_t)z * EDIM * EDIM;
    __half* C16 = QKV ? ((z == 0) ? H0 : (z == 1) ? H1 : H2) : nullptr;
    const bool phi = QKV && (z < 2);

    uint32_t aoff[4], boff[2];
    #pragma unroll
    for (int mt = 0; mt < 4; ++mt)
        aoff[mt] = (uint32_t)(((m_off + 16 * mt + (lane & 15)) * LDT
                               + (lane >> 4) * 8) * 2);
    #pragma unroll
    for (int p = 0; p < 2; ++p)
        boff[p] = (uint32_t)(((n_off + 16 * p + ((lane >> 4) << 3) + (lane & 7)) * LDT
                              + ((lane >> 3) & 1) * 8) * 2);

    auto stage_tile = [&](const __half* __restrict__ src, int row0,
                          int kc, uint32_t dstbase) {
        #pragma unroll
        for (int j = 0; j < 2; ++j) {
            int u = tid + j * 256;
            int row = u >> 2, seg = u & 3;
            uint32_t d = dstbase + (uint32_t)((row * LDT + seg * 8) * 2);
            const __half* g = src + (size_t)(row0 + row) * EDIM + kc + seg * 8;
            CP_ASYNC16(d, g);
        }
    };
    auto stage_chunk = [&](int t, int buf) {
        int kc = t * BK;
        uint32_t base = sb + buf * 2 * TILEB;
        stage_tile(Ah, m0g, kc, base);
        stage_tile(Bh, n0g, kc, base + TILEB);
        CP_COMMIT();
    };

    float acc[4][4][4] = {};

    stage_chunk(0, 0);
    for (int t = 0; t < NT; ++t) {
        const int cur = t & 1;
        if (t + 1 < NT) {
            stage_chunk(t + 1, 1 - cur);
            CP_WAIT(1);
        } else {
            CP_WAIT(0);
        }
        __syncthreads();

        const uint32_t base = sb + cur * 2 * TILEB;
        #pragma unroll
        for (int ks = 0; ks < BK; ks += 16) {
            const uint32_t kso = (uint32_t)(ks * 2);
            uint32_t ah[4][4], bh[2][4];
            #pragma unroll
            for (int mt = 0; mt < 4; ++mt)
                LDSM_X4(ah[mt][0], ah[mt][1], ah[mt][2], ah[mt][3],
                        base + aoff[mt] + kso);
            #pragma unroll
            for (int p = 0; p < 2; ++p)
                LDSM_X4(bh[p][0], bh[p][1], bh[p][2], bh[p][3],
                        base + TILEB + boff[p] + kso);
            #pragma unroll
            for (int i = 0; i < 4; ++i)
                #pragma unroll
                for (int j = 0; j < 4; ++j) {
                    const int p = j >> 1, w = (j & 1) * 2;
                    MMA16816H(acc[i][j], ah[i], bh[p][w], bh[p][w + 1]);
                }
        }
        __syncthreads();
    }

    #pragma unroll
    for (int i = 0; i < 4; ++i) {
        const int r = m0g + m_off + 16 * i + (lane >> 2);
        #pragma unroll
        for (int j = 0; j < 4; ++j) {
            const int c = n0g + n_off + 8 * j + ((lane & 3) << 1);
            float v0 = acc[i][j][0], v1 = acc[i][j][1];
            float v2 = acc[i][j][2], v3 = acc[i][j][3];
            if (QKV) {
                if (phi) {
                    v0 = (v0 > 0.f) ? (v0 + 1.f) : __expf(v0);
                    v1 = (v1 > 0.f) ? (v1 + 1.f) : __expf(v1);
                    v2 = (v2 > 0.f) ? (v2 + 1.f) : __expf(v2);
                    v3 = (v3 > 0.f) ? (v3 + 1.f) : __expf(v3);
                }
                *(__half2*)(C16 + (size_t)r * EDIM + c) = __floats2half2_rn(v0, v1);
                *(__half2*)(C16 + (size_t)(r + 8) * EDIM + c) = __floats2half2_rn(v2, v3);
            } else {
                float b0 = bias[c], b1 = bias[c + 1];
                *(float2*)(C + (size_t)r * EDIM + c) = make_float2(v0 + b0, v1 + b1);
                *(float2*)(C + (size_t)(r + 8) * EDIM + c) = make_float2(v2 + b0, v3 + b1);
            }
        }
    }
}

// ---------------------------------------------------------------------------
// Per-chunk kv state via fp16 mma with ldmatrix.trans:
// kv[d,e] = sum_c k[c,d]*v[c,e] (64x64, k=128), zk[d] = sum_c k[c,d].
// K,V staged ROW-MAJOR [128][72] (vectorized); trans loads make K^T/V^T frags.
// ---------------------------------------------------------------------------
__global__ void __launch_bounds__(256)
chunk_kv_mma(const __half* __restrict__ k16, const __half* __restrict__ v16,
             float* __restrict__ kv, float* __restrict__ zk)
{
    __shared__ __align__(16) __half sKr[128 * 72];
    __shared__ __align__(16) __half sVr[128 * 72];
    const uint32_t sbK = smem_u32(sKr);
    const uint32_t sbV = smem_u32(sVr);

    const int n = blockIdx.x, h = blockIdx.y, b = blockIdx.z;
    const int tid = threadIdx.x;
    const int wid = tid >> 5, lane = tid & 31;
    const int m_off = (wid & 1) * 32;       // d
    const int n_off = (wid >> 1) * 16;      // e
    const size_t rowbase = ((size_t)(b * TLEN + n * CHK)) * EDIM + h * DHEAD;

    // vectorized row-major staging: 128 rows x 64 halves (8 x uint4 per row)
    #pragma unroll
    for (int it = 0; it < 4; ++it) {
        int u = tid + it * 256;             // 0..1023
        int row = u >> 3, seg = u & 7;
        *(uint4*)&sKr[row * 72 + seg * 8] =
            *(const uint4*)(k16 + rowbase + (size_t)row * EDIM + seg * 8);
        *(uint4*)&sVr[row * 72 + seg * 8] =
            *(const uint4*)(v16 + rowbase + (size_t)row * EDIM + seg * 8);
    }
    __syncthreads();

    if (tid < DHEAD) {
        float z = 0.f;
        #pragma unroll 8
        for (int c = 0; c < CHK; ++c) z += __half2float(sKr[c * 72 + tid]);
        zk[((size_t)((b * NHEAD + h) * NCH) + n) * DHEAD + tid] = z;
    }

    // trans-fragment offsets (bytes), add ks*144 per k-step
    // A (K^T): row c = bit4*8 + (lane&7), col d = m_off + 16*mt + bit3*8
    uint32_t aoffT[2];
    #pragma unroll
    for (int mt = 0; mt < 2; ++mt)
        aoffT[mt] = (uint32_t)(((((lane >> 4) & 1) * 8 + (lane & 7)) * 72
                                + m_off + 16 * mt + ((lane >> 3) & 1) * 8) * 2);
    // B (V^T): row s = bit3*8 + (lane&7), col e = n_off + bit4*8
    const uint32_t boffT = (uint32_t)(((((lane >> 3) & 1) * 8 + (lane & 7)) * 72
                                      + n_off + ((lane >> 4) & 1) * 8) * 2);

    float acc[2][2][4] = {};
    #pragma unroll
    for (int ks = 0; ks < CHK; ks += 16) {
        const uint32_t kb = (uint32_t)(ks * 144);
        uint32_t a[2][4], bv[4];
        #pragma unroll
        for (int mt = 0; mt < 2; ++mt)
            LDSM_X4_T(a[mt][0], a[mt][1], a[mt][2], a[mt][3], sbK + aoffT[mt] + kb);
        LDSM_X4_T(bv[0], bv[1], bv[2], bv[3], sbV + boffT + kb);
        #pragma unroll
        for (int i = 0; i < 2; ++i)
            #pragma unroll
            for (int j2 = 0; j2 < 2; ++j2)
                MMA16816H(acc[i][j2], a[i], bv[2 * j2], bv[2 * j2 + 1]);
    }

    const size_t obase = ((size_t)((b * NHEAD + h) * NCH) + n) * DHEAD * DHEAD;
    #pragma unroll
    for (int i = 0; i < 2; ++i) {
        const int r1 = m_off + 16 * i + (lane >> 2);
        const int r2 = r1 + 8;
        #pragma unroll
        for (int j2 = 0; j2 < 2; ++j2) {
            const int c = n_off + 8 * j2 + ((lane & 3) << 1);
            *(float2*)(kv + obase + (size_t)r1 * DHEAD + c) =
                make_float2(acc[i][j2][0], acc[i][j2][1]);
            *(float2*)(kv + obase + (size_t)r2 * DHEAD + c) =
                make_float2(acc[i][j2][2], acc[i][j2][3]);
        }
    }
}

// ---------------------------------------------------------------------------
// Exclusive prefix over the N=16 chunk axis
// ---------------------------------------------------------------------------
__global__ void prefix_scan_kernel(const float* __restrict__ src,
                                   float* __restrict__ dst, int per)
{
    int i = blockIdx.x * blockDim.x + threadIdx.x;
    int total = BSZ * NHEAD * per;
    if (i >= total) return;
    int bh = i / per, r = i - bh * per;
    size_t base = (size_t)bh * NCH * per + r;
    float acc = 0.f;
    #pragma unroll
    for (int nn = 0; nn < NCH; ++nn) {
        dst[base + (size_t)nn * per] = acc;
        acc += src[base + (size_t)nn * per];
    }
}

// ---------------------------------------------------------------------------
// Tensor-core per-chunk attention. V and S staged ROW-MAJOR (vectorized);
// pass-B B-operands loaded with ldmatrix.trans.
// ---------------------------------------------------------------------------
#define SQ_O    0                       // [128][72] fp16
#define SK_O    18432                   // [128][72] fp16
#define SV_O    36864                   // [128][72] fp16 (row-major)
#define SS_O    55296                   // [64][72]  fp16 (row-major, d rows)
#define SA_O    64512                   // [128][136] fp16 masked A
#define SZ_O    99328                   // [64] fp32
#define SDEN_O  99584                   // [128] fp32
#define ATTN_SMEM 100096

__global__ void __launch_bounds__(256)
chunk_attn_mma(const __half* __restrict__ q16, const __half* __restrict__ k16,
               const __half* __restrict__ v16, const float* __restrict__ S,
               const float* __restrict__ Z, __half* __restrict__ y16)
{
    extern __shared__ char smc[];
    const uint32_t sb = smem_u32(smc);
    float* sZ   = (float*)(smc + SZ_O);
    float* sDen = (float*)(smc + SDEN_O);

    const int n = blockIdx.x, h = blockIdx.y, b = blockIdx.z;
    const int tid = threadIdx.x;
    const int wid = tid >> 5, lane = tid & 31;
    const int m_off = (wid & 1) * 64;
    const int n_off = (wid >> 1) * 32;      // pass A (N=128)
    const int n_off2 = (wid >> 1) * 16;     // pass B (N=64)
    const size_t rowbase = ((size_t)(b * TLEN + n * CHK)) * EDIM + h * DHEAD;
    const size_t sbase = ((size_t)((b * NHEAD + h) * NCH) + n) * DHEAD * DHEAD;
    const size_t zbase = ((size_t)((b * NHEAD + h) * NCH) + n) * DHEAD;

    // stage Q, K, V row-major [128][72], vectorized
    #pragma unroll
    for (int it = 0; it < 4; ++it) {
        int u = tid + it * 256;             // 0..1023
        int row = u >> 3, seg = u & 7;
        uint32_t so = (uint32_t)((row * 72 + seg * 8) * 2);
        *(uint4*)(smc + SQ_O + so) =
            *(const uint4*)(q16 + rowbase + (size_t)row * EDIM + seg * 8);
        *(uint4*)(smc + SK_O + so) =
            *(const uint4*)(k16 + rowbase + (size_t)row * EDIM + seg * 8);
        *(uint4*)(smc + SV_O + so) =
            *(const uint4*)(v16 + rowbase + (size_t)row * EDIM + seg * 8);
    }
    // stage S fp32 -> fp16 row-major [64][72] (d rows, e cols), vectorized
    #pragma unroll
    for (int it = 0; it < 4; ++it) {
        int u = tid + it * 256;             // 0..1023 float4s
        int row = u >> 4, col4 = (u & 15) * 4;
        float4 s4 = *(const float4*)(S + sbase + (size_t)row * DHEAD + col4);
        __half2* dst = (__half2*)(smc + SS_O + (row * 72 + col4) * 2);
        dst[0] = __floats2half2_rn(s4.x, s4.y);
        dst[1] = __floats2half2_rn(s4.z, s4.w);
    }
    if (tid < DHEAD) sZ[tid] = Z[zbase + tid];
    __syncthreads();

    // den init: eps + phiq . Z
    if (tid < CHK) {
        float s2 = 1e-6f;
        const __half2* qr = (const __half2*)(smc + SQ_O + tid * 144);
        #pragma unroll
        for (int d2 = 0; d2 < 32; ++d2) {
            float2 qq = __half22float2(qr[d2]);
            s2 += qq.x * sZ[2 * d2] + qq.y * sZ[2 * d2 + 1];
        }
        sDen[tid] = s2;
    }
    __syncthreads();

    // fragment offsets
    uint32_t aoffQ[4], aoffA[4], boffK[2];
    #pragma unroll
    for (int mt = 0; mt < 4; ++mt) {
        int rr = m_off + 16 * mt + (lane & 15);
        aoffQ[mt] = (uint32_t)((rr * 72 + (lane >> 4) * 8) * 2);
        aoffA[mt] = (uint32_t)((rr * 136 + (lane >> 4) * 8) * 2);
    }
    #pragma unroll
    for (int p = 0; p < 2; ++p)
        boffK[p] = (uint32_t)(((n_off + 16 * p + ((lane >> 4) << 3) + (lane & 7)) * 72
                               + ((lane >> 3) & 1) * 8) * 2);
    // trans B offsets: row = bit3*8 + (lane&7), col = n_off2 + bit4*8
    const uint32_t boffT = (uint32_t)(((((lane >> 3) & 1) * 8 + (lane & 7)) * 72
                                      + n_off2 + ((lane >> 4) & 1) * 8) * 2);

    // ---- Pass A: A = Q K^T (128x128, k=64) ----
    {
        float acc[4][4][4] = {};
        #pragma unroll
        for (int ks = 0; ks < DHEAD; ks += 16) {
            const uint32_t kso = (uint32_t)(ks * 2);
            uint32_t a[4][4], bk[2][4];
            #pragma unroll
            for (int mt = 0; mt < 4; ++mt)
                LDSM_X4(a[mt][0], a[mt][1], a[mt][2], a[mt][3],
                        sb + SQ_O + aoffQ[mt] + kso);
            #pragma unroll
            for (int p = 0; p < 2; ++p)
                LDSM_X4(bk[p][0], bk[p][1], bk[p][2], bk[p][3],
                        sb + SK_O + boffK[p] + kso);
            #pragma unroll
            for (int i = 0; i < 4; ++i)
                #pragma unroll
                for (int j = 0; j < 4; ++j) {
                    const int p = j >> 1, w = (j & 1) * 2;
                    MMA16816H(acc[i][j], a[i], bk[p][w], bk[p][w + 1]);
                }
        }
        #pragma unroll
        for (int i = 0; i < 4; ++i) {
            const int r1 = m_off + 16 * i + (lane >> 2);
            const int r2 = r1 + 8;
            float rs1 = 0.f, rs2 = 0.f;
            #pragma unroll
            for (int j = 0; j < 4; ++j) {
                const int c = n_off + 8 * j + ((lane & 3) << 1);
                float v0 = (c <= r1) ? acc[i][j][0] : 0.f;
                float v1 = (c + 1 <= r1) ? acc[i][j][1] : 0.f;
                float v2 = (c <= r2) ? acc[i][j][2] : 0.f;
                float v3 = (c + 1 <= r2) ? acc[i][j][3] : 0.f;
                rs1 += v0 + v1; rs2 += v2 + v3;
                *(__half2*)(smc + SA_O + (r1 * 136 + c) * 2) = __floats2half2_rn(v0, v1);
                *(__half2*)(smc + SA_O + (r2 * 136 + c) * 2) = __floats2half2_rn(v2, v3);
            }
            rs1 += __shfl_xor_sync(0xFFFFFFFFu, rs1, 1);
            rs1 += __shfl_xor_sync(0xFFFFFFFFu, rs1, 2);
            rs2 += __shfl_xor_sync(0xFFFFFFFFu, rs2, 1);
            rs2 += __shfl_xor_sync(0xFFFFFFFFu, rs2, 2);
            if ((lane & 3) == 0) {
                atomicAdd(&sDen[r1], rs1);
                atomicAdd(&sDen[r2], rs2);
            }
        }
    }
    __syncthreads();

    // ---- Pass B: num = A.V + Q.S (128x64), trans B-operands ----
    {
        float acc2[4][2][4] = {};
        #pragma unroll
        for (int ks = 0; ks < CHK; ks += 16) {        // A.V, k = s = 128
            const uint32_t kso = (uint32_t)(ks * 2);
            const uint32_t kb = (uint32_t)(ks * 144);
            uint32_t a[4][4], bv[4];
            #pragma unroll
            for (int mt = 0; mt < 4; ++mt)
                LDSM_X4(a[mt][0], a[mt][1], a[mt][2], a[mt][3],
                        sb + SA_O + aoffA[mt] + kso);
            LDSM_X4_T(bv[0], bv[1], bv[2], bv[3], sb + SV_O + boffT + kb);
            #pragma unroll
            for (int i = 0; i < 4; ++i)
                #pragma unroll
                for (int j2 = 0; j2 < 2; ++j2)
                    MMA16816H(acc2[i][j2], a[i], bv[2 * j2], bv[2 * j2 + 1]);
        }
        #pragma unroll
        for (int ks = 0; ks < DHEAD; ks += 16) {      // Q.S, k = d = 64
            const uint32_t kso = (uint32_t)(ks * 2);
            const uint32_t kb = (uint32_t)(ks * 144);
            uint32_t a[4][4], bs[4];
            #pragma unroll
            for (int mt = 0; mt < 4; ++mt)
                LDSM_X4(a[mt][0], a[mt][1], a[mt][2], a[mt][3],
                        sb + SQ_O + aoffQ[mt] + kso);
            LDSM_X4_T(bs[0], bs[1], bs[2], bs[3], sb + SS_O + boffT + kb);
            #pragma unroll
            for (int i = 0; i < 4; ++i)
                #pragma unroll
                for (int j2 = 0; j2 < 2; ++j2)
                    MMA16816H(acc2[i][j2], a[i], bs[2 * j2], bs[2 * j2 + 1]);
        }
        #pragma unroll
        for (int i = 0; i < 4; ++i) {
            const int r1 = m_off + 16 * i + (lane >> 2);
            const int r2 = r1 + 8;
            const float inv1 = 1.0f / sDen[r1];
            const float inv2 = 1.0f / sDen[r2];
            #pragma unroll
            for (int j2 = 0; j2 < 2; ++j2) {
                const int c = n_off2 + 8 * j2 + ((lane & 3) << 1);
                *(__half2*)(y16 + rowbase + (size_t)r1 * EDIM + c) =
                    __floats2half2_rn(acc2[i][j2][0] * inv1, acc2[i][j2][1] * inv1);
                *(__half2*)(y16 + rowbase + (size_t)r2 * EDIM + c) =
                    __floats2half2_rn(acc2[i][j2][2] * inv2, acc2[i][j2][3] * inv2);
            }
        }
    }
}

// ---------------------------------------------------------------------------
extern "C" void kernel_launch(void* const* d_in, const int* in_sizes, int n_in,
                              void* d_out, int out_size)
{
    const float* x  = (const float*)d_in[0];
    const float* Wq = (const float*)d_in[1];
    const float* Wk = (const float*)d_in[2];
    const float* Wv = (const float*)d_in[3];
    const float* Wp = (const float*)d_in[4];
    const float* bp = (const float*)d_in[5];
    float* out = (float*)d_out;

    float *kv, *S, *zk, *Z;
    __half *xh, *qh, *kh, *vh, *yh, *wh;
    cudaGetSymbolAddress((void**)&kv, g_kv);
    cudaGetSymbolAddress((void**)&S,  g_S);
    cudaGetSymbolAddress((void**)&zk, g_zk);
    cudaGetSymbolAddress((void**)&Z,  g_Z);
    cudaGetSymbolAddress((void**)&xh, g_xh);
    cudaGetSymbolAddress((void**)&qh, g_qh);
    cudaGetSymbolAddress((void**)&kh, g_kh);
    cudaGetSymbolAddress((void**)&vh, g_vh);
    cudaGetSymbolAddress((void**)&yh, g_yh);
    cudaGetSymbolAddress((void**)&wh, g_wh);

    cudaFuncSetAttribute(tc_gemm<true>,  cudaFuncAttributeMaxDynamicSharedMemorySize, GEMM_SMEM);
    cudaFuncSetAttribute(tc_gemm<false>, cudaFuncAttributeMaxDynamicSharedMemorySize, GEMM_SMEM);
    cudaFuncSetAttribute(chunk_attn_mma,
                         cudaFuncAttributeMaxDynamicSharedMemorySize, ATTN_SMEM);

    const size_t WSZ = (size_t)EDIM * EDIM;
    const int W4 = (int)(WSZ / 4);

    cast_f16_kernel<<<(MROWS * EDIM / 4 + 255) / 256, 256>>>(x, xh, MROWS * EDIM / 4);
    cast_w_kernel<<<dim3((W4 + 255) / 256, 4), 256>>>(Wq, Wk, Wv, Wp, wh, W4);

    dim3 gq(EDIM / 128, MROWS / 128, 3);   // batched q/k/v, fp16-only outputs
    tc_gemm<true><<<gq, 256, GEMM_SMEM>>>(xh, wh, nullptr, nullptr, qh, kh, vh);

    chunk_kv_mma<<<dim3(NCH, NHEAD, BSZ), 256>>>(kh, vh, kv, zk);
    prefix_scan_kernel<<<(BSZ * NHEAD * DHEAD * DHEAD + 255) / 256, 256>>>(kv, S, DHEAD * DHEAD);
    prefix_scan_kernel<<<(BSZ * NHEAD * DHEAD + 255) / 256, 256>>>(zk, Z, DHEAD);

    chunk_attn_mma<<<dim3(NCH, NHEAD, BSZ), 256, ATTN_SMEM>>>(qh, kh, vh, S, Z, yh);

    dim3 gp(EDIM / 128, MROWS / 128);      // final projection (1-pass fp16)
    tc_gemm<false><<<gp, 256, GEMM_SMEM>>>(yh, wh + 3 * WSZ, bp, out,
                                           nullptr, nullptr, nullptr);
}

// round 10
// speedup vs baseline: 4.6357x; 1.0247x over previous
#include <cuda_runtime.h>
#include <cuda_fp16.h>
#include <math.h>
#include <stdint.h>

// Problem constants
#define BSZ   4
#define TLEN  2048
#define EDIM  1024
#define NHEAD 16
#define DHEAD 64
#define CHK   128
#define NCH   16            // TLEN / CHK
#define MROWS (BSZ*TLEN)    // 8192

// Scratch (device globals; allocation-free rule)
__device__ float g_kv[(size_t)BSZ*NHEAD*NCH*DHEAD*DHEAD];
__device__ float g_S [(size_t)BSZ*NHEAD*NCH*DHEAD*DHEAD];
__device__ float g_zk[(size_t)BSZ*NHEAD*NCH*DHEAD];
__device__ float g_Z [(size_t)BSZ*NHEAD*NCH*DHEAD];
// fp16 buffers
__device__ __half g_xh[(size_t)MROWS*EDIM];
__device__ __half g_qh[(size_t)MROWS*EDIM];
__device__ __half g_kh[(size_t)MROWS*EDIM];
__device__ __half g_vh[(size_t)MROWS*EDIM];
__device__ __half g_yh[(size_t)MROWS*EDIM];
__device__ __half g_wh[(size_t)4*EDIM*EDIM];      // Wq,Wk,Wv,Wp fp16

// ---------------------------------------------------------------------------
// helpers
// ---------------------------------------------------------------------------
__device__ __forceinline__ uint32_t smem_u32(const void* p) {
    uint32_t a;
    asm("{ .reg .u64 t; cvta.to.shared.u64 t, %1; cvt.u32.u64 %0, t; }"
        : "=r"(a) : "l"(p));
    return a;
}
#define CP_ASYNC16(dst, src) \
    asm volatile("cp.async.cg.shared.global [%0], [%1], 16;" \
                 :: "r"(dst), "l"(src) : "memory")
#define CP_COMMIT() asm volatile("cp.async.commit_group;" ::: "memory")
#define CP_WAIT(N)  asm volatile("cp.async.wait_group %0;" :: "n"(N) : "memory")
#define LDSM_X4(r0, r1, r2, r3, a) \
    asm volatile("ldmatrix.sync.aligned.m8n8.x4.shared.b16 {%0,%1,%2,%3}, [%4];" \
                 : "=r"(r0), "=r"(r1), "=r"(r2), "=r"(r3) : "r"(a))
#define LDSM_X4_T(r0, r1, r2, r3, a) \
    asm volatile("ldmatrix.sync.aligned.m8n8.x4.trans.shared.b16 {%0,%1,%2,%3}, [%4];" \
                 : "=r"(r0), "=r"(r1), "=r"(r2), "=r"(r3) : "r"(a))
#define MMA16816H(d, a, b0v, b1v) \
    asm volatile("mma.sync.aligned.m16n8k16.row.col.f32.f16.f16.f32 " \
                 "{%0,%1,%2,%3}, {%4,%5,%6,%7}, {%8,%9}, {%0,%1,%2,%3};" \
                 : "+f"((d)[0]), "+f"((d)[1]), "+f"((d)[2]), "+f"((d)[3]) \
                 : "r"((a)[0]), "r"((a)[1]), "r"((a)[2]), "r"((a)[3]), \
                   "r"(b0v), "r"(b1v))

// ---------------------------------------------------------------------------
// merged fp32 -> fp16 casts: x (2M float4) then 4 weights (256K float4 each)
// ---------------------------------------------------------------------------
#define N4X (MROWS * EDIM / 4)          // 2097152
#define N4W (EDIM * EDIM / 4)           // 262144

__global__ void cast_all_kernel(const float* __restrict__ x,
                                const float* __restrict__ W0,
                                const float* __restrict__ W1,
                                const float* __restrict__ W2,
                                const float* __restrict__ W3,
                                __half* __restrict__ xh,
                                __half* __restrict__ wh)
{
    int i = blockIdx.x * blockDim.x + threadIdx.x;
    const float* src;
    __half* dst;
    int off;
    if (i < N4X) {
        src = x; dst = xh; off = i;
    } else {
        int j = i - N4X;
        if (j >= 4 * N4W) return;
        int w = j / N4W;
        off = j - w * N4W;
        src = (w == 0) ? W0 : (w == 1) ? W1 : (w == 2) ? W2 : W3;
        dst = wh + (size_t)w * EDIM * EDIM;
    }
    float4 v = ((const float4*)src)[off];
    ((__half2*)dst)[2 * off + 0] = __floats2half2_rn(v.x, v.y);
    ((__half2*)dst)[2 * off + 1] = __floats2half2_rn(v.z, v.w);
}

// ---------------------------------------------------------------------------
// mma.sync fp16 GEMM (NT): C[m,n] = sum_k A[m,k]*B[n,k].
// BM=BN=128, BK=32, 8 warps (2x4), warp tile 64x32, cp.async double-buffer.
// QKV=true: batched blockIdx.z (0=q,1=k phi; 2=v), writes fp16 ONLY.
// QKV=false: single GEMM, +bias, fp32 out.
// ---------------------------------------------------------------------------
#define BK      32
#define LDT     40                      // BK + 8 pad (fp16 elems)
#define TILEB   (128 * LDT * 2)         // 10240 B per tile
#define NT      (EDIM / BK)             // 32 chunks
#define GEMM_SMEM (2 * 2 * TILEB)       // 40960 B

template <bool QKV>
__global__ void __launch_bounds__(256, 1)
tc_gemm(const __half* __restrict__ Ah, const __half* __restrict__ Wbase,
        const float* __restrict__ bias, float* __restrict__ C,
        __half* __restrict__ H0, __half* __restrict__ H1, __half* __restrict__ H2)
{
    extern __shared__ char smc[];
    const uint32_t sb = smem_u32(smc);
    const int tid = threadIdx.x;
    const int wid = tid >> 5, lane = tid & 31;
    const int m0g = blockIdx.y * 128;
    const int n0g = blockIdx.x * 128;
    const int m_off = (wid & 1) * 64;
    const int n_off = (wid >> 1) * 32;
    const int z = QKV ? blockIdx.z : 0;
    const __half* Bh = Wbase + (size_t)z * EDIM * EDIM;
    __half* C16 = QKV ? ((z == 0) ? H0 : (z == 1) ? H1 : H2) : nullptr;
    const bool phi = QKV && (z < 2);

    uint32_t aoff[4], boff[2];
    #pragma unroll
    for (int mt = 0; mt < 4; ++mt)
        aoff[mt] = (uint32_t)(((m_off + 16 * mt + (lane & 15)) * LDT
                               + (lane >> 4) * 8) * 2);
    #pragma unroll
    for (int p = 0; p < 2; ++p)
        boff[p] = (uint32_t)(((n_off + 16 * p + ((lane >> 4) << 3) + (lane & 7)) * LDT
                              + ((lane >> 3) & 1) * 8) * 2);

    auto stage_tile = [&](const __half* __restrict__ src, int row0,
                          int kc, uint32_t dstbase) {
        #pragma unroll
        for (int j = 0; j < 2; ++j) {
            int u = tid + j * 256;
            int row = u >> 2, seg = u & 3;
            uint32_t d = dstbase + (uint32_t)((row * LDT + seg * 8) * 2);
            const __half* g = src + (size_t)(row0 + row) * EDIM + kc + seg * 8;
            CP_ASYNC16(d, g);
        }
    };
    auto stage_chunk = [&](int t, int buf) {
        int kc = t * BK;
        uint32_t base = sb + buf * 2 * TILEB;
        stage_tile(Ah, m0g, kc, base);
        stage_tile(Bh, n0g, kc, base + TILEB);
        CP_COMMIT();
    };

    float acc[4][4][4] = {};

    stage_chunk(0, 0);
    for (int t = 0; t < NT; ++t) {
        const int cur = t & 1;
        if (t + 1 < NT) {
            stage_chunk(t + 1, 1 - cur);
            CP_WAIT(1);
        } else {
            CP_WAIT(0);
        }
        __syncthreads();

        const uint32_t base = sb + cur * 2 * TILEB;
        #pragma unroll
        for (int ks = 0; ks < BK; ks += 16) {
            const uint32_t kso = (uint32_t)(ks * 2);
            uint32_t ah[4][4], bh[2][4];
            #pragma unroll
            for (int mt = 0; mt < 4; ++mt)
                LDSM_X4(ah[mt][0], ah[mt][1], ah[mt][2], ah[mt][3],
                        base + aoff[mt] + kso);
            #pragma unroll
            for (int p = 0; p < 2; ++p)
                LDSM_X4(bh[p][0], bh[p][1], bh[p][2], bh[p][3],
                        base + TILEB + boff[p] + kso);
            #pragma unroll
            for (int i = 0; i < 4; ++i)
                #pragma unroll
                for (int j = 0; j < 4; ++j) {
                    const int p = j >> 1, w = (j & 1) * 2;
                    MMA16816H(acc[i][j], ah[i], bh[p][w], bh[p][w + 1]);
                }
        }
        __syncthreads();
    }

    #pragma unroll
    for (int i = 0; i < 4; ++i) {
        const int r = m0g + m_off + 16 * i + (lane >> 2);
        #pragma unroll
        for (int j = 0; j < 4; ++j) {
            const int c = n0g + n_off + 8 * j + ((lane & 3) << 1);
            float v0 = acc[i][j][0], v1 = acc[i][j][1];
            float v2 = acc[i][j][2], v3 = acc[i][j][3];
            if (QKV) {
                if (phi) {
                    v0 = (v0 > 0.f) ? (v0 + 1.f) : __expf(v0);
                    v1 = (v1 > 0.f) ? (v1 + 1.f) : __expf(v1);
                    v2 = (v2 > 0.f) ? (v2 + 1.f) : __expf(v2);
                    v3 = (v3 > 0.f) ? (v3 + 1.f) : __expf(v3);
                }
                *(__half2*)(C16 + (size_t)r * EDIM + c) = __floats2half2_rn(v0, v1);
                *(__half2*)(C16 + (size_t)(r + 8) * EDIM + c) = __floats2half2_rn(v2, v3);
            } else {
                float b0 = bias[c], b1 = bias[c + 1];
                *(float2*)(C + (size_t)r * EDIM + c) = make_float2(v0 + b0, v1 + b1);
                *(float2*)(C + (size_t)(r + 8) * EDIM + c) = make_float2(v2 + b0, v3 + b1);
            }
        }
    }
}

// ---------------------------------------------------------------------------
// Per-chunk kv state via fp16 mma with ldmatrix.trans, cp.async staging.
// ---------------------------------------------------------------------------
__global__ void __launch_bounds__(256)
chunk_kv_mma(const __half* __restrict__ k16, const __half* __restrict__ v16,
             float* __restrict__ kv, float* __restrict__ zk)
{
    __shared__ __align__(16) __half sKr[128 * 72];
    __shared__ __align__(16) __half sVr[128 * 72];
    const uint32_t sbK = smem_u32(sKr);
    const uint32_t sbV = smem_u32(sVr);

    const int n = blockIdx.x, h = blockIdx.y, b = blockIdx.z;
    const int tid = threadIdx.x;
    const int wid = tid >> 5, lane = tid & 31;
    const int m_off = (wid & 1) * 32;       // d
    const int n_off = (wid >> 1) * 16;      // e
    const size_t rowbase = ((size_t)(b * TLEN + n * CHK)) * EDIM + h * DHEAD;

    // cp.async row-major staging: 128 rows x 64 halves (8 x 16B per row)
    #pragma unroll
    for (int it = 0; it < 4; ++it) {
        int u = tid + it * 256;             // 0..1023
        int row = u >> 3, seg = u & 7;
        const __half* g = k16 + rowbase + (size_t)row * EDIM + seg * 8;
        const __half* g2 = v16 + rowbase + (size_t)row * EDIM + seg * 8;
        CP_ASYNC16(sbK + (uint32_t)((row * 72 + seg * 8) * 2), g);
        CP_ASYNC16(sbV + (uint32_t)((row * 72 + seg * 8) * 2), g2);
    }
    CP_COMMIT();
    CP_WAIT(0);
    __syncthreads();

    if (tid < DHEAD) {
        float z = 0.f;
        #pragma unroll 8
        for (int c = 0; c < CHK; ++c) z += __half2float(sKr[c * 72 + tid]);
        zk[((size_t)((b * NHEAD + h) * NCH) + n) * DHEAD + tid] = z;
    }

    // trans-fragment offsets (bytes), add ks*144 per k-step
    uint32_t aoffT[2];
    #pragma unroll
    for (int mt = 0; mt < 2; ++mt)
        aoffT[mt] = (uint32_t)(((((lane >> 4) & 1) * 8 + (lane & 7)) * 72
                                + m_off + 16 * mt + ((lane >> 3) & 1) * 8) * 2);
    const uint32_t boffT = (uint32_t)(((((lane >> 3) & 1) * 8 + (lane & 7)) * 72
                                      + n_off + ((lane >> 4) & 1) * 8) * 2);

    float acc[2][2][4] = {};
    #pragma unroll
    for (int ks = 0; ks < CHK; ks += 16) {
        const uint32_t kb = (uint32_t)(ks * 144);
        uint32_t a[2][4], bv[4];
        #pragma unroll
        for (int mt = 0; mt < 2; ++mt)
            LDSM_X4_T(a[mt][0], a[mt][1], a[mt][2], a[mt][3], sbK + aoffT[mt] + kb);
        LDSM_X4_T(bv[0], bv[1], bv[2], bv[3], sbV + boffT + kb);
        #pragma unroll
        for (int i = 0; i < 2; ++i)
            #pragma unroll
            for (int j2 = 0; j2 < 2; ++j2)
                MMA16816H(acc[i][j2], a[i], bv[2 * j2], bv[2 * j2 + 1]);
    }

    const size_t obase = ((size_t)((b * NHEAD + h) * NCH) + n) * DHEAD * DHEAD;
    #pragma unroll
    for (int i = 0; i < 2; ++i) {
        const int r1 = m_off + 16 * i + (lane >> 2);
        const int r2 = r1 + 8;
        #pragma unroll
        for (int j2 = 0; j2 < 2; ++j2) {
            const int c = n_off + 8 * j2 + ((lane & 3) << 1);
            *(float2*)(kv + obase + (size_t)r1 * DHEAD + c) =
                make_float2(acc[i][j2][0], acc[i][j2][1]);
            *(float2*)(kv + obase + (size_t)r2 * DHEAD + c) =
                make_float2(acc[i][j2][2], acc[i][j2][3]);
        }
    }
}

// ---------------------------------------------------------------------------
// Merged exclusive prefix scans over the N=16 chunk axis (kv->S and zk->Z)
// ---------------------------------------------------------------------------
#define SCAN1 (BSZ * NHEAD * DHEAD * DHEAD)   // 262144
#define SCAN2 (BSZ * NHEAD * DHEAD)           // 4096

__global__ void prefix_scan_all(const float* __restrict__ kv,
                                float* __restrict__ S,
                                const float* __restrict__ zk,
                                float* __restrict__ Z)
{
    int i = blockIdx.x * blockDim.x + threadIdx.x;
    const float* src;
    float* dst;
    size_t base;
    int per;
    if (i < SCAN1) {
        per = DHEAD * DHEAD;
        int bh = i / per, r = i - bh * per;
        base = (size_t)bh * NCH * per + r;
        src = kv; dst = S;
    } else {
        int j = i - SCAN1;
        if (j >= SCAN2) return;
        per = DHEAD;
        int bh = j / per, r = j - bh * per;
        base = (size_t)bh * NCH * per + r;
        src = zk; dst = Z;
    }
    float acc = 0.f;
    #pragma unroll
    for (int nn = 0; nn < NCH; ++nn) {
        dst[base + (size_t)nn * per] = acc;
        acc += src[base + (size_t)nn * per];
    }
}

// ---------------------------------------------------------------------------
// Tensor-core per-chunk attention; cp.async staging, causal triangle skip.
// ---------------------------------------------------------------------------
#define SQ_O    0                       // [128][72] fp16
#define SK_O    18432                   // [128][72] fp16
#define SV_O    36864                   // [128][72] fp16 (row-major)
#define SS_O    55296                   // [64][72]  fp16 (row-major, d rows)
#define SA_O    64512                   // [128][136] fp16 masked A
#define SZ_O    99328                   // [64] fp32
#define SDEN_O  99584                   // [128] fp32
#define ATTN_SMEM 100096

__global__ void __launch_bounds__(256)
chunk_attn_mma(const __half* __restrict__ q16, const __half* __restrict__ k16,
               const __half* __restrict__ v16, const float* __restrict__ S,
               const float* __restrict__ Z, __half* __restrict__ y16)
{
    extern __shared__ char smc[];
    const uint32_t sb = smem_u32(smc);
    float* sZ   = (float*)(smc + SZ_O);
    float* sDen = (float*)(smc + SDEN_O);

    const int n = blockIdx.x, h = blockIdx.y, b = blockIdx.z;
    const int tid = threadIdx.x;
    const int wid = tid >> 5, lane = tid & 31;
    const int m_off = (wid & 1) * 64;
    const int n_off = (wid >> 1) * 32;      // pass A (N=128)
    const int n_off2 = (wid >> 1) * 16;     // pass B (N=64)
    const size_t rowbase = ((size_t)(b * TLEN + n * CHK)) * EDIM + h * DHEAD;
    const size_t sbase = ((size_t)((b * NHEAD + h) * NCH) + n) * DHEAD * DHEAD;
    const size_t zbase = ((size_t)((b * NHEAD + h) * NCH) + n) * DHEAD;

    // cp.async stage Q, K, V row-major [128][72]
    #pragma unroll
    for (int it = 0; it < 4; ++it) {
        int u = tid + it * 256;             // 0..1023
        int row = u >> 3, seg = u & 7;
        uint32_t so = (uint32_t)((row * 72 + seg * 8) * 2);
        CP_ASYNC16(sb + SQ_O + so, q16 + rowbase + (size_t)row * EDIM + seg * 8);
        CP_ASYNC16(sb + SK_O + so, k16 + rowbase + (size_t)row * EDIM + seg * 8);
        CP_ASYNC16(sb + SV_O + so, v16 + rowbase + (size_t)row * EDIM + seg * 8);
    }
    CP_COMMIT();
    // stage S fp32 -> fp16 row-major [64][72] (overlaps with cp.async)
    #pragma unroll
    for (int it = 0; it < 4; ++it) {
        int u = tid + it * 256;             // 0..1023 float4s
        int row = u >> 4, col4 = (u & 15) * 4;
        float4 s4 = *(const float4*)(S + sbase + (size_t)row * DHEAD + col4);
        __half2* dst = (__half2*)(smc + SS_O + (row * 72 + col4) * 2);
        dst[0] = __floats2half2_rn(s4.x, s4.y);
        dst[1] = __floats2half2_rn(s4.z, s4.w);
    }
    if (tid < DHEAD) sZ[tid] = Z[zbase + tid];
    CP_WAIT(0);
    __syncthreads();

    // den init: eps + phiq . Z
    if (tid < CHK) {
        float s2 = 1e-6f;
        const __half2* qr = (const __half2*)(smc + SQ_O + tid * 144);
        #pragma unroll
        for (int d2 = 0; d2 < 32; ++d2) {
            float2 qq = __half22float2(qr[d2]);
            s2 += qq.x * sZ[2 * d2] + qq.y * sZ[2 * d2 + 1];
        }
        sDen[tid] = s2;
    }
    __syncthreads();

    // fragment offsets
    uint32_t aoffQ[4], aoffA[4], boffK[2];
    #pragma unroll
    for (int mt = 0; mt < 4; ++mt) {
        int rr = m_off + 16 * mt + (lane & 15);
        aoffQ[mt] = (uint32_t)((rr * 72 + (lane >> 4) * 8) * 2);
        aoffA[mt] = (uint32_t)((rr * 136 + (lane >> 4) * 8) * 2);
    }
    #pragma unroll
    for (int p = 0; p < 2; ++p)
        boffK[p] = (uint32_t)(((n_off + 16 * p + ((lane >> 4) << 3) + (lane & 7)) * 72
                               + ((lane >> 3) & 1) * 8) * 2);
    const uint32_t boffT = (uint32_t)(((((lane >> 3) & 1) * 8 + (lane & 7)) * 72
                                      + n_off2 + ((lane >> 4) & 1) * 8) * 2);

    // ---- Pass A: A = Q K^T (128x128, k=64), causal triangle skip ----
    {
        float acc[4][4][4] = {};
        #pragma unroll
        for (int ks = 0; ks < DHEAD; ks += 16) {
            const uint32_t kso = (uint32_t)(ks * 2);
            uint32_t a[4][4], bk[2][4];
            #pragma unroll
            for (int mt = 0; mt < 4; ++mt)
                if (n_off <= m_off + 16 * mt + 15)           // any tile in this row strip live
                    LDSM_X4(a[mt][0], a[mt][1], a[mt][2], a[mt][3],
                            sb + SQ_O + aoffQ[mt] + kso);
            #pragma unroll
            for (int p = 0; p < 2; ++p)
                if (n_off + 16 * p <= m_off + 63)            // any tile in this col strip live
                    LDSM_X4(bk[p][0], bk[p][1], bk[p][2], bk[p][3],
                            sb + SK_O + boffK[p] + kso);
            #pragma unroll
            for (int i = 0; i < 4; ++i)
                #pragma unroll
                for (int j = 0; j < 4; ++j) {
                    if (n_off + 8 * j > m_off + 16 * i + 15) continue;  // fully masked
                    const int p = j >> 1, w = (j & 1) * 2;
                    MMA16816H(acc[i][j], a[i], bk[p][w], bk[p][w + 1]);
                }
        }
        #pragma unroll
        for (int i = 0; i < 4; ++i) {
            const int r1 = m_off + 16 * i + (lane >> 2);
            const int r2 = r1 + 8;
            float rs1 = 0.f, rs2 = 0.f;
            #pragma unroll
            for (int j = 0; j < 4; ++j) {
                const int c = n_off + 8 * j + ((lane & 3) << 1);
                float v0 = (c <= r1) ? acc[i][j][0] : 0.f;
                float v1 = (c + 1 <= r1) ? acc[i][j][1] : 0.f;
                float v2 = (c <= r2) ? acc[i][j][2] : 0.f;
                float v3 = (c + 1 <= r2) ? acc[i][j][3] : 0.f;
                rs1 += v0 + v1; rs2 += v2 + v3;
                *(__half2*)(smc + SA_O + (r1 * 136 + c) * 2) = __floats2half2_rn(v0, v1);
                *(__half2*)(smc + SA_O + (r2 * 136 + c) * 2) = __floats2half2_rn(v2, v3);
            }
            rs1 += __shfl_xor_sync(0xFFFFFFFFu, rs1, 1);
            rs1 += __shfl_xor_sync(0xFFFFFFFFu, rs1, 2);
            rs2 += __shfl_xor_sync(0xFFFFFFFFu, rs2, 1);
            rs2 += __shfl_xor_sync(0xFFFFFFFFu, rs2, 2);
            if ((lane & 3) == 0) {
                atomicAdd(&sDen[r1], rs1);
                atomicAdd(&sDen[r2], rs2);
            }
        }
    }
    __syncthreads();

    // ---- Pass B: num = A.V + Q.S (128x64), trans B-operands ----
    {
        float acc2[4][2][4] = {};
        #pragma unroll
        for (int ks = 0; ks < CHK; ks += 16) {        // A.V, k = s = 128
            const uint32_t kso = (uint32_t)(ks * 2);
            const uint32_t kb = (uint32_t)(ks * 144);
            uint32_t a[4][4], bv[4];
            #pragma unroll
            for (int mt = 0; mt < 4; ++mt)
                LDSM_X4(a[mt][0], a[mt][1], a[mt][2], a[mt][3],
                        sb + SA_O + aoffA[mt] + kso);
            LDSM_X4_T(bv[0], bv[1], bv[2], bv[3], sb + SV_O + boffT + kb);
            #pragma unroll
            for (int i = 0; i < 4; ++i)
                #pragma unroll
                for (int j2 = 0; j2 < 2; ++j2)
                    MMA16816H(acc2[i][j2], a[i], bv[2 * j2], bv[2 * j2 + 1]);
        }
        #pragma unroll
        for (int ks = 0; ks < DHEAD; ks += 16) {      // Q.S, k = d = 64
            const uint32_t kso = (uint32_t)(ks * 2);
            const uint32_t kb = (uint32_t)(ks * 144);
            uint32_t a[4][4], bs[4];
            #pragma unroll
            for (int mt = 0; mt < 4; ++mt)
                LDSM_X4(a[mt][0], a[mt][1], a[mt][2], a[mt][3],
                        sb + SQ_O + aoffQ[mt] + kso);
            LDSM_X4_T(bs[0], bs[1], bs[2], bs[3], sb + SS_O + boffT + kb);
            #pragma unroll
            for (int i = 0; i < 4; ++i)
                #pragma unroll
                for (int j2 = 0; j2 < 2; ++j2)
                    MMA16816H(acc2[i][j2], a[i], bs[2 * j2], bs[2 * j2 + 1]);
        }
        #pragma unroll
        for (int i = 0; i < 4; ++i) {
            const int r1 = m_off + 16 * i + (lane >> 2);
            const int r2 = r1 + 8;
            const float inv1 = 1.0f / sDen[r1];
            const float inv2 = 1.0f / sDen[r2];
            #pragma unroll
            for (int j2 = 0; j2 < 2; ++j2) {
                const int c = n_off2 + 8 * j2 + ((lane & 3) << 1);
                *(__half2*)(y16 + rowbase + (size_t)r1 * EDIM + c) =
                    __floats2half2_rn(acc2[i][j2][0] * inv1, acc2[i][j2][1] * inv1);
                *(__half2*)(y16 + rowbase + (size_t)r2 * EDIM + c) =
                    __floats2half2_rn(acc2[i][j2][2] * inv2, acc2[i][j2][3] * inv2);
            }
        }
    }
}

// ---------------------------------------------------------------------------
extern "C" void kernel_launch(void* const* d_in, const int* in_sizes, int n_in,
                              void* d_out, int out_size)
{
    const float* x  = (const float*)d_in[0];
    const float* Wq = (const float*)d_in[1];
    const float* Wk = (const float*)d_in[2];
    const float* Wv = (const float*)d_in[3];
    const float* Wp = (const float*)d_in[4];
    const float* bp = (const float*)d_in[5];
    float* out = (float*)d_out;

    float *kv, *S, *zk, *Z;
    __half *xh, *qh, *kh, *vh, *yh, *wh;
    cudaGetSymbolAddress((void**)&kv, g_kv);
    cudaGetSymbolAddress((void**)&S,  g_S);
    cudaGetSymbolAddress((void**)&zk, g_zk);
    cudaGetSymbolAddress((void**)&Z,  g_Z);
    cudaGetSymbolAddress((void**)&xh, g_xh);
    cudaGetSymbolAddress((void**)&qh, g_qh);
    cudaGetSymbolAddress((void**)&kh, g_kh);
    cudaGetSymbolAddress((void**)&vh, g_vh);
    cudaGetSymbolAddress((void**)&yh, g_yh);
    cudaGetSymbolAddress((void**)&wh, g_wh);

    cudaFuncSetAttribute(tc_gemm<true>,  cudaFuncAttributeMaxDynamicSharedMemorySize, GEMM_SMEM);
    cudaFuncSetAttribute(tc_gemm<false>, cudaFuncAttributeMaxDynamicSharedMemorySize, GEMM_SMEM);
    cudaFuncSetAttribute(chunk_attn_mma,
                         cudaFuncAttributeMaxDynamicSharedMemorySize, ATTN_SMEM);

    const size_t WSZ = (size_t)EDIM * EDIM;

    const int castN = N4X + 4 * N4W;
    cast_all_kernel<<<(castN + 255) / 256, 256>>>(x, Wq, Wk, Wv, Wp, xh, wh);

    dim3 gq(EDIM / 128, MROWS / 128, 3);   // batched q/k/v, fp16-only outputs
    tc_gemm<true><<<gq, 256, GEMM_SMEM>>>(xh, wh, nullptr, nullptr, qh, kh, vh);

    chunk_kv_mma<<<dim3(NCH, NHEAD, BSZ), 256>>>(kh, vh, kv, zk);

    const int scanN = SCAN1 + SCAN2;
    prefix_scan_all<<<(scanN + 255) / 256, 256>>>(kv, S, zk, Z);

    chunk_attn_mma<<<dim3(NCH, NHEAD, BSZ), 256, ATTN_SMEM>>>(qh, kh, vh, S, Z, yh);

    dim3 gp(EDIM / 128, MROWS / 128);      // final projection (1-pass fp16)
    tc_gemm<false><<<gp, 256, GEMM_SMEM>>>(yh, wh + 3 * WSZ, bp, out,
                                           nullptr, nullptr, nullptr);
}

// round 11
// speedup vs baseline: 5.8246x; 1.2565x over previous
#include <cuda_runtime.h>
#include <cuda_fp16.h>
#include <math.h>
#include <stdint.h>

// Problem constants
#define BSZ   4
#define TLEN  2048
#define EDIM  1024
#define NHEAD 16
#define DHEAD 64
#define CHK   128
#define NCH   16            // TLEN / CHK
#define MROWS (BSZ*TLEN)    // 8192

// Scratch (device globals; allocation-free rule)
__device__ float g_kv[(size_t)BSZ*NHEAD*NCH*DHEAD*DHEAD];
__device__ float g_S [(size_t)BSZ*NHEAD*NCH*DHEAD*DHEAD];
__device__ float g_zk[(size_t)BSZ*NHEAD*NCH*DHEAD];
__device__ float g_Z [(size_t)BSZ*NHEAD*NCH*DHEAD];
// fp16 buffers
__device__ __half g_xh[(size_t)MROWS*EDIM];
__device__ __half g_qh[(size_t)MROWS*EDIM];
__device__ __half g_kh[(size_t)MROWS*EDIM];
__device__ __half g_vh[(size_t)MROWS*EDIM];
__device__ __half g_yh[(size_t)MROWS*EDIM];
__device__ __half g_wh[(size_t)4*EDIM*EDIM];      // Wq,Wk,Wv,Wp fp16

// ---------------------------------------------------------------------------
// helpers
// ---------------------------------------------------------------------------
__device__ __forceinline__ uint32_t smem_u32(const void* p) {
    uint32_t a;
    asm("{ .reg .u64 t; cvta.to.shared.u64 t, %1; cvt.u32.u64 %0, t; }"
        : "=r"(a) : "l"(p));
    return a;
}
#define CP_ASYNC16(dst, src) \
    asm volatile("cp.async.cg.shared.global [%0], [%1], 16;" \
                 :: "r"(dst), "l"(src) : "memory")
#define CP_COMMIT() asm volatile("cp.async.commit_group;" ::: "memory")
#define CP_WAIT(N)  asm volatile("cp.async.wait_group %0;" :: "n"(N) : "memory")
#define LDSM_X4(r0, r1, r2, r3, a) \
    asm volatile("ldmatrix.sync.aligned.m8n8.x4.shared.b16 {%0,%1,%2,%3}, [%4];" \
                 : "=r"(r0), "=r"(r1), "=r"(r2), "=r"(r3) : "r"(a))
#define LDSM_X4_T(r0, r1, r2, r3, a) \
    asm volatile("ldmatrix.sync.aligned.m8n8.x4.trans.shared.b16 {%0,%1,%2,%3}, [%4];" \
                 : "=r"(r0), "=r"(r1), "=r"(r2), "=r"(r3) : "r"(a))
#define MMA16816H(d, a, b0v, b1v) \
    asm volatile("mma.sync.aligned.m16n8k16.row.col.f32.f16.f16.f32 " \
                 "{%0,%1,%2,%3}, {%4,%5,%6,%7}, {%8,%9}, {%0,%1,%2,%3};" \
                 : "+f"((d)[0]), "+f"((d)[1]), "+f"((d)[2]), "+f"((d)[3]) \
                 : "r"((a)[0]), "r"((a)[1]), "r"((a)[2]), "r"((a)[3]), \
                   "r"(b0v), "r"(b1v))

// ---------------------------------------------------------------------------
// merged fp32 -> fp16 casts: x (2M float4) then 4 weights (256K float4 each)
// ---------------------------------------------------------------------------
#define N4X (MROWS * EDIM / 4)          // 2097152
#define N4W (EDIM * EDIM / 4)           // 262144

__global__ void cast_all_kernel(const float* __restrict__ x,
                                const float* __restrict__ W0,
                                const float* __restrict__ W1,
                                const float* __restrict__ W2,
                                const float* __restrict__ W3,
                                __half* __restrict__ xh,
                                __half* __restrict__ wh)
{
    int i = blockIdx.x * blockDim.x + threadIdx.x;
    const float* src;
    __half* dst;
    int off;
    if (i < N4X) {
        src = x; dst = xh; off = i;
    } else {
        int j = i - N4X;
        if (j >= 4 * N4W) return;
        int w = j / N4W;
        off = j - w * N4W;
        src = (w == 0) ? W0 : (w == 1) ? W1 : (w == 2) ? W2 : W3;
        dst = wh + (size_t)w * EDIM * EDIM;
    }
    float4 v = ((const float4*)src)[off];
    ((__half2*)dst)[2 * off + 0] = __floats2half2_rn(v.x, v.y);
    ((__half2*)dst)[2 * off + 1] = __floats2half2_rn(v.z, v.w);
}

// ---------------------------------------------------------------------------
// mma.sync fp16 GEMM (NT): C[m,n] = sum_k A[m,k]*B[n,k].
// BM=BN=128, BK=32, 8 warps (2x4), warp tile 64x32, cp.async double-buffer.
// 2 CTAs/SM to hide barrier/staging bubbles with co-resident mma issue.
// QKV=true: batched blockIdx.z (0=q,1=k phi; 2=v), writes fp16 ONLY.
// QKV=false: single GEMM, +bias, fp32 out.
// ---------------------------------------------------------------------------
#define BK      32
#define LDT     40                      // BK + 8 pad (fp16 elems)
#define TILEB   (128 * LDT * 2)         // 10240 B per tile
#define NT      (EDIM / BK)             // 32 chunks
#define GEMM_SMEM (2 * 2 * TILEB)       // 40960 B

template <bool QKV>
__global__ void __launch_bounds__(256, 2)
tc_gemm(const __half* __restrict__ Ah, const __half* __restrict__ Wbase,
        const float* __restrict__ bias, float* __restrict__ C,
        __half* __restrict__ H0, __half* __restrict__ H1, __half* __restrict__ H2)
{
    extern __shared__ char smc[];
    const uint32_t sb = smem_u32(smc);
    const int tid = threadIdx.x;
    const int wid = tid >> 5, lane = tid & 31;
    const int m0g = blockIdx.y * 128;
    const int n0g = blockIdx.x * 128;
    const int m_off = (wid & 1) * 64;
    const int n_off = (wid >> 1) * 32;
    const int z = QKV ? blockIdx.z : 0;
    const __half* Bh = Wbase + (size_t)z * EDIM * EDIM;
    __half* C16 = QKV ? ((z == 0) ? H0 : (z == 1) ? H1 : H2) : nullptr;
    const bool phi = QKV && (z < 2);

    uint32_t aoff[4], boff[2];
    #pragma unroll
    for (int mt = 0; mt < 4; ++mt)
        aoff[mt] = (uint32_t)(((m_off + 16 * mt + (lane & 15)) * LDT
                               + (lane >> 4) * 8) * 2);
    #pragma unroll
    for (int p = 0; p < 2; ++p)
        boff[p] = (uint32_t)(((n_off + 16 * p + ((lane >> 4) << 3) + (lane & 7)) * LDT
                              + ((lane >> 3) & 1) * 8) * 2);

    auto stage_tile = [&](const __half* __restrict__ src, int row0,
                          int kc, uint32_t dstbase) {
        #pragma unroll
        for (int j = 0; j < 2; ++j) {
            int u = tid + j * 256;
            int row = u >> 2, seg = u & 3;
            uint32_t d = dstbase + (uint32_t)((row * LDT + seg * 8) * 2);
            const __half* g = src + (size_t)(row0 + row) * EDIM + kc + seg * 8;
            CP_ASYNC16(d, g);
        }
    };
    auto stage_chunk = [&](int t, int buf) {
        int kc = t * BK;
        uint32_t base = sb + buf * 2 * TILEB;
        stage_tile(Ah, m0g, kc, base);
        stage_tile(Bh, n0g, kc, base + TILEB);
        CP_COMMIT();
    };

    float acc[4][4][4] = {};

    stage_chunk(0, 0);
    for (int t = 0; t < NT; ++t) {
        const int cur = t & 1;
        if (t + 1 < NT) {
            stage_chunk(t + 1, 1 - cur);
            CP_WAIT(1);
        } else {
            CP_WAIT(0);
        }
        __syncthreads();

        const uint32_t base = sb + cur * 2 * TILEB;
        #pragma unroll
        for (int ks = 0; ks < BK; ks += 16) {
            const uint32_t kso = (uint32_t)(ks * 2);
            uint32_t ah[4][4], bh[2][4];
            #pragma unroll
            for (int mt = 0; mt < 4; ++mt)
                LDSM_X4(ah[mt][0], ah[mt][1], ah[mt][2], ah[mt][3],
                        base + aoff[mt] + kso);
            #pragma unroll
            for (int p = 0; p < 2; ++p)
                LDSM_X4(bh[p][0], bh[p][1], bh[p][2], bh[p][3],
                        base + TILEB + boff[p] + kso);
            #pragma unroll
            for (int i = 0; i < 4; ++i)
                #pragma unroll
                for (int j = 0; j < 4; ++j) {
                    const int p = j >> 1, w = (j & 1) * 2;
                    MMA16816H(acc[i][j], ah[i], bh[p][w], bh[p][w + 1]);
                }
        }
        __syncthreads();
    }

    #pragma unroll
    for (int i = 0; i < 4; ++i) {
        const int r = m0g + m_off + 16 * i + (lane >> 2);
        #pragma unroll
        for (int j = 0; j < 4; ++j) {
            const int c = n0g + n_off + 8 * j + ((lane & 3) << 1);
            float v0 = acc[i][j][0], v1 = acc[i][j][1];
            float v2 = acc[i][j][2], v3 = acc[i][j][3];
            if (QKV) {
                if (phi) {
                    v0 = (v0 > 0.f) ? (v0 + 1.f) : __expf(v0);
                    v1 = (v1 > 0.f) ? (v1 + 1.f) : __expf(v1);
                    v2 = (v2 > 0.f) ? (v2 + 1.f) : __expf(v2);
                    v3 = (v3 > 0.f) ? (v3 + 1.f) : __expf(v3);
                }
                *(__half2*)(C16 + (size_t)r * EDIM + c) = __floats2half2_rn(v0, v1);
                *(__half2*)(C16 + (size_t)(r + 8) * EDIM + c) = __floats2half2_rn(v2, v3);
            } else {
                float b0 = bias[c], b1 = bias[c + 1];
                *(float2*)(C + (size_t)r * EDIM + c) = make_float2(v0 + b0, v1 + b1);
                *(float2*)(C + (size_t)(r + 8) * EDIM + c) = make_float2(v2 + b0, v3 + b1);
            }
        }
    }
}

// ---------------------------------------------------------------------------
// Per-chunk kv state via fp16 mma with ldmatrix.trans, cp.async staging.
// ---------------------------------------------------------------------------
__global__ void __launch_bounds__(256)
chunk_kv_mma(const __half* __restrict__ k16, const __half* __restrict__ v16,
             float* __restrict__ kv, float* __restrict__ zk)
{
    __shared__ __align__(16) __half sKr[128 * 72];
    __shared__ __align__(16) __half sVr[128 * 72];
    const uint32_t sbK = smem_u32(sKr);
    const uint32_t sbV = smem_u32(sVr);

    const int n = blockIdx.x, h = blockIdx.y, b = blockIdx.z;
    const int tid = threadIdx.x;
    const int wid = tid >> 5, lane = tid & 31;
    const int m_off = (wid & 1) * 32;       // d
    const int n_off = (wid >> 1) * 16;      // e
    const size_t rowbase = ((size_t)(b * TLEN + n * CHK)) * EDIM + h * DHEAD;

    // cp.async row-major staging: 128 rows x 64 halves (8 x 16B per row)
    #pragma unroll
    for (int it = 0; it < 4; ++it) {
        int u = tid + it * 256;             // 0..1023
        int row = u >> 3, seg = u & 7;
        const __half* g = k16 + rowbase + (size_t)row * EDIM + seg * 8;
        const __half* g2 = v16 + rowbase + (size_t)row * EDIM + seg * 8;
        CP_ASYNC16(sbK + (uint32_t)((row * 72 + seg * 8) * 2), g);
        CP_ASYNC16(sbV + (uint32_t)((row * 72 + seg * 8) * 2), g2);
    }
    CP_COMMIT();
    CP_WAIT(0);
    __syncthreads();

    if (tid < DHEAD) {
        float z = 0.f;
        #pragma unroll 8
        for (int c = 0; c < CHK; ++c) z += __half2float(sKr[c * 72 + tid]);
        zk[((size_t)((b * NHEAD + h) * NCH) + n) * DHEAD + tid] = z;
    }

    // trans-fragment offsets (bytes), add ks*144 per k-step
    uint32_t aoffT[2];
    #pragma unroll
    for (int mt = 0; mt < 2; ++mt)
        aoffT[mt] = (uint32_t)(((((lane >> 4) & 1) * 8 + (lane & 7)) * 72
                                + m_off + 16 * mt + ((lane >> 3) & 1) * 8) * 2);
    const uint32_t boffT = (uint32_t)(((((lane >> 3) & 1) * 8 + (lane & 7)) * 72
                                      + n_off + ((lane >> 4) & 1) * 8) * 2);

    float acc[2][2][4] = {};
    #pragma unroll
    for (int ks = 0; ks < CHK; ks += 16) {
        const uint32_t kb = (uint32_t)(ks * 144);
        uint32_t a[2][4], bv[4];
        #pragma unroll
        for (int mt = 0; mt < 2; ++mt)
            LDSM_X4_T(a[mt][0], a[mt][1], a[mt][2], a[mt][3], sbK + aoffT[mt] + kb);
        LDSM_X4_T(bv[0], bv[1], bv[2], bv[3], sbV + boffT + kb);
        #pragma unroll
        for (int i = 0; i < 2; ++i)
            #pragma unroll
            for (int j2 = 0; j2 < 2; ++j2)
                MMA16816H(acc[i][j2], a[i], bv[2 * j2], bv[2 * j2 + 1]);
    }

    const size_t obase = ((size_t)((b * NHEAD + h) * NCH) + n) * DHEAD * DHEAD;
    #pragma unroll
    for (int i = 0; i < 2; ++i) {
        const int r1 = m_off + 16 * i + (lane >> 2);
        const int r2 = r1 + 8;
        #pragma unroll
        for (int j2 = 0; j2 < 2; ++j2) {
            const int c = n_off + 8 * j2 + ((lane & 3) << 1);
            *(float2*)(kv + obase + (size_t)r1 * DHEAD + c) =
                make_float2(acc[i][j2][0], acc[i][j2][1]);
            *(float2*)(kv + obase + (size_t)r2 * DHEAD + c) =
                make_float2(acc[i][j2][2], acc[i][j2][3]);
        }
    }
}

// ---------------------------------------------------------------------------
// Merged exclusive prefix scans over the N=16 chunk axis (kv->S and zk->Z)
// ---------------------------------------------------------------------------
#define SCAN1 (BSZ * NHEAD * DHEAD * DHEAD)   // 262144
#define SCAN2 (BSZ * NHEAD * DHEAD)           // 4096

__global__ void prefix_scan_all(const float* __restrict__ kv,
                                float* __restrict__ S,
                                const float* __restrict__ zk,
                                float* __restrict__ Z)
{
    int i = blockIdx.x * blockDim.x + threadIdx.x;
    const float* src;
    float* dst;
    size_t base;
    int per;
    if (i < SCAN1) {
        per = DHEAD * DHEAD;
        int bh = i / per, r = i - bh * per;
        base = (size_t)bh * NCH * per + r;
        src = kv; dst = S;
    } else {
        int j = i - SCAN1;
        if (j >= SCAN2) return;
        per = DHEAD;
        int bh = j / per, r = j - bh * per;
        base = (size_t)bh * NCH * per + r;
        src = zk; dst = Z;
    }
    float acc = 0.f;
    #pragma unroll
    for (int nn = 0; nn < NCH; ++nn) {
        dst[base + (size_t)nn * per] = acc;
        acc += src[base + (size_t)nn * per];
    }
}

// ---------------------------------------------------------------------------
// Tensor-core per-chunk attention; cp.async staging, causal triangle skip.
// ---------------------------------------------------------------------------
#define SQ_O    0                       // [128][72] fp16
#define SK_O    18432                   // [128][72] fp16
#define SV_O    36864                   // [128][72] fp16 (row-major)
#define SS_O    55296                   // [64][72]  fp16 (row-major, d rows)
#define SA_O    64512                   // [128][136] fp16 masked A
#define SZ_O    99328                   // [64] fp32
#define SDEN_O  99584                   // [128] fp32
#define ATTN_SMEM 100096

__global__ void __launch_bounds__(256)
chunk_attn_mma(const __half* __restrict__ q16, const __half* __restrict__ k16,
               const __half* __restrict__ v16, const float* __restrict__ S,
               const float* __restrict__ Z, __half* __restrict__ y16)
{
    extern __shared__ char smc[];
    const uint32_t sb = smem_u32(smc);
    float* sZ   = (float*)(smc + SZ_O);
    float* sDen = (float*)(smc + SDEN_O);

    const int n = blockIdx.x, h = blockIdx.y, b = blockIdx.z;
    const int tid = threadIdx.x;
    const int wid = tid >> 5, lane = tid & 31;
    const int m_off = (wid & 1) * 64;
    const int n_off = (wid >> 1) * 32;      // pass A (N=128)
    const int n_off2 = (wid >> 1) * 16;     // pass B (N=64)
    const size_t rowbase = ((size_t)(b * TLEN + n * CHK)) * EDIM + h * DHEAD;
    const size_t sbase = ((size_t)((b * NHEAD + h) * NCH) + n) * DHEAD * DHEAD;
    const size_t zbase = ((size_t)((b * NHEAD + h) * NCH) + n) * DHEAD;

    // cp.async stage Q, K, V row-major [128][72]
    #pragma unroll
    for (int it = 0; it < 4; ++it) {
        int u = tid + it * 256;             // 0..1023
        int row = u >> 3, seg = u & 7;
        uint32_t so = (uint32_t)((row * 72 + seg * 8) * 2);
        CP_ASYNC16(sb + SQ_O + so, q16 + rowbase + (size_t)row * EDIM + seg * 8);
        CP_ASYNC16(sb + SK_O + so, k16 + rowbase + (size_t)row * EDIM + seg * 8);
        CP_ASYNC16(sb + SV_O + so, v16 + rowbase + (size_t)row * EDIM + seg * 8);
    }
    CP_COMMIT();
    // stage S fp32 -> fp16 row-major [64][72] (overlaps with cp.async)
    #pragma unroll
    for (int it = 0; it < 4; ++it) {
        int u = tid + it * 256;             // 0..1023 float4s
        int row = u >> 4, col4 = (u & 15) * 4;
        float4 s4 = *(const float4*)(S + sbase + (size_t)row * DHEAD + col4);
        __half2* dst = (__half2*)(smc + SS_O + (row * 72 + col4) * 2);
        dst[0] = __floats2half2_rn(s4.x, s4.y);
        dst[1] = __floats2half2_rn(s4.z, s4.w);
    }
    if (tid < DHEAD) sZ[tid] = Z[zbase + tid];
    CP_WAIT(0);
    __syncthreads();

    // den init: eps + phiq . Z
    if (tid < CHK) {
        float s2 = 1e-6f;
        const __half2* qr = (const __half2*)(smc + SQ_O + tid * 144);
        #pragma unroll
        for (int d2 = 0; d2 < 32; ++d2) {
            float2 qq = __half22float2(qr[d2]);
            s2 += qq.x * sZ[2 * d2] + qq.y * sZ[2 * d2 + 1];
        }
        sDen[tid] = s2;
    }
    __syncthreads();

    // fragment offsets
    uint32_t aoffQ[4], aoffA[4], boffK[2];
    #pragma unroll
    for (int mt = 0; mt < 4; ++mt) {
        int rr = m_off + 16 * mt + (lane & 15);
        aoffQ[mt] = (uint32_t)((rr * 72 + (lane >> 4) * 8) * 2);
        aoffA[mt] = (uint32_t)((rr * 136 + (lane >> 4) * 8) * 2);
    }
    #pragma unroll
    for (int p = 0; p < 2; ++p)
        boffK[p] = (uint32_t)(((n_off + 16 * p + ((lane >> 4) << 3) + (lane & 7)) * 72
                               + ((lane >> 3) & 1) * 8) * 2);
    const uint32_t boffT = (uint32_t)(((((lane >> 3) & 1) * 8 + (lane & 7)) * 72
                                      + n_off2 + ((lane >> 4) & 1) * 8) * 2);

    // ---- Pass A: A = Q K^T (128x128, k=64), causal triangle skip ----
    {
        float acc[4][4][4] = {};
        #pragma unroll
        for (int ks = 0; ks < DHEAD; ks += 16) {
            const uint32_t kso = (uint32_t)(ks * 2);
            uint32_t a[4][4], bk[2][4];
            #pragma unroll
            for (int mt = 0; mt < 4; ++mt)
                if (n_off <= m_off + 16 * mt + 15)           // any tile in this row strip live
                    LDSM_X4(a[mt][0], a[mt][1], a[mt][2], a[mt][3],
                            sb + SQ_O + aoffQ[mt] + kso);
            #pragma unroll
            for (int p = 0; p < 2; ++p)
                if (n_off + 16 * p <= m_off + 63)            // any tile in this col strip live
                    LDSM_X4(bk[p][0], bk[p][1], bk[p][2], bk[p][3],
                            sb + SK_O + boffK[p] + kso);
            #pragma unroll
            for (int i = 0; i < 4; ++i)
                #pragma unroll
                for (int j = 0; j < 4; ++j) {
                    if (n_off + 8 * j > m_off + 16 * i + 15) continue;  // fully masked
                    const int p = j >> 1, w = (j & 1) * 2;
                    MMA16816H(acc[i][j], a[i], bk[p][w], bk[p][w + 1]);
                }
        }
        #pragma unroll
        for (int i = 0; i < 4; ++i) {
            const int r1 = m_off + 16 * i + (lane >> 2);
            const int r2 = r1 + 8;
            float rs1 = 0.f, rs2 = 0.f;
            #pragma unroll
            for (int j = 0; j < 4; ++j) {
                const int c = n_off + 8 * j + ((lane & 3) << 1);
                float v0 = (c <= r1) ? acc[i][j][0] : 0.f;
                float v1 = (c + 1 <= r1) ? acc[i][j][1] : 0.f;
                float v2 = (c <= r2) ? acc[i][j][2] : 0.f;
                float v3 = (c + 1 <= r2) ? acc[i][j][3] : 0.f;
                rs1 += v0 + v1; rs2 += v2 + v3;
                *(__half2*)(smc + SA_O + (r1 * 136 + c) * 2) = __floats2half2_rn(v0, v1);
                *(__half2*)(smc + SA_O + (r2 * 136 + c) * 2) = __floats2half2_rn(v2, v3);
            }
            rs1 += __shfl_xor_sync(0xFFFFFFFFu, rs1, 1);
            rs1 += __shfl_xor_sync(0xFFFFFFFFu, rs1, 2);
            rs2 += __shfl_xor_sync(0xFFFFFFFFu, rs2, 1);
            rs2 += __shfl_xor_sync(0xFFFFFFFFu, rs2, 2);
            if ((lane & 3) == 0) {
                atomicAdd(&sDen[r1], rs1);
                atomicAdd(&sDen[r2], rs2);
            }
        }
    }
    __syncthreads();

    // ---- Pass B: num = A.V + Q.S (128x64), trans B-operands ----
    {
        float acc2[4][2][4] = {};
        #pragma unroll
        for (int ks = 0; ks < CHK; ks += 16) {        // A.V, k = s = 128
            const uint32_t kso = (uint32_t)(ks * 2);
            const uint32_t kb = (uint32_t)(ks * 144);
            uint32_t a[4][4], bv[4];
            #pragma unroll
            for (int mt = 0; mt < 4; ++mt)
                LDSM_X4(a[mt][0], a[mt][1], a[mt][2], a[mt][3],
                        sb + SA_O + aoffA[mt] + kso);
            LDSM_X4_T(bv[0], bv[1], bv[2], bv[3], sb + SV_O + boffT + kb);
            #pragma unroll
            for (int i = 0; i < 4; ++i)
                #pragma unroll
                for (int j2 = 0; j2 < 2; ++j2)
                    MMA16816H(acc2[i][j2], a[i], bv[2 * j2], bv[2 * j2 + 1]);
        }
        #pragma unroll
        for (int ks = 0; ks < DHEAD; ks += 16) {      // Q.S, k = d = 64
            const uint32_t kso = (uint32_t)(ks * 2);
            const uint32_t kb = (uint32_t)(ks * 144);
            uint32_t a[4][4], bs[4];
            #pragma unroll
            for (int mt = 0; mt < 4; ++mt)
                LDSM_X4(a[mt][0], a[mt][1], a[mt][2], a[mt][3],
                        sb + SQ_O + aoffQ[mt] + kso);
            LDSM_X4_T(bs[0], bs[1], bs[2], bs[3], sb + SS_O + boffT + kb);
            #pragma unroll
            for (int i = 0; i < 4; ++i)
                #pragma unroll
                for (int j2 = 0; j2 < 2; ++j2)
                    MMA16816H(acc2[i][j2], a[i], bs[2 * j2], bs[2 * j2 + 1]);
        }
        #pragma unroll
        for (int i = 0; i < 4; ++i) {
            const int r1 = m_off + 16 * i + (lane >> 2);
            const int r2 = r1 + 8;
            const float inv1 = 1.0f / sDen[r1];
            const float inv2 = 1.0f / sDen[r2];
            #pragma unroll
            for (int j2 = 0; j2 < 2; ++j2) {
                const int c = n_off2 + 8 * j2 + ((lane & 3) << 1);
                *(__half2*)(y16 + rowbase + (size_t)r1 * EDIM + c) =
                    __floats2half2_rn(acc2[i][j2][0] * inv1, acc2[i][j2][1] * inv1);
                *(__half2*)(y16 + rowbase + (size_t)r2 * EDIM + c) =
                    __floats2half2_rn(acc2[i][j2][2] * inv2, acc2[i][j2][3] * inv2);
            }
        }
    }
}

// ---------------------------------------------------------------------------
extern "C" void kernel_launch(void* const* d_in, const int* in_sizes, int n_in,
                              void* d_out, int out_size)
{
    const float* x  = (const float*)d_in[0];
    const float* Wq = (const float*)d_in[1];
    const float* Wk = (const float*)d_in[2];
    const float* Wv = (const float*)d_in[3];
    const float* Wp = (const float*)d_in[4];
    const float* bp = (const float*)d_in[5];
    float* out = (float*)d_out;

    float *kv, *S, *zk, *Z;
    __half *xh, *qh, *kh, *vh, *yh, *wh;
    cudaGetSymbolAddress((void**)&kv, g_kv);
    cudaGetSymbolAddress((void**)&S,  g_S);
    cudaGetSymbolAddress((void**)&zk, g_zk);
    cudaGetSymbolAddress((void**)&Z,  g_Z);
    cudaGetSymbolAddress((void**)&xh, g_xh);
    cudaGetSymbolAddress((void**)&qh, g_qh);
    cudaGetSymbolAddress((void**)&kh, g_kh);
    cudaGetSymbolAddress((void**)&vh, g_vh);
    cudaGetSymbolAddress((void**)&yh, g_yh);
    cudaGetSymbolAddress((void**)&wh, g_wh);

    cudaFuncSetAttribute(tc_gemm<true>,  cudaFuncAttributeMaxDynamicSharedMemorySize, GEMM_SMEM);
    cudaFuncSetAttribute(tc_gemm<false>, cudaFuncAttributeMaxDynamicSharedMemorySize, GEMM_SMEM);
    cudaFuncSetAttribute(chunk_attn_mma,
                         cudaFuncAttributeMaxDynamicSharedMemorySize, ATTN_SMEM);

    const size_t WSZ = (size_t)EDIM * EDIM;

    const int castN = N4X + 4 * N4W;
    cast_all_kernel<<<(castN + 255) / 256, 256>>>(x, Wq, Wk, Wv, Wp, xh, wh);

    dim3 gq(EDIM / 128, MROWS / 128, 3);   // batched q/k/v, fp16-only outputs
    tc_gemm<true><<<gq, 256, GEMM_SMEM>>>(xh, wh, nullptr, nullptr, qh, kh, vh);

    chunk_kv_mma<<<dim3(NCH, NHEAD, BSZ), 256>>>(kh, vh, kv, zk);

    const int scanN = SCAN1 + SCAN2;
    prefix_scan_all<<<(scanN + 255) / 256, 256>>>(kv, S, zk, Z);

    chunk_attn_mma<<<dim3(NCH, NHEAD, BSZ), 256, ATTN_SMEM>>>(qh, kh, vh, S, Z, yh);

    dim3 gp(EDIM / 128, MROWS / 128);      // final projection (1-pass fp16)
    tc_gemm<false><<<gp, 256, GEMM_SMEM>>>(yh, wh + 3 * WSZ, bp, out,
                                           nullptr, nullptr, nullptr);
}

// round 12
// speedup vs baseline: 6.4872x; 1.1138x over previous
#include <cuda_runtime.h>
#include <cuda_fp16.h>
#include <math.h>
#include <stdint.h>

// Problem constants
#define BSZ   4
#define TLEN  2048
#define EDIM  1024
#define NHEAD 16
#define DHEAD 64
#define CHK   128
#define NCH   16            // TLEN / CHK
#define MROWS (BSZ*TLEN)    // 8192

// Scratch (device globals; allocation-free rule)
__device__ float g_kv[(size_t)BSZ*NHEAD*NCH*DHEAD*DHEAD];
__device__ float g_S [(size_t)BSZ*NHEAD*NCH*DHEAD*DHEAD];
__device__ float g_zk[(size_t)BSZ*NHEAD*NCH*DHEAD];
__device__ float g_Z [(size_t)BSZ*NHEAD*NCH*DHEAD];
// fp16 buffers
__device__ __half g_xh[(size_t)MROWS*EDIM];
__device__ __half g_qh[(size_t)MROWS*EDIM];
__device__ __half g_kh[(size_t)MROWS*EDIM];
__device__ __half g_vh[(size_t)MROWS*EDIM];
__device__ __half g_yh[(size_t)MROWS*EDIM];
__device__ __half g_wh[(size_t)4*EDIM*EDIM];      // Wq,Wk,Wv,Wp fp16

// ---------------------------------------------------------------------------
// helpers
// ---------------------------------------------------------------------------
__device__ __forceinline__ uint32_t smem_u32(const void* p) {
    uint32_t a;
    asm("{ .reg .u64 t; cvta.to.shared.u64 t, %1; cvt.u32.u64 %0, t; }"
        : "=r"(a) : "l"(p));
    return a;
}
#define CP_ASYNC16(dst, src) \
    asm volatile("cp.async.cg.shared.global [%0], [%1], 16;" \
                 :: "r"(dst), "l"(src) : "memory")
#define CP_COMMIT() asm volatile("cp.async.commit_group;" ::: "memory")
#define CP_WAIT(N)  asm volatile("cp.async.wait_group %0;" :: "n"(N) : "memory")
#define LDSM_X4(r0, r1, r2, r3, a) \
    asm volatile("ldmatrix.sync.aligned.m8n8.x4.shared.b16 {%0,%1,%2,%3}, [%4];" \
                 : "=r"(r0), "=r"(r1), "=r"(r2), "=r"(r3) : "r"(a))
#define LDSM_X4_T(r0, r1, r2, r3, a) \
    asm volatile("ldmatrix.sync.aligned.m8n8.x4.trans.shared.b16 {%0,%1,%2,%3}, [%4];" \
                 : "=r"(r0), "=r"(r1), "=r"(r2), "=r"(r3) : "r"(a))
#define MMA16816H(d, a, b0v, b1v) \
    asm volatile("mma.sync.aligned.m16n8k16.row.col.f32.f16.f16.f32 " \
                 "{%0,%1,%2,%3}, {%4,%5,%6,%7}, {%8,%9}, {%0,%1,%2,%3};" \
                 : "+f"((d)[0]), "+f"((d)[1]), "+f"((d)[2]), "+f"((d)[3]) \
                 : "r"((a)[0]), "r"((a)[1]), "r"((a)[2]), "r"((a)[3]), \
                   "r"(b0v), "r"(b1v))

// ---------------------------------------------------------------------------
// merged fp32 -> fp16 casts: x (2M float4) then 4 weights (256K float4 each)
// ---------------------------------------------------------------------------
#define N4X (MROWS * EDIM / 4)          // 2097152
#define N4W (EDIM * EDIM / 4)           // 262144

__global__ void cast_all_kernel(const float* __restrict__ x,
                                const float* __restrict__ W0,
                                const float* __restrict__ W1,
                                const float* __restrict__ W2,
                                const float* __restrict__ W3,
                                __half* __restrict__ xh,
                                __half* __restrict__ wh)
{
    int i = blockIdx.x * blockDim.x + threadIdx.x;
    const float* src;
    __half* dst;
    int off;
    if (i < N4X) {
        src = x; dst = xh; off = i;
    } else {
        int j = i - N4X;
        if (j >= 4 * N4W) return;
        int w = j / N4W;
        off = j - w * N4W;
        src = (w == 0) ? W0 : (w == 1) ? W1 : (w == 2) ? W2 : W3;
        dst = wh + (size_t)w * EDIM * EDIM;
    }
    float4 v = ((const float4*)src)[off];
    ((__half2*)dst)[2 * off + 0] = __floats2half2_rn(v.x, v.y);
    ((__half2*)dst)[2 * off + 1] = __floats2half2_rn(v.z, v.w);
}

// ---------------------------------------------------------------------------
// mma.sync fp16 GEMM (NT): C[m,n] = sum_k A[m,k]*B[n,k].
// BM=BN=128, BK=64, 8 warps (2x4), warp tile 64x32, cp.async double-buffer,
// 2 CTAs/SM. QKV=true: batched blockIdx.z (0=q,1=k phi; 2=v), fp16 out only.
// QKV=false: single GEMM, +bias, fp32 out.
// ---------------------------------------------------------------------------
#define BK      64
#define LDT     72                      // BK + 8 pad (fp16 elems)
#define TILEB   (128 * LDT * 2)         // 18432 B per tile
#define NT      (EDIM / BK)             // 16 chunks
#define GEMM_SMEM (2 * 2 * TILEB)       // 73728 B

template <bool QKV>
__global__ void __launch_bounds__(256, 2)
tc_gemm(const __half* __restrict__ Ah, const __half* __restrict__ Wbase,
        const float* __restrict__ bias, float* __restrict__ C,
        __half* __restrict__ H0, __half* __restrict__ H1, __half* __restrict__ H2)
{
    extern __shared__ char smc[];
    const uint32_t sb = smem_u32(smc);
    const int tid = threadIdx.x;
    const int wid = tid >> 5, lane = tid & 31;
    const int m0g = blockIdx.y * 128;
    const int n0g = blockIdx.x * 128;
    const int m_off = (wid & 1) * 64;
    const int n_off = (wid >> 1) * 32;
    const int z = QKV ? blockIdx.z : 0;
    const __half* Bh = Wbase + (size_t)z * EDIM * EDIM;
    __half* C16 = QKV ? ((z == 0) ? H0 : (z == 1) ? H1 : H2) : nullptr;
    const bool phi = QKV && (z < 2);

    uint32_t aoff[4], boff[2];
    #pragma unroll
    for (int mt = 0; mt < 4; ++mt)
        aoff[mt] = (uint32_t)(((m_off + 16 * mt + (lane & 15)) * LDT
                               + (lane >> 4) * 8) * 2);
    #pragma unroll
    for (int p = 0; p < 2; ++p)
        boff[p] = (uint32_t)(((n_off + 16 * p + ((lane >> 4) << 3) + (lane & 7)) * LDT
                              + ((lane >> 3) & 1) * 8) * 2);

    auto stage_tile = [&](const __half* __restrict__ src, int row0,
                          int kc, uint32_t dstbase) {
        #pragma unroll
        for (int j = 0; j < 4; ++j) {
            int u = tid + j * 256;          // 0..1023: 128 rows x 8 segs
            int row = u >> 3, seg = u & 7;
            uint32_t d = dstbase + (uint32_t)((row * LDT + seg * 8) * 2);
            const __half* g = src + (size_t)(row0 + row) * EDIM + kc + seg * 8;
            CP_ASYNC16(d, g);
        }
    };
    auto stage_chunk = [&](int t, int buf) {
        int kc = t * BK;
        uint32_t base = sb + buf * 2 * TILEB;
        stage_tile(Ah, m0g, kc, base);
        stage_tile(Bh, n0g, kc, base + TILEB);
        CP_COMMIT();
    };

    float acc[4][4][4] = {};

    stage_chunk(0, 0);
    for (int t = 0; t < NT; ++t) {
        const int cur = t & 1;
        if (t + 1 < NT) {
            stage_chunk(t + 1, 1 - cur);
            CP_WAIT(1);
        } else {
            CP_WAIT(0);
        }
        __syncthreads();

        const uint32_t base = sb + cur * 2 * TILEB;
        #pragma unroll
        for (int ks = 0; ks < BK; ks += 16) {
            const uint32_t kso = (uint32_t)(ks * 2);
            uint32_t ah[4][4], bh[2][4];
            #pragma unroll
            for (int mt = 0; mt < 4; ++mt)
                LDSM_X4(ah[mt][0], ah[mt][1], ah[mt][2], ah[mt][3],
                        base + aoff[mt] + kso);
            #pragma unroll
            for (int p = 0; p < 2; ++p)
                LDSM_X4(bh[p][0], bh[p][1], bh[p][2], bh[p][3],
                        base + TILEB + boff[p] + kso);
            #pragma unroll
            for (int i = 0; i < 4; ++i)
                #pragma unroll
                for (int j = 0; j < 4; ++j) {
                    const int p = j >> 1, w = (j & 1) * 2;
                    MMA16816H(acc[i][j], ah[i], bh[p][w], bh[p][w + 1]);
                }
        }
        __syncthreads();
    }

    #pragma unroll
    for (int i = 0; i < 4; ++i) {
        const int r = m0g + m_off + 16 * i + (lane >> 2);
        #pragma unroll
        for (int j = 0; j < 4; ++j) {
            const int c = n0g + n_off + 8 * j + ((lane & 3) << 1);
            float v0 = acc[i][j][0], v1 = acc[i][j][1];
            float v2 = acc[i][j][2], v3 = acc[i][j][3];
            if (QKV) {
                if (phi) {
                    v0 = (v0 > 0.f) ? (v0 + 1.f) : __expf(v0);
                    v1 = (v1 > 0.f) ? (v1 + 1.f) : __expf(v1);
                    v2 = (v2 > 0.f) ? (v2 + 1.f) : __expf(v2);
                    v3 = (v3 > 0.f) ? (v3 + 1.f) : __expf(v3);
                }
                *(__half2*)(C16 + (size_t)r * EDIM + c) = __floats2half2_rn(v0, v1);
                *(__half2*)(C16 + (size_t)(r + 8) * EDIM + c) = __floats2half2_rn(v2, v3);
            } else {
                float b0 = bias[c], b1 = bias[c + 1];
                *(float2*)(C + (size_t)r * EDIM + c) = make_float2(v0 + b0, v1 + b1);
                *(float2*)(C + (size_t)(r + 8) * EDIM + c) = make_float2(v2 + b0, v3 + b1);
            }
        }
    }
}

// ---------------------------------------------------------------------------
// Per-chunk kv state via fp16 mma with ldmatrix.trans, cp.async staging.
// ---------------------------------------------------------------------------
__global__ void __launch_bounds__(256)
chunk_kv_mma(const __half* __restrict__ k16, const __half* __restrict__ v16,
             float* __restrict__ kv, float* __restrict__ zk)
{
    __shared__ __align__(16) __half sKr[128 * 72];
    __shared__ __align__(16) __half sVr[128 * 72];
    const uint32_t sbK = smem_u32(sKr);
    const uint32_t sbV = smem_u32(sVr);

    const int n = blockIdx.x, h = blockIdx.y, b = blockIdx.z;
    const int tid = threadIdx.x;
    const int wid = tid >> 5, lane = tid & 31;
    const int m_off = (wid & 1) * 32;       // d
    const int n_off = (wid >> 1) * 16;      // e
    const size_t rowbase = ((size_t)(b * TLEN + n * CHK)) * EDIM + h * DHEAD;

    // cp.async row-major staging: 128 rows x 64 halves (8 x 16B per row)
    #pragma unroll
    for (int it = 0; it < 4; ++it) {
        int u = tid + it * 256;             // 0..1023
        int row = u >> 3, seg = u & 7;
        const __half* g = k16 + rowbase + (size_t)row * EDIM + seg * 8;
        const __half* g2 = v16 + rowbase + (size_t)row * EDIM + seg * 8;
        CP_ASYNC16(sbK + (uint32_t)((row * 72 + seg * 8) * 2), g);
        CP_ASYNC16(sbV + (uint32_t)((row * 72 + seg * 8) * 2), g2);
    }
    CP_COMMIT();
    CP_WAIT(0);
    __syncthreads();

    if (tid < DHEAD) {
        float z = 0.f;
        #pragma unroll 8
        for (int c = 0; c < CHK; ++c) z += __half2float(sKr[c * 72 + tid]);
        zk[((size_t)((b * NHEAD + h) * NCH) + n) * DHEAD + tid] = z;
    }

    // trans-fragment offsets (bytes), add ks*144 per k-step
    uint32_t aoffT[2];
    #pragma unroll
    for (int mt = 0; mt < 2; ++mt)
        aoffT[mt] = (uint32_t)(((((lane >> 4) & 1) * 8 + (lane & 7)) * 72
                                + m_off + 16 * mt + ((lane >> 3) & 1) * 8) * 2);
    const uint32_t boffT = (uint32_t)(((((lane >> 3) & 1) * 8 + (lane & 7)) * 72
                                      + n_off + ((lane >> 4) & 1) * 8) * 2);

    float acc[2][2][4] = {};
    #pragma unroll
    for (int ks = 0; ks < CHK; ks += 16) {
        const uint32_t kb = (uint32_t)(ks * 144);
        uint32_t a[2][4], bv[4];
        #pragma unroll
        for (int mt = 0; mt < 2; ++mt)
            LDSM_X4_T(a[mt][0], a[mt][1], a[mt][2], a[mt][3], sbK + aoffT[mt] + kb);
        LDSM_X4_T(bv[0], bv[1], bv[2], bv[3], sbV + boffT + kb);
        #pragma unroll
        for (int i = 0; i < 2; ++i)
            #pragma unroll
            for (int j2 = 0; j2 < 2; ++j2)
                MMA16816H(acc[i][j2], a[i], bv[2 * j2], bv[2 * j2 + 1]);
    }

    const size_t obase = ((size_t)((b * NHEAD + h) * NCH) + n) * DHEAD * DHEAD;
    #pragma unroll
    for (int i = 0; i < 2; ++i) {
        const int r1 = m_off + 16 * i + (lane >> 2);
        const int r2 = r1 + 8;
        #pragma unroll
        for (int j2 = 0; j2 < 2; ++j2) {
            const int c = n_off + 8 * j2 + ((lane & 3) << 1);
            *(float2*)(kv + obase + (size_t)r1 * DHEAD + c) =
                make_float2(acc[i][j2][0], acc[i][j2][1]);
            *(float2*)(kv + obase + (size_t)r2 * DHEAD + c) =
                make_float2(acc[i][j2][2], acc[i][j2][3]);
        }
    }
}

// ---------------------------------------------------------------------------
// Merged exclusive prefix scans over the N=16 chunk axis (kv->S and zk->Z)
// ---------------------------------------------------------------------------
#define SCAN1 (BSZ * NHEAD * DHEAD * DHEAD)   // 262144
#define SCAN2 (BSZ * NHEAD * DHEAD)           // 4096

__global__ void prefix_scan_all(const float* __restrict__ kv,
                                float* __restrict__ S,
                                const float* __restrict__ zk,
                                float* __restrict__ Z)
{
    int i = blockIdx.x * blockDim.x + threadIdx.x;
    const float* src;
    float* dst;
    size_t base;
    int per;
    if (i < SCAN1) {
        per = DHEAD * DHEAD;
        int bh = i / per, r = i - bh * per;
        base = (size_t)bh * NCH * per + r;
        src = kv; dst = S;
    } else {
        int j = i - SCAN1;
        if (j >= SCAN2) return;
        per = DHEAD;
        int bh = j / per, r = j - bh * per;
        base = (size_t)bh * NCH * per + r;
        src = zk; dst = Z;
    }
    float acc = 0.f;
    #pragma unroll
    for (int nn = 0; nn < NCH; ++nn) {
        dst[base + (size_t)nn * per] = acc;
        acc += src[base + (size_t)nn * per];
    }
}

// ---------------------------------------------------------------------------
// Tensor-core per-chunk attention; cp.async staging, causal triangle skip,
// 2 CTAs/SM (200KB smem of 228KB).
// ---------------------------------------------------------------------------
#define SQ_O    0                       // [128][72] fp16
#define SK_O    18432                   // [128][72] fp16
#define SV_O    36864                   // [128][72] fp16 (row-major)
#define SS_O    55296                   // [64][72]  fp16 (row-major, d rows)
#define SA_O    64512                   // [128][136] fp16 masked A
#define SZ_O    99328                   // [64] fp32
#define SDEN_O  99584                   // [128] fp32
#define ATTN_SMEM 100096

__global__ void __launch_bounds__(256, 2)
chunk_attn_mma(const __half* __restrict__ q16, const __half* __restrict__ k16,
               const __half* __restrict__ v16, const float* __restrict__ S,
               const float* __restrict__ Z, __half* __restrict__ y16)
{
    extern __shared__ char smc[];
    const uint32_t sb = smem_u32(smc);
    float* sZ   = (float*)(smc + SZ_O);
    float* sDen = (float*)(smc + SDEN_O);

    const int n = blockIdx.x, h = blockIdx.y, b = blockIdx.z;
    const int tid = threadIdx.x;
    const int wid = tid >> 5, lane = tid & 31;
    const int m_off = (wid & 1) * 64;
    const int n_off = (wid >> 1) * 32;      // pass A (N=128)
    const int n_off2 = (wid >> 1) * 16;     // pass B (N=64)
    const size_t rowbase = ((size_t)(b * TLEN + n * CHK)) * EDIM + h * DHEAD;
    const size_t sbase = ((size_t)((b * NHEAD + h) * NCH) + n) * DHEAD * DHEAD;
    const size_t zbase = ((size_t)((b * NHEAD + h) * NCH) + n) * DHEAD;

    // cp.async stage Q, K, V row-major [128][72]
    #pragma unroll
    for (int it = 0; it < 4; ++it) {
        int u = tid + it * 256;             // 0..1023
        int row = u >> 3, seg = u & 7;
        uint32_t so = (uint32_t)((row * 72 + seg * 8) * 2);
        CP_ASYNC16(sb + SQ_O + so, q16 + rowbase + (size_t)row * EDIM + seg * 8);
        CP_ASYNC16(sb + SK_O + so, k16 + rowbase + (size_t)row * EDIM + seg * 8);
        CP_ASYNC16(sb + SV_O + so, v16 + rowbase + (size_t)row * EDIM + seg * 8);
    }
    CP_COMMIT();
    // stage S fp32 -> fp16 row-major [64][72] (overlaps with cp.async)
    #pragma unroll
    for (int it = 0; it < 4; ++it) {
        int u = tid + it * 256;             // 0..1023 float4s
        int row = u >> 4, col4 = (u & 15) * 4;
        float4 s4 = *(const float4*)(S + sbase + (size_t)row * DHEAD + col4);
        __half2* dst = (__half2*)(smc + SS_O + (row * 72 + col4) * 2);
        dst[0] = __floats2half2_rn(s4.x, s4.y);
        dst[1] = __floats2half2_rn(s4.z, s4.w);
    }
    if (tid < DHEAD) sZ[tid] = Z[zbase + tid];
    CP_WAIT(0);
    __syncthreads();

    // den init: eps + phiq . Z
    if (tid < CHK) {
        float s2 = 1e-6f;
        const __half2* qr = (const __half2*)(smc + SQ_O + tid * 144);
        #pragma unroll
        for (int d2 = 0; d2 < 32; ++d2) {
            float2 qq = __half22float2(qr[d2]);
            s2 += qq.x * sZ[2 * d2] + qq.y * sZ[2 * d2 + 1];
        }
        sDen[tid] = s2;
    }
    __syncthreads();

    // fragment offsets
    uint32_t aoffQ[4], aoffA[4], boffK[2];
    #pragma unroll
    for (int mt = 0; mt < 4; ++mt) {
        int rr = m_off + 16 * mt + (lane & 15);
        aoffQ[mt] = (uint32_t)((rr * 72 + (lane >> 4) * 8) * 2);
        aoffA[mt] = (uint32_t)((rr * 136 + (lane >> 4) * 8) * 2);
    }
    #pragma unroll
    for (int p = 0; p < 2; ++p)
        boffK[p] = (uint32_t)(((n_off + 16 * p + ((lane >> 4) << 3) + (lane & 7)) * 72
                               + ((lane >> 3) & 1) * 8) * 2);
    const uint32_t boffT = (uint32_t)(((((lane >> 3) & 1) * 8 + (lane & 7)) * 72
                                      + n_off2 + ((lane >> 4) & 1) * 8) * 2);

    // ---- Pass A: A = Q K^T (128x128, k=64), causal triangle skip ----
    {
        float acc[4][4][4] = {};
        #pragma unroll
        for (int ks = 0; ks < DHEAD; ks += 16) {
            const uint32_t kso = (uint32_t)(ks * 2);
            uint32_t a[4][4], bk[2][4];
            #pragma unroll
            for (int mt = 0; mt < 4; ++mt)
                if (n_off <= m_off + 16 * mt + 15)           // row strip has live tiles
                    LDSM_X4(a[mt][0], a[mt][1], a[mt][2], a[mt][3],
                            sb + SQ_O + aoffQ[mt] + kso);
            #pragma unroll
            for (int p = 0; p < 2; ++p)
                if (n_off + 16 * p <= m_off + 63)            // col strip has live tiles
                    LDSM_X4(bk[p][0], bk[p][1], bk[p][2], bk[p][3],
                            sb + SK_O + boffK[p] + kso);
            #pragma unroll
            for (int i = 0; i < 4; ++i)
                #pragma unroll
                for (int j = 0; j < 4; ++j) {
                    if (n_off + 8 * j > m_off + 16 * i + 15) continue;  // fully masked
                    const int p = j >> 1, w = (j & 1) * 2;
                    MMA16816H(acc[i][j], a[i], bk[p][w], bk[p][w + 1]);
                }
        }
        #pragma unroll
        for (int i = 0; i < 4; ++i) {
            const int r1 = m_off + 16 * i + (lane >> 2);
            const int r2 = r1 + 8;
            float rs1 = 0.f, rs2 = 0.f;
            #pragma unroll
            for (int j = 0; j < 4; ++j) {
                const int c = n_off + 8 * j + ((lane & 3) << 1);
                float v0 = (c <= r1) ? acc[i][j][0] : 0.f;
                float v1 = (c + 1 <= r1) ? acc[i][j][1] : 0.f;
                float v2 = (c <= r2) ? acc[i][j][2] : 0.f;
                float v3 = (c + 1 <= r2) ? acc[i][j][3] : 0.f;
                rs1 += v0 + v1; rs2 += v2 + v3;
                *(__half2*)(smc + SA_O + (r1 * 136 + c) * 2) = __floats2half2_rn(v0, v1);
                *(__half2*)(smc + SA_O + (r2 * 136 + c) * 2) = __floats2half2_rn(v2, v3);
            }
            rs1 += __shfl_xor_sync(0xFFFFFFFFu, rs1, 1);
            rs1 += __shfl_xor_sync(0xFFFFFFFFu, rs1, 2);
            rs2 += __shfl_xor_sync(0xFFFFFFFFu, rs2, 1);
            rs2 += __shfl_xor_sync(0xFFFFFFFFu, rs2, 2);
            if ((lane & 3) == 0) {
                atomicAdd(&sDen[r1], rs1);
                atomicAdd(&sDen[r2], rs2);
            }
        }
    }
    __syncthreads();

    // ---- Pass B: num = A.V + Q.S (128x64), trans B-operands ----
    {
        float acc2[4][2][4] = {};
        #pragma unroll
        for (int ks = 0; ks < CHK; ks += 16) {        // A.V, k = s = 128
            const uint32_t kso = (uint32_t)(ks * 2);
            const uint32_t kb = (uint32_t)(ks * 144);
            uint32_t a[4][4], bv[4];
            #pragma unroll
            for (int mt = 0; mt < 4; ++mt)
                LDSM_X4(a[mt][0], a[mt][1], a[mt][2], a[mt][3],
                        sb + SA_O + aoffA[mt] + kso);
            LDSM_X4_T(bv[0], bv[1], bv[2], bv[3], sb + SV_O + boffT + kb);
            #pragma unroll
            for (int i = 0; i < 4; ++i)
                #pragma unroll
                for (int j2 = 0; j2 < 2; ++j2)
                    MMA16816H(acc2[i][j2], a[i], bv[2 * j2], bv[2 * j2 + 1]);
        }
        #pragma unroll
        for (int ks = 0; ks < DHEAD; ks += 16) {      // Q.S, k = d = 64
            const uint32_t kso = (uint32_t)(ks * 2);
            const uint32_t kb = (uint32_t)(ks * 144);
            uint32_t a[4][4], bs[4];
            #pragma unroll
            for (int mt = 0; mt < 4; ++mt)
                LDSM_X4(a[mt][0], a[mt][1], a[mt][2], a[mt][3],
                        sb + SQ_O + aoffQ[mt] + kso);
            LDSM_X4_T(bs[0], bs[1], bs[2], bs[3], sb + SS_O + boffT + kb);
            #pragma unroll
            for (int i = 0; i < 4; ++i)
                #pragma unroll
                for (int j2 = 0; j2 < 2; ++j2)
                    MMA16816H(acc2[i][j2], a[i], bs[2 * j2], bs[2 * j2 + 1]);
        }
        #pragma unroll
        for (int i = 0; i < 4; ++i) {
            const int r1 = m_off + 16 * i + (lane >> 2);
            const int r2 = r1 + 8;
            const float inv1 = 1.0f / sDen[r1];
            const float inv2 = 1.0f / sDen[r2];
            #pragma unroll
            for (int j2 = 0; j2 < 2; ++j2) {
                const int c = n_off2 + 8 * j2 + ((lane & 3) << 1);
                *(__half2*)(y16 + rowbase + (size_t)r1 * EDIM + c) =
                    __floats2half2_rn(acc2[i][j2][0] * inv1, acc2[i][j2][1] * inv1);
                *(__half2*)(y16 + rowbase + (size_t)r2 * EDIM + c) =
                    __floats2half2_rn(acc2[i][j2][2] * inv2, acc2[i][j2][3] * inv2);
            }
        }
    }
}

// ---------------------------------------------------------------------------
extern "C" void kernel_launch(void* const* d_in, const int* in_sizes, int n_in,
                              void* d_out, int out_size)
{
    const float* x  = (const float*)d_in[0];
    const float* Wq = (const float*)d_in[1];
    const float* Wk = (const float*)d_in[2];
    const float* Wv = (const float*)d_in[3];
    const float* Wp = (const float*)d_in[4];
    const float* bp = (const float*)d_in[5];
    float* out = (float*)d_out;

    float *kv, *S, *zk, *Z;
    __half *xh, *qh, *kh, *vh, *yh, *wh;
    cudaGetSymbolAddress((void**)&kv, g_kv);
    cudaGetSymbolAddress((void**)&S,  g_S);
    cudaGetSymbolAddress((void**)&zk, g_zk);
    cudaGetSymbolAddress((void**)&Z,  g_Z);
    cudaGetSymbolAddress((void**)&xh, g_xh);
    cudaGetSymbolAddress((void**)&qh, g_qh);
    cudaGetSymbolAddress((void**)&kh, g_kh);
    cudaGetSymbolAddress((void**)&vh, g_vh);
    cudaGetSymbolAddress((void**)&yh, g_yh);
    cudaGetSymbolAddress((void**)&wh, g_wh);

    cudaFuncSetAttribute(tc_gemm<true>,  cudaFuncAttributeMaxDynamicSharedMemorySize, GEMM_SMEM);
    cudaFuncSetAttribute(tc_gemm<false>, cudaFuncAttributeMaxDynamicSharedMemorySize, GEMM_SMEM);
    cudaFuncSetAttribute(chunk_attn_mma,
                         cudaFuncAttributeMaxDynamicSharedMemorySize, ATTN_SMEM);

    const size_t WSZ = (size_t)EDIM * EDIM;

    const int castN = N4X + 4 * N4W;
    cast_all_kernel<<<(castN + 255) / 256, 256>>>(x, Wq, Wk, Wv, Wp, xh, wh);

    dim3 gq(EDIM / 128, MROWS / 128, 3);   // batched q/k/v, fp16-only outputs
    tc_gemm<true><<<gq, 256, GEMM_SMEM>>>(xh, wh, nullptr, nullptr, qh, kh, vh);

    chunk_kv_mma<<<dim3(NCH, NHEAD, BSZ), 256>>>(kh, vh, kv, zk);

    const int scanN = SCAN1 + SCAN2;
    prefix_scan_all<<<(scanN + 255) / 256, 256>>>(kv, S, zk, Z);

    chunk_attn_mma<<<dim3(NCH, NHEAD, BSZ), 256, ATTN_SMEM>>>(qh, kh, vh, S, Z, yh);

    dim3 gp(EDIM / 128, MROWS / 128);      // final projection (1-pass fp16)
    tc_gemm<false><<<gp, 256, GEMM_SMEM>>>(yh, wh + 3 * WSZ, bp, out,
                                           nullptr, nullptr, nullptr);
}